// round 1
// baseline (speedup 1.0000x reference)
#include <cuda_runtime.h>
#include <math.h>

// ---------------------------------------------------------------------------
// Shapes (fixed for this problem)
// ---------------------------------------------------------------------------
#define Bq 8
#define Nn 1024
#define MROWS (Bq * Nn)   // 8192

// ---------------------------------------------------------------------------
// Scratch: single big __device__ array (no runtime allocation allowed)
// ---------------------------------------------------------------------------
#define S_MASK   0L
#define S_NUMEL  (S_MASK  + 8192L)
#define S_MEAN   (S_NUMEL + 8L)
#define S_C      (S_MEAN  + 8L*512)
#define S_H1     (S_C     + 8L*128)
#define S_H2     (S_H1    + 8192L*784)
#define S_FEA    (S_H2    + 8192L*512)
#define S_Q      (S_FEA   + 8192L*512)
#define S_A1     (S_Q     + 8192L*640)
#define S_AF     (S_A1    + 8192L*512)
#define S_ADJ    (S_AF    + 8192L*384)
#define S_DINV   (S_ADJ   + 8L*1024*1024)
#define S_TA     (S_DINV  + 8192L)
#define S_TB     (S_TA    + 8192L*512)
#define S_TC     (S_TB    + 8192L*512)
#define S_X1     (S_TC    + 8192L*512)
#define S_X2     (S_X1    + 8192L*512)
#define S_G1     (S_X2    + 8192L*384)
#define S_G2     (S_G1    + 8192L*128)
#define S_GATE   (S_G2    + 8192L*64)
#define S_POOL   (S_GATE  + 8192L)
#define S_TOTAL  (S_POOL  + 8L*384)

__device__ float g_scratch[S_TOTAL];

#define CDIV(a,b) (((a)+(b)-1)/(b))

// ---------------------------------------------------------------------------
// Generic fp32 tiled GEMM: C = act(alpha*op(A,B) + bias + cinCoef*Cin) * masks
//   A: [M,K] row-major (per-batch stride sA)
//   B: !transB -> [K,N] row-major; transB -> stored [N,K] row-major (C=A*B^T)
//   rowMask/colMask: per-batch vectors of length M / N
// ---------------------------------------------------------------------------
__global__ void gemm_kernel(const float* __restrict__ A, long sA,
                            const float* __restrict__ B, long sB, int transB,
                            const float* __restrict__ bias,
                            const float* __restrict__ Cin, long sCin, float cinCoef,
                            const float* __restrict__ rowMask,
                            const float* __restrict__ colMask,
                            float* __restrict__ C, long sC,
                            int M, int N, int K, float alpha, int act)
{
    __shared__ float As[16][64];
    __shared__ float Bs[16][64];

    const int bz = blockIdx.z;
    A += (long)bz * sA;
    B += (long)bz * sB;
    C += (long)bz * sC;
    if (Cin) Cin += (long)bz * sCin;

    const int rowBase = blockIdx.y * 64;
    const int colBase = blockIdx.x * 64;
    const int tid = threadIdx.x;          // 256 threads
    const int tx = tid & 15, ty = tid >> 4;

    float acc[4][4];
#pragma unroll
    for (int i = 0; i < 4; i++)
#pragma unroll
        for (int j = 0; j < 4; j++) acc[i][j] = 0.f;

    const int ar  = tid >> 2, ak  = (tid & 3) * 4;   // A-load layout
    const int bkr = tid >> 4, bnc = (tid & 15) * 4;  // B normal
    const int bnr = tid >> 2, bkc = (tid & 3) * 4;   // B trans

    for (int k0 = 0; k0 < K; k0 += 16) {
        const int gr = rowBase + ar;
#pragma unroll
        for (int i = 0; i < 4; i++) {
            const int gk = k0 + ak + i;
            As[ak + i][ar] = (gr < M && gk < K) ? A[(long)gr * K + gk] : 0.f;
        }
        if (!transB) {
            const int gk = k0 + bkr;
#pragma unroll
            for (int i = 0; i < 4; i++) {
                const int gn = colBase + bnc + i;
                Bs[bkr][bnc + i] = (gk < K && gn < N) ? B[(long)gk * N + gn] : 0.f;
            }
        } else {
            const int gn = colBase + bnr;
#pragma unroll
            for (int i = 0; i < 4; i++) {
                const int gk = k0 + bkc + i;
                Bs[bkc + i][bnr] = (gn < N && gk < K) ? B[(long)gn * K + gk] : 0.f;
            }
        }
        __syncthreads();
#pragma unroll
        for (int kk = 0; kk < 16; kk++) {
            float a0[4], b0[4];
#pragma unroll
            for (int i = 0; i < 4; i++) a0[i] = As[kk][ty * 4 + i];
#pragma unroll
            for (int j = 0; j < 4; j++) b0[j] = Bs[kk][tx * 4 + j];
#pragma unroll
            for (int i = 0; i < 4; i++)
#pragma unroll
                for (int j = 0; j < 4; j++) acc[i][j] += a0[i] * b0[j];
        }
        __syncthreads();
    }

#pragma unroll
    for (int i = 0; i < 4; i++) {
        const int gr = rowBase + ty * 4 + i;
        if (gr >= M) continue;
#pragma unroll
        for (int j = 0; j < 4; j++) {
            const int gc = colBase + tx * 4 + j;
            if (gc >= N) continue;
            float v = alpha * acc[i][j];
            if (bias)    v += bias[gc];
            if (Cin)     v += cinCoef * Cin[(long)gr * N + gc];
            if (rowMask) v *= rowMask[(long)bz * M + gr];
            if (colMask) v *= colMask[(long)bz * N + gc];
            if (act == 1)      v = fmaxf(v, 0.f);
            else if (act == 2) v = tanhf(v);
            C[(long)gr * N + gc] = v;
        }
    }
}

// ---------------------------------------------------------------------------
// Glue kernels
// ---------------------------------------------------------------------------
__global__ void mask_kernel(const float* __restrict__ inp, float* __restrict__ mask)
{
    const int row  = blockIdx.x * 8 + (threadIdx.x >> 5);
    const int lane = threadIdx.x & 31;
    const float* p = inp + (long)row * 1024;
    float s = 0.f;
    for (int k = lane; k < 1024; k += 32) s += p[k];
#pragma unroll
    for (int o = 16; o > 0; o >>= 1) s += __shfl_xor_sync(0xffffffffu, s, o);
    if (lane == 0) mask[row] = (s != 0.f) ? 1.f : 0.f;
}

__global__ void numel_kernel(const float* __restrict__ mask, float* __restrict__ numel)
{
    const int b = blockIdx.x, tid = threadIdx.x;     // 1024 threads
    __shared__ float sh[1024];
    sh[tid] = mask[b * 1024 + tid];
    __syncthreads();
    for (int s = 512; s > 0; s >>= 1) {
        if (tid < s) sh[tid] += sh[tid + s];
        __syncthreads();
    }
    if (tid == 0) numel[b] = sh[0];
}

__global__ void mean_kernel(const float* __restrict__ fea, const float* __restrict__ numel,
                            float* __restrict__ mean)
{
    const int b = blockIdx.y;
    const int f = blockIdx.x * blockDim.x + threadIdx.x;  // 512
    const float* p = fea + (long)b * 1024 * 512 + f;
    float s = 0.f;
    for (int n = 0; n < 1024; n++) s += p[(long)n * 512];
    mean[b * 512 + f] = s / numel[b];
}

__global__ void cvec_kernel(const float* __restrict__ mean, const float* __restrict__ Wc,
                            const float* __restrict__ bc, float* __restrict__ c)
{
    const int b = blockIdx.x, j = threadIdx.x;  // 128
    float s = bc[j];
    for (int k = 0; k < 512; k++) s += mean[b * 512 + k] * Wc[k * 128 + j];
    c[b * 128 + j] = fmaxf(s, 0.f);
}

__global__ void concat_kernel(const float* __restrict__ fea, const float* __restrict__ c,
                              float* __restrict__ q)
{
    const long idx = (long)blockIdx.x * blockDim.x + threadIdx.x;
    if (idx >= 8192L * 640) return;
    const int f = (int)(idx % 640);
    const long row = idx / 640;
    const int b = (int)(row >> 10);
    q[idx] = (f < 512) ? fea[row * 512 + f] : c[b * 128 + (f - 512)];
}

__global__ void deg_kernel(const float* __restrict__ A, float* __restrict__ dinv)
{
    const int row  = blockIdx.x * 8 + (threadIdx.x >> 5);
    const int lane = threadIdx.x & 31;
    const float* p = A + (long)row * 1024;
    float s = 0.f;
    for (int j = lane; j < 1024; j += 32) s += p[j];
#pragma unroll
    for (int o = 16; o > 0; o >>= 1) s += __shfl_xor_sync(0xffffffffu, s, o);
    if (lane == 0) dinv[row] = (s > 0.f) ? rsqrtf(fmaxf(s, 1e-30f)) : 0.f;
}

__global__ void lhat_kernel(float* __restrict__ A, const float* __restrict__ dinv)
{
    const long idx = (long)blockIdx.x * blockDim.x + threadIdx.x;
    if (idx >= 8L * 1024 * 1024) return;
    const long row = idx >> 10;
    const int  j   = (int)(idx & 1023);
    const int  b   = (int)(row >> 10);
    A[idx] *= -dinv[row] * dinv[(long)b * 1024 + j];
}

__global__ void pool_kernel(const float* __restrict__ gate, const float* __restrict__ mask,
                            const float* __restrict__ x, float* __restrict__ pooled)
{
    const int b = blockIdx.x, tid = threadIdx.x;   // 1024 threads
    __shared__ float sh[1024];
    const float g = (mask[b * 1024 + tid] > 0.f) ? gate[b * 1024 + tid] : -1e9f;
    sh[tid] = g;
    __syncthreads();
    for (int s = 512; s > 0; s >>= 1) {
        if (tid < s) sh[tid] = fmaxf(sh[tid], sh[tid + s]);
        __syncthreads();
    }
    const float maxv = sh[0];
    __syncthreads();
    const float e = expf(g - maxv);
    sh[tid] = e;
    __syncthreads();
    for (int s = 512; s > 0; s >>= 1) {
        if (tid < s) sh[tid] += sh[tid + s];
        __syncthreads();
    }
    const float sum = sh[0];
    __syncthreads();
    sh[tid] = e / sum;   // attn weights
    __syncthreads();
    if (tid < 384) {
        float s = 0.f;
        const float* xb = x + (long)b * 1024 * 384 + tid;
        for (int n = 0; n < 1024; n++) s += sh[n] * xb[(long)n * 384];
        pooled[b * 384 + tid] = s;
    }
}

__global__ void final_kernel(const float* __restrict__ pooled, const float* __restrict__ Wm1,
                             const float* __restrict__ bm1, const float* __restrict__ Wm2,
                             const float* __restrict__ bm2, float* __restrict__ out)
{
    const int b = blockIdx.x, tid = threadIdx.x;   // 256
    __shared__ float sh[256];
    float s = bm1[tid];
    const float* p = pooled + b * 384;
    for (int k = 0; k < 384; k++) s += p[k] * Wm1[k * 256 + tid];
    sh[tid] = fmaxf(s, 0.f) * Wm2[tid];
    __syncthreads();
    for (int r = 128; r > 0; r >>= 1) {
        if (tid < r) sh[tid] += sh[tid + r];
        __syncthreads();
    }
    if (tid == 0) out[b] = 1.f / (1.f + expf(-(sh[0] + bm2[0])));
}

// ---------------------------------------------------------------------------
// Host-side GEMM launcher
// ---------------------------------------------------------------------------
static void gemm(const float* A, long sA, const float* B, long sB, int transB,
                 const float* bias, const float* Cin, long sCin, float cinCoef,
                 const float* rowMask, const float* colMask,
                 float* C, long sC, int M, int N, int K, float alpha, int act, int batch)
{
    dim3 grid(CDIV(N, 64), CDIV(M, 64), batch);
    gemm_kernel<<<grid, 256>>>(A, sA, B, sB, transB, bias, Cin, sCin, cinCoef,
                               rowMask, colMask, C, sC, M, N, K, alpha, act);
}

// ---------------------------------------------------------------------------
// Entry point
// ---------------------------------------------------------------------------
extern "C" void kernel_launch(void* const* d_in, const int* in_sizes, int n_in,
                              void* d_out, int out_size)
{
    const float* inp = (const float*)d_in[0];
    // d_in[1] = y (unused)
    const float* Wf1 = (const float*)d_in[2];  const float* bf1 = (const float*)d_in[3];
    const float* Wf2 = (const float*)d_in[4];  const float* bf2 = (const float*)d_in[5];
    const float* Wf3 = (const float*)d_in[6];  const float* bf3 = (const float*)d_in[7];
    const float* Wc  = (const float*)d_in[8];  const float* bc  = (const float*)d_in[9];
    const float* Wa1 = (const float*)d_in[10]; const float* ba1 = (const float*)d_in[11];
    const float* Wa2 = (const float*)d_in[12]; const float* ba2 = (const float*)d_in[13];
    const float* Wg1 = (const float*)d_in[14]; const float* bg1 = (const float*)d_in[15];
    const float* Wg2 = (const float*)d_in[16]; const float* bg2 = (const float*)d_in[17];
    const float* Wp1 = (const float*)d_in[18]; const float* bp1 = (const float*)d_in[19];
    const float* Wp2 = (const float*)d_in[20]; const float* bp2 = (const float*)d_in[21];
    const float* Wp3 = (const float*)d_in[22]; const float* bp3 = (const float*)d_in[23];
    const float* Wm1 = (const float*)d_in[24]; const float* bm1 = (const float*)d_in[25];
    const float* Wm2 = (const float*)d_in[26]; const float* bm2 = (const float*)d_in[27];
    float* out = (float*)d_out;

    float* base = nullptr;
    cudaGetSymbolAddress((void**)&base, g_scratch);

    float* mask  = base + S_MASK;
    float* numel = base + S_NUMEL;
    float* meanf = base + S_MEAN;
    float* cvec  = base + S_C;
    float* h1    = base + S_H1;
    float* h2    = base + S_H2;
    float* fea   = base + S_FEA;
    float* q     = base + S_Q;
    float* a1    = base + S_A1;
    float* af    = base + S_AF;
    float* adj   = base + S_ADJ;
    float* dinv  = base + S_DINV;
    float* Ta    = base + S_TA;
    float* Tb    = base + S_TB;
    float* Tc    = base + S_TC;
    float* x1    = base + S_X1;
    float* x2    = base + S_X2;
    float* g1    = base + S_G1;
    float* g2    = base + S_G2;
    float* gate  = base + S_GATE;
    float* pool  = base + S_POOL;

    // 1) node mask + numel
    mask_kernel<<<1024, 256>>>(inp, mask);
    numel_kernel<<<8, 1024>>>(mask, numel);

    // 2) feature extractor
    gemm(inp, 0, Wf1, 0, 0, bf1, nullptr, 0, 0.f, mask, nullptr, h1, 0, MROWS, 784, 1024, 1.f, 1, 1);
    gemm(h1,  0, Wf2, 0, 0, bf2, nullptr, 0, 0.f, mask, nullptr, h2, 0, MROWS, 512, 784,  1.f, 1, 1);
    gemm(h2,  0, Wf3, 0, 0, bf3, nullptr, 0, 0.f, mask, nullptr, fea,0, MROWS, 512, 512,  1.f, 1, 1);

    // 3) c vector
    mean_kernel<<<dim3(4, 8), 128>>>(fea, numel, meanf);
    cvec_kernel<<<8, 128>>>(meanf, Wc, bc, cvec);

    // 4) adjacency net
    concat_kernel<<<(int)CDIV(8192L * 640, 256), 256>>>(fea, cvec, q);
    gemm(q,  0, Wa1, 0, 0, ba1, nullptr, 0, 0.f, mask, nullptr, a1, 0, MROWS, 512, 640, 1.f, 1, 1);
    gemm(a1, 0, Wa2, 0, 0, ba2, nullptr, 0, 0.f, mask, nullptr, af, 0, MROWS, 384, 512, 1.f, 1, 1);

    // 5) adjacency A = (a a^T) * pairMask ; then Lhat in place
    gemm(af, 1024L * 384, af, 1024L * 384, 1, nullptr, nullptr, 0, 0.f,
         mask, mask, adj, 1024L * 1024, 1024, 1024, 384, 1.f, 0, 8);
    deg_kernel<<<1024, 256>>>(adj, dinv);
    lhat_kernel<<<(int)CDIV(8L * 1024 * 1024, 256), 256>>>(adj, dinv);

    // 6) ChebConv 1: fea[.,512] -> x1[.,512], K=5
    {
        const long sT = 1024L * 512, sL = 1024L * 1024, wk = 512L * 512;
        // x1 = T0 @ W0
        gemm(fea, 0, Wg1, 0, 0, nullptr, nullptr, 0, 0.f, nullptr, nullptr, x1, 0, MROWS, 512, 512, 1.f, 0, 1);
        // T1 = Lhat @ T0
        gemm(adj, sL, fea, sT, 0, nullptr, nullptr, 0, 0.f, nullptr, nullptr, Tb, sT, 1024, 512, 1024, 1.f, 0, 8);
        gemm(Tb, 0, Wg1 + wk, 0, 0, nullptr, x1, 0, 1.f, nullptr, nullptr, x1, 0, MROWS, 512, 512, 1.f, 0, 1);
        // T2 = 2 L T1 - T0
        gemm(adj, sL, Tb, sT, 0, nullptr, fea, sT, -1.f, nullptr, nullptr, Tc, sT, 1024, 512, 1024, 2.f, 0, 8);
        gemm(Tc, 0, Wg1 + 2 * wk, 0, 0, nullptr, x1, 0, 1.f, nullptr, nullptr, x1, 0, MROWS, 512, 512, 1.f, 0, 1);
        // T3 = 2 L T2 - T1
        gemm(adj, sL, Tc, sT, 0, nullptr, Tb, sT, -1.f, nullptr, nullptr, Ta, sT, 1024, 512, 1024, 2.f, 0, 8);
        gemm(Ta, 0, Wg1 + 3 * wk, 0, 0, nullptr, x1, 0, 1.f, nullptr, nullptr, x1, 0, MROWS, 512, 512, 1.f, 0, 1);
        // T4 = 2 L T3 - T2
        gemm(adj, sL, Ta, sT, 0, nullptr, Tc, sT, -1.f, nullptr, nullptr, Tb, sT, 1024, 512, 1024, 2.f, 0, 8);
        // x1 = relu(x1 + T4 @ W4 + bg1)
        gemm(Tb, 0, Wg1 + 4 * wk, 0, 0, bg1, x1, 0, 1.f, nullptr, nullptr, x1, 0, MROWS, 512, 512, 1.f, 1, 1);
    }

    // 7) ChebConv 2: x1[.,512] -> x2[.,384], K=5
    {
        const long sT = 1024L * 512, sL = 1024L * 1024, wk = 512L * 384;
        gemm(x1, 0, Wg2, 0, 0, nullptr, nullptr, 0, 0.f, nullptr, nullptr, x2, 0, MROWS, 384, 512, 1.f, 0, 1);
        gemm(adj, sL, x1, sT, 0, nullptr, nullptr, 0, 0.f, nullptr, nullptr, Tb, sT, 1024, 512, 1024, 1.f, 0, 8);
        gemm(Tb, 0, Wg2 + wk, 0, 0, nullptr, x2, 0, 1.f, nullptr, nullptr, x2, 0, MROWS, 384, 512, 1.f, 0, 1);
        gemm(adj, sL, Tb, sT, 0, nullptr, x1, sT, -1.f, nullptr, nullptr, Tc, sT, 1024, 512, 1024, 2.f, 0, 8);
        gemm(Tc, 0, Wg2 + 2 * wk, 0, 0, nullptr, x2, 0, 1.f, nullptr, nullptr, x2, 0, MROWS, 384, 512, 1.f, 0, 1);
        gemm(adj, sL, Tc, sT, 0, nullptr, Tb, sT, -1.f, nullptr, nullptr, Ta, sT, 1024, 512, 1024, 2.f, 0, 8);
        gemm(Ta, 0, Wg2 + 3 * wk, 0, 0, nullptr, x2, 0, 1.f, nullptr, nullptr, x2, 0, MROWS, 384, 512, 1.f, 0, 1);
        gemm(adj, sL, Ta, sT, 0, nullptr, Tc, sT, -1.f, nullptr, nullptr, Tb, sT, 1024, 512, 1024, 2.f, 0, 8);
        gemm(Tb, 0, Wg2 + 4 * wk, 0, 0, bg2, x2, 0, 1.f, nullptr, nullptr, x2, 0, MROWS, 384, 512, 1.f, 1, 1);
    }

    // 8) attention gate
    gemm(x2, 0, Wp1, 0, 0, bp1, nullptr, 0, 0.f, nullptr, nullptr, g1, 0, MROWS, 128, 384, 1.f, 1, 1);
    gemm(g1, 0, Wp2, 0, 0, bp2, nullptr, 0, 0.f, nullptr, nullptr, g2, 0, MROWS, 64, 128, 1.f, 1, 1);
    gemm(g2, 0, Wp3, 0, 0, bp3, nullptr, 0, 0.f, nullptr, nullptr, gate, 0, MROWS, 1, 64, 1.f, 2, 1);

    // 9) softmax pooling + output MLP
    pool_kernel<<<8, 1024>>>(gate, mask, x2, pool);
    final_kernel<<<8, 256>>>(pool, Wm1, bm1, Wm2, bm2, out);

    (void)in_sizes; (void)n_in; (void)out_size;
}

// round 2
// speedup vs baseline: 1.5726x; 1.5726x over previous
#include <cuda_runtime.h>
#include <math.h>

#define Bq 8
#define Nn 1024
#define MROWS (Bq * Nn)   // 8192

// ---------------------------------------------------------------------------
// Scratch
// ---------------------------------------------------------------------------
#define S_MASK   0L
#define S_NUMEL  (S_MASK  + 8192L)
#define S_MEAN   (S_NUMEL + 8L)
#define S_C      (S_MEAN  + 8L*512)
#define S_H1     (S_C     + 8L*128)
#define S_H2     (S_H1    + 8192L*784)
#define S_FEA    (S_H2    + 8192L*512)
#define S_Q      (S_FEA   + 8192L*512)
#define S_A1     (S_Q     + 8192L*640)
#define S_AF     (S_A1    + 8192L*512)
#define S_ADJ    (S_AF    + 8192L*384)
#define S_DINV   (S_ADJ   + 8L*1024*1024)
#define S_TA     (S_DINV  + 8192L)
#define S_TB     (S_TA    + 8192L*512)
#define S_TC     (S_TB    + 8192L*512)
#define S_X1     (S_TC    + 8192L*512)
#define S_X2     (S_X1    + 8192L*512)
#define S_G1     (S_X2    + 8192L*384)
#define S_G2     (S_G1    + 8192L*128)
#define S_GATE   (S_G2    + 8192L*64)
#define S_POOL   (S_GATE  + 8192L)
#define S_TOTAL  (S_POOL  + 8L*384)

__device__ float g_scratch[S_TOTAL];

#define CDIV(a,b) (((a)+(b)-1)/(b))

// ---------------------------------------------------------------------------
// Big GEMM: 128x128 tile, K-step 8, 8x8 per thread, float4 everywhere,
// double-buffered smem. Requires M%128==0, K%8==0, N%4==0 (col-guarded).
// C = act(alpha*op(A,B) + bias + cinCoef*Cin) * rowMask * colMask
// ---------------------------------------------------------------------------
__global__ void __launch_bounds__(256, 2)
gemm128_kernel(const float* __restrict__ A, long sA,
               const float* __restrict__ B, long sB, int transB,
               const float* __restrict__ bias,
               const float* __restrict__ Cin, long sCin, float cinCoef,
               const float* __restrict__ rowMask,
               const float* __restrict__ colMask,
               float* __restrict__ C, long sC,
               int M, int N, int K, float alpha, int act)
{
    __shared__ float As[2][8][128];
    __shared__ float Bs[2][8][128];

    const int bz = blockIdx.z;
    A += (long)bz * sA;
    B += (long)bz * sB;
    C += (long)bz * sC;
    if (Cin) Cin += (long)bz * sCin;

    const int rowBase = blockIdx.y * 128;
    const int colBase = blockIdx.x * 128;
    const int tid = threadIdx.x;              // 256 threads
    const int tx = tid & 15, ty = tid >> 4;   // 16 x 16 thread grid, 8x8 each

    // load-index layouts
    const int am  = tid >> 1, ak  = (tid & 1) * 4;   // A: 128 rows x 8 k
    const int bk  = tid >> 5, bn  = (tid & 31) * 4;  // B normal: 8 k x 128 n
    const int tbn = tid >> 1, tbk = (tid & 1) * 4;   // B trans:  128 n x 8 k

    float acc[8][8];
#pragma unroll
    for (int i = 0; i < 8; i++)
#pragma unroll
        for (int j = 0; j < 8; j++) acc[i][j] = 0.f;

    const float4 zero4 = make_float4(0.f, 0.f, 0.f, 0.f);

    // ---- preload tile 0 ----
    float4 ra = *(const float4*)(A + (long)(rowBase + am) * K + ak);
    float4 rb;
    if (!transB) {
        const int gn = colBase + bn;
        rb = (gn < N) ? *(const float4*)(B + (long)bk * N + gn) : zero4;
    } else {
        const int gn = colBase + tbn;
        rb = (gn < N) ? *(const float4*)(B + (long)gn * K + tbk) : zero4;
    }
    As[0][ak + 0][am] = ra.x; As[0][ak + 1][am] = ra.y;
    As[0][ak + 2][am] = ra.z; As[0][ak + 3][am] = ra.w;
    if (!transB) {
        *(float4*)&Bs[0][bk][bn] = rb;
    } else {
        Bs[0][tbk + 0][tbn] = rb.x; Bs[0][tbk + 1][tbn] = rb.y;
        Bs[0][tbk + 2][tbn] = rb.z; Bs[0][tbk + 3][tbn] = rb.w;
    }
    __syncthreads();

    int buf = 0;
    for (int k0 = 0; k0 < K; k0 += 8) {
        const bool hasNext = (k0 + 8) < K;
        if (hasNext) {
            ra = *(const float4*)(A + (long)(rowBase + am) * K + (k0 + 8 + ak));
            if (!transB) {
                const int gn = colBase + bn;
                rb = (gn < N) ? *(const float4*)(B + (long)(k0 + 8 + bk) * N + gn) : zero4;
            } else {
                const int gn = colBase + tbn;
                rb = (gn < N) ? *(const float4*)(B + (long)gn * K + (k0 + 8 + tbk)) : zero4;
            }
        }
#pragma unroll
        for (int kk = 0; kk < 8; kk++) {
            float a0[8], b0[8];
            *(float4*)&a0[0] = *(const float4*)&As[buf][kk][ty * 8];
            *(float4*)&a0[4] = *(const float4*)&As[buf][kk][ty * 8 + 4];
            *(float4*)&b0[0] = *(const float4*)&Bs[buf][kk][tx * 8];
            *(float4*)&b0[4] = *(const float4*)&Bs[buf][kk][tx * 8 + 4];
#pragma unroll
            for (int i = 0; i < 8; i++)
#pragma unroll
                for (int j = 0; j < 8; j++) acc[i][j] += a0[i] * b0[j];
        }
        if (hasNext) {
            const int nb = buf ^ 1;
            As[nb][ak + 0][am] = ra.x; As[nb][ak + 1][am] = ra.y;
            As[nb][ak + 2][am] = ra.z; As[nb][ak + 3][am] = ra.w;
            if (!transB) {
                *(float4*)&Bs[nb][bk][bn] = rb;
            } else {
                Bs[nb][tbk + 0][tbn] = rb.x; Bs[nb][tbk + 1][tbn] = rb.y;
                Bs[nb][tbk + 2][tbn] = rb.z; Bs[nb][tbk + 3][tbn] = rb.w;
            }
            __syncthreads();
            buf = nb;
        }
    }

    // ---- epilogue ----
#pragma unroll
    for (int i = 0; i < 8; i++) {
        const int gr = rowBase + ty * 8 + i;
        const float rm = rowMask ? rowMask[(long)bz * M + gr] : 1.f;
#pragma unroll
        for (int j = 0; j < 8; j += 4) {
            const int gc = colBase + tx * 8 + j;
            if (gc >= N) continue;
            float4 v;
            float* vp = &v.x;
#pragma unroll
            for (int t = 0; t < 4; t++) {
                float val = alpha * acc[i][j + t];
                if (bias)    val += bias[gc + t];
                if (Cin)     val += cinCoef * Cin[(long)gr * N + gc + t];
                val *= rm;
                if (colMask) val *= colMask[(long)bz * N + gc + t];
                if (act == 1)      val = fmaxf(val, 0.f);
                else if (act == 2) val = tanhf(val);
                vp[t] = val;
            }
            *(float4*)(C + (long)gr * N + gc) = v;
        }
    }
}

// ---------------------------------------------------------------------------
// Small GEMM (N < 128): 64x64 tile, 4x4/thread (from round 0)
// ---------------------------------------------------------------------------
__global__ void gemm_kernel(const float* __restrict__ A, long sA,
                            const float* __restrict__ B, long sB, int transB,
                            const float* __restrict__ bias,
                            const float* __restrict__ Cin, long sCin, float cinCoef,
                            const float* __restrict__ rowMask,
                            const float* __restrict__ colMask,
                            float* __restrict__ C, long sC,
                            int M, int N, int K, float alpha, int act)
{
    __shared__ float As[16][64];
    __shared__ float Bs[16][64];

    const int bz = blockIdx.z;
    A += (long)bz * sA;
    B += (long)bz * sB;
    C += (long)bz * sC;
    if (Cin) Cin += (long)bz * sCin;

    const int rowBase = blockIdx.y * 64;
    const int colBase = blockIdx.x * 64;
    const int tid = threadIdx.x;
    const int tx = tid & 15, ty = tid >> 4;

    float acc[4][4];
#pragma unroll
    for (int i = 0; i < 4; i++)
#pragma unroll
        for (int j = 0; j < 4; j++) acc[i][j] = 0.f;

    const int ar  = tid >> 2, ak  = (tid & 3) * 4;
    const int bkr = tid >> 4, bnc = (tid & 15) * 4;
    const int bnr = tid >> 2, bkc = (tid & 3) * 4;

    for (int k0 = 0; k0 < K; k0 += 16) {
        const int gr = rowBase + ar;
#pragma unroll
        for (int i = 0; i < 4; i++) {
            const int gk = k0 + ak + i;
            As[ak + i][ar] = (gr < M && gk < K) ? A[(long)gr * K + gk] : 0.f;
        }
        if (!transB) {
            const int gk = k0 + bkr;
#pragma unroll
            for (int i = 0; i < 4; i++) {
                const int gn = colBase + bnc + i;
                Bs[bkr][bnc + i] = (gk < K && gn < N) ? B[(long)gk * N + gn] : 0.f;
            }
        } else {
            const int gn = colBase + bnr;
#pragma unroll
            for (int i = 0; i < 4; i++) {
                const int gk = k0 + bkc + i;
                Bs[bkc + i][bnr] = (gn < N && gk < K) ? B[(long)gn * K + gk] : 0.f;
            }
        }
        __syncthreads();
#pragma unroll
        for (int kk = 0; kk < 16; kk++) {
            float a0[4], b0[4];
#pragma unroll
            for (int i = 0; i < 4; i++) a0[i] = As[kk][ty * 4 + i];
#pragma unroll
            for (int j = 0; j < 4; j++) b0[j] = Bs[kk][tx * 4 + j];
#pragma unroll
            for (int i = 0; i < 4; i++)
#pragma unroll
                for (int j = 0; j < 4; j++) acc[i][j] += a0[i] * b0[j];
        }
        __syncthreads();
    }

#pragma unroll
    for (int i = 0; i < 4; i++) {
        const int gr = rowBase + ty * 4 + i;
        if (gr >= M) continue;
#pragma unroll
        for (int j = 0; j < 4; j++) {
            const int gc = colBase + tx * 4 + j;
            if (gc >= N) continue;
            float v = alpha * acc[i][j];
            if (bias)    v += bias[gc];
            if (Cin)     v += cinCoef * Cin[(long)gr * N + gc];
            if (rowMask) v *= rowMask[(long)bz * M + gr];
            if (colMask) v *= colMask[(long)bz * N + gc];
            if (act == 1)      v = fmaxf(v, 0.f);
            else if (act == 2) v = tanhf(v);
            C[(long)gr * N + gc] = v;
        }
    }
}

// ---------------------------------------------------------------------------
// Glue kernels
// ---------------------------------------------------------------------------
__global__ void mask_kernel(const float* __restrict__ inp, float* __restrict__ mask)
{
    const int row  = blockIdx.x * 8 + (threadIdx.x >> 5);
    const int lane = threadIdx.x & 31;
    const float* p = inp + (long)row * 1024;
    float s = 0.f;
    for (int k = lane; k < 1024; k += 32) s += p[k];
#pragma unroll
    for (int o = 16; o > 0; o >>= 1) s += __shfl_xor_sync(0xffffffffu, s, o);
    if (lane == 0) mask[row] = (s != 0.f) ? 1.f : 0.f;
}

__global__ void numel_kernel(const float* __restrict__ mask, float* __restrict__ numel)
{
    const int b = blockIdx.x, tid = threadIdx.x;
    __shared__ float sh[1024];
    sh[tid] = mask[b * 1024 + tid];
    __syncthreads();
    for (int s = 512; s > 0; s >>= 1) {
        if (tid < s) sh[tid] += sh[tid + s];
        __syncthreads();
    }
    if (tid == 0) numel[b] = sh[0];
}

__global__ void mean_kernel(const float* __restrict__ fea, const float* __restrict__ numel,
                            float* __restrict__ mean)
{
    const int b = blockIdx.y;
    const int f = blockIdx.x * blockDim.x + threadIdx.x;
    const float* p = fea + (long)b * 1024 * 512 + f;
    float s = 0.f;
    for (int n = 0; n < 1024; n++) s += p[(long)n * 512];
    mean[b * 512 + f] = s / numel[b];
}

__global__ void cvec_kernel(const float* __restrict__ mean, const float* __restrict__ Wc,
                            const float* __restrict__ bc, float* __restrict__ c)
{
    const int b = blockIdx.x, j = threadIdx.x;
    float s = bc[j];
    for (int k = 0; k < 512; k++) s += mean[b * 512 + k] * Wc[k * 128 + j];
    c[b * 128 + j] = fmaxf(s, 0.f);
}

__global__ void concat_kernel(const float* __restrict__ fea, const float* __restrict__ c,
                              float* __restrict__ q)
{
    const long idx = (long)blockIdx.x * blockDim.x + threadIdx.x;
    if (idx >= 8192L * 640) return;
    const int f = (int)(idx % 640);
    const long row = idx / 640;
    const int b = (int)(row >> 10);
    q[idx] = (f < 512) ? fea[row * 512 + f] : c[b * 128 + (f - 512)];
}

__global__ void deg_kernel(const float* __restrict__ A, float* __restrict__ dinv)
{
    const int row  = blockIdx.x * 8 + (threadIdx.x >> 5);
    const int lane = threadIdx.x & 31;
    const float* p = A + (long)row * 1024;
    float s = 0.f;
    for (int j = lane; j < 1024; j += 32) s += p[j];
#pragma unroll
    for (int o = 16; o > 0; o >>= 1) s += __shfl_xor_sync(0xffffffffu, s, o);
    if (lane == 0) dinv[row] = (s > 0.f) ? rsqrtf(fmaxf(s, 1e-30f)) : 0.f;
}

__global__ void lhat_kernel(float* __restrict__ A, const float* __restrict__ dinv)
{
    const long idx = (long)blockIdx.x * blockDim.x + threadIdx.x;
    if (idx >= 8L * 1024 * 1024) return;
    const long row = idx >> 10;
    const int  j   = (int)(idx & 1023);
    const int  b   = (int)(row >> 10);
    A[idx] *= -dinv[row] * dinv[(long)b * 1024 + j];
}

__global__ void pool_kernel(const float* __restrict__ gate, const float* __restrict__ mask,
                            const float* __restrict__ x, float* __restrict__ pooled)
{
    const int b = blockIdx.x, tid = threadIdx.x;
    __shared__ float sh[1024];
    const float g = (mask[b * 1024 + tid] > 0.f) ? gate[b * 1024 + tid] : -1e9f;
    sh[tid] = g;
    __syncthreads();
    for (int s = 512; s > 0; s >>= 1) {
        if (tid < s) sh[tid] = fmaxf(sh[tid], sh[tid + s]);
        __syncthreads();
    }
    const float maxv = sh[0];
    __syncthreads();
    const float e = expf(g - maxv);
    sh[tid] = e;
    __syncthreads();
    for (int s = 512; s > 0; s >>= 1) {
        if (tid < s) sh[tid] += sh[tid + s];
        __syncthreads();
    }
    const float sum = sh[0];
    __syncthreads();
    sh[tid] = e / sum;
    __syncthreads();
    if (tid < 384) {
        float s = 0.f;
        const float* xb = x + (long)b * 1024 * 384 + tid;
        for (int n = 0; n < 1024; n++) s += sh[n] * xb[(long)n * 384];
        pooled[b * 384 + tid] = s;
    }
}

__global__ void final_kernel(const float* __restrict__ pooled, const float* __restrict__ Wm1,
                             const float* __restrict__ bm1, const float* __restrict__ Wm2,
                             const float* __restrict__ bm2, float* __restrict__ out)
{
    const int b = blockIdx.x, tid = threadIdx.x;
    __shared__ float sh[256];
    float s = bm1[tid];
    const float* p = pooled + b * 384;
    for (int k = 0; k < 384; k++) s += p[k] * Wm1[k * 256 + tid];
    sh[tid] = fmaxf(s, 0.f) * Wm2[tid];
    __syncthreads();
    for (int r = 128; r > 0; r >>= 1) {
        if (tid < r) sh[tid] += sh[tid + r];
        __syncthreads();
    }
    if (tid == 0) out[b] = 1.f / (1.f + expf(-(sh[0] + bm2[0])));
}

// ---------------------------------------------------------------------------
// Host-side GEMM launcher: dispatch big/small kernel
// ---------------------------------------------------------------------------
static void gemm(const float* A, long sA, const float* B, long sB, int transB,
                 const float* bias, const float* Cin, long sCin, float cinCoef,
                 const float* rowMask, const float* colMask,
                 float* C, long sC, int M, int N, int K, float alpha, int act, int batch)
{
    if (N >= 128 && (M % 128) == 0 && (K % 8) == 0 && (N % 4) == 0) {
        dim3 grid(CDIV(N, 128), M / 128, batch);
        gemm128_kernel<<<grid, 256>>>(A, sA, B, sB, transB, bias, Cin, sCin, cinCoef,
                                      rowMask, colMask, C, sC, M, N, K, alpha, act);
    } else {
        dim3 grid(CDIV(N, 64), CDIV(M, 64), batch);
        gemm_kernel<<<grid, 256>>>(A, sA, B, sB, transB, bias, Cin, sCin, cinCoef,
                                   rowMask, colMask, C, sC, M, N, K, alpha, act);
    }
}

// ---------------------------------------------------------------------------
// Entry point
// ---------------------------------------------------------------------------
extern "C" void kernel_launch(void* const* d_in, const int* in_sizes, int n_in,
                              void* d_out, int out_size)
{
    const float* inp = (const float*)d_in[0];
    const float* Wf1 = (const float*)d_in[2];  const float* bf1 = (const float*)d_in[3];
    const float* Wf2 = (const float*)d_in[4];  const float* bf2 = (const float*)d_in[5];
    const float* Wf3 = (const float*)d_in[6];  const float* bf3 = (const float*)d_in[7];
    const float* Wc  = (const float*)d_in[8];  const float* bc  = (const float*)d_in[9];
    const float* Wa1 = (const float*)d_in[10]; const float* ba1 = (const float*)d_in[11];
    const float* Wa2 = (const float*)d_in[12]; const float* ba2 = (const float*)d_in[13];
    const float* Wg1 = (const float*)d_in[14]; const float* bg1 = (const float*)d_in[15];
    const float* Wg2 = (const float*)d_in[16]; const float* bg2 = (const float*)d_in[17];
    const float* Wp1 = (const float*)d_in[18]; const float* bp1 = (const float*)d_in[19];
    const float* Wp2 = (const float*)d_in[20]; const float* bp2 = (const float*)d_in[21];
    const float* Wp3 = (const float*)d_in[22]; const float* bp3 = (const float*)d_in[23];
    const float* Wm1 = (const float*)d_in[24]; const float* bm1 = (const float*)d_in[25];
    const float* Wm2 = (const float*)d_in[26]; const float* bm2 = (const float*)d_in[27];
    float* out = (float*)d_out;

    float* base = nullptr;
    cudaGetSymbolAddress((void**)&base, g_scratch);

    float* mask  = base + S_MASK;
    float* numel = base + S_NUMEL;
    float* meanf = base + S_MEAN;
    float* cvec  = base + S_C;
    float* h1    = base + S_H1;
    float* h2    = base + S_H2;
    float* fea   = base + S_FEA;
    float* q     = base + S_Q;
    float* a1    = base + S_A1;
    float* af    = base + S_AF;
    float* adj   = base + S_ADJ;
    float* dinv  = base + S_DINV;
    float* Ta    = base + S_TA;
    float* Tb    = base + S_TB;
    float* Tc    = base + S_TC;
    float* x1    = base + S_X1;
    float* x2    = base + S_X2;
    float* g1    = base + S_G1;
    float* g2    = base + S_G2;
    float* gate  = base + S_GATE;
    float* pool  = base + S_POOL;

    // 1) node mask + numel
    mask_kernel<<<1024, 256>>>(inp, mask);
    numel_kernel<<<8, 1024>>>(mask, numel);

    // 2) feature extractor
    gemm(inp, 0, Wf1, 0, 0, bf1, nullptr, 0, 0.f, mask, nullptr, h1, 0, MROWS, 784, 1024, 1.f, 1, 1);
    gemm(h1,  0, Wf2, 0, 0, bf2, nullptr, 0, 0.f, mask, nullptr, h2, 0, MROWS, 512, 784,  1.f, 1, 1);
    gemm(h2,  0, Wf3, 0, 0, bf3, nullptr, 0, 0.f, mask, nullptr, fea,0, MROWS, 512, 512,  1.f, 1, 1);

    // 3) c vector
    mean_kernel<<<dim3(4, 8), 128>>>(fea, numel, meanf);
    cvec_kernel<<<8, 128>>>(meanf, Wc, bc, cvec);

    // 4) adjacency net
    concat_kernel<<<(int)CDIV(8192L * 640, 256), 256>>>(fea, cvec, q);
    gemm(q,  0, Wa1, 0, 0, ba1, nullptr, 0, 0.f, mask, nullptr, a1, 0, MROWS, 512, 640, 1.f, 1, 1);
    gemm(a1, 0, Wa2, 0, 0, ba2, nullptr, 0, 0.f, mask, nullptr, af, 0, MROWS, 384, 512, 1.f, 1, 1);

    // 5) A = (a a^T) * pairMask ; Lhat in place
    gemm(af, 1024L * 384, af, 1024L * 384, 1, nullptr, nullptr, 0, 0.f,
         mask, mask, adj, 1024L * 1024, 1024, 1024, 384, 1.f, 0, 8);
    deg_kernel<<<1024, 256>>>(adj, dinv);
    lhat_kernel<<<(int)CDIV(8L * 1024 * 1024, 256), 256>>>(adj, dinv);

    // 6) ChebConv 1: fea[.,512] -> x1[.,512], K=5
    {
        const long sT = 1024L * 512, sL = 1024L * 1024, wk = 512L * 512;
        gemm(fea, 0, Wg1, 0, 0, nullptr, nullptr, 0, 0.f, nullptr, nullptr, x1, 0, MROWS, 512, 512, 1.f, 0, 1);
        gemm(adj, sL, fea, sT, 0, nullptr, nullptr, 0, 0.f, nullptr, nullptr, Tb, sT, 1024, 512, 1024, 1.f, 0, 8);
        gemm(Tb, 0, Wg1 + wk, 0, 0, nullptr, x1, 0, 1.f, nullptr, nullptr, x1, 0, MROWS, 512, 512, 1.f, 0, 1);
        gemm(adj, sL, Tb, sT, 0, nullptr, fea, sT, -1.f, nullptr, nullptr, Tc, sT, 1024, 512, 1024, 2.f, 0, 8);
        gemm(Tc, 0, Wg1 + 2 * wk, 0, 0, nullptr, x1, 0, 1.f, nullptr, nullptr, x1, 0, MROWS, 512, 512, 1.f, 0, 1);
        gemm(adj, sL, Tc, sT, 0, nullptr, Tb, sT, -1.f, nullptr, nullptr, Ta, sT, 1024, 512, 1024, 2.f, 0, 8);
        gemm(Ta, 0, Wg1 + 3 * wk, 0, 0, nullptr, x1, 0, 1.f, nullptr, nullptr, x1, 0, MROWS, 512, 512, 1.f, 0, 1);
        gemm(adj, sL, Ta, sT, 0, nullptr, Tc, sT, -1.f, nullptr, nullptr, Tb, sT, 1024, 512, 1024, 2.f, 0, 8);
        gemm(Tb, 0, Wg1 + 4 * wk, 0, 0, bg1, x1, 0, 1.f, nullptr, nullptr, x1, 0, MROWS, 512, 512, 1.f, 1, 1);
    }

    // 7) ChebConv 2: x1[.,512] -> x2[.,384], K=5
    {
        const long sT = 1024L * 512, sL = 1024L * 1024, wk = 512L * 384;
        gemm(x1, 0, Wg2, 0, 0, nullptr, nullptr, 0, 0.f, nullptr, nullptr, x2, 0, MROWS, 384, 512, 1.f, 0, 1);
        gemm(adj, sL, x1, sT, 0, nullptr, nullptr, 0, 0.f, nullptr, nullptr, Tb, sT, 1024, 512, 1024, 1.f, 0, 8);
        gemm(Tb, 0, Wg2 + wk, 0, 0, nullptr, x2, 0, 1.f, nullptr, nullptr, x2, 0, MROWS, 384, 512, 1.f, 0, 1);
        gemm(adj, sL, Tb, sT, 0, nullptr, x1, sT, -1.f, nullptr, nullptr, Tc, sT, 1024, 512, 1024, 2.f, 0, 8);
        gemm(Tc, 0, Wg2 + 2 * wk, 0, 0, nullptr, x2, 0, 1.f, nullptr, nullptr, x2, 0, MROWS, 384, 512, 1.f, 0, 1);
        gemm(adj, sL, Tc, sT, 0, nullptr, Tb, sT, -1.f, nullptr, nullptr, Ta, sT, 1024, 512, 1024, 2.f, 0, 8);
        gemm(Ta, 0, Wg2 + 3 * wk, 0, 0, nullptr, x2, 0, 1.f, nullptr, nullptr, x2, 0, MROWS, 384, 512, 1.f, 0, 1);
        gemm(adj, sL, Ta, sT, 0, nullptr, Tc, sT, -1.f, nullptr, nullptr, Tb, sT, 1024, 512, 1024, 2.f, 0, 8);
        gemm(Tb, 0, Wg2 + 4 * wk, 0, 0, bg2, x2, 0, 1.f, nullptr, nullptr, x2, 0, MROWS, 384, 512, 1.f, 1, 1);
    }

    // 8) attention gate
    gemm(x2, 0, Wp1, 0, 0, bp1, nullptr, 0, 0.f, nullptr, nullptr, g1, 0, MROWS, 128, 384, 1.f, 1, 1);
    gemm(g1, 0, Wp2, 0, 0, bp2, nullptr, 0, 0.f, nullptr, nullptr, g2, 0, MROWS, 64, 128, 1.f, 1, 1);
    gemm(g2, 0, Wp3, 0, 0, bp3, nullptr, 0, 0.f, nullptr, nullptr, gate, 0, MROWS, 1, 64, 1.f, 2, 1);

    // 9) softmax pooling + output MLP
    pool_kernel<<<8, 1024>>>(gate, mask, x2, pool);
    final_kernel<<<8, 256>>>(pool, Wm1, bm1, Wm2, bm2, out);

    (void)in_sizes; (void)n_in; (void)out_size;
}

// round 4
// speedup vs baseline: 3.0699x; 1.9522x over previous
#include <cuda_runtime.h>
#include <math.h>
#include <stdint.h>

#define Bq 8
#define Nn 1024
#define MROWS (Bq * Nn)   // 8192

// ---------------------------------------------------------------------------
// Scratch
// ---------------------------------------------------------------------------
#define S_MASK   0L
#define S_NUMEL  (S_MASK  + 8192L)
#define S_MEAN   (S_NUMEL + 8L)
#define S_C      (S_MEAN  + 8L*512)
#define S_H1     (S_C     + 8L*128)
#define S_H2     (S_H1    + 8192L*784)
#define S_FEA    (S_H2    + 8192L*512)
#define S_Q      (S_FEA   + 8192L*512)
#define S_A1     (S_Q     + 8192L*640)
#define S_AF     (S_A1    + 8192L*512)
#define S_ADJ    (S_AF    + 8192L*384)
#define S_DINV   (S_ADJ   + 8L*1024*1024)
#define S_TA     (S_DINV  + 8192L)
#define S_TB     (S_TA    + 8192L*512)
#define S_TC     (S_TB    + 8192L*512)
#define S_X1     (S_TC    + 8192L*512)
#define S_X2     (S_X1    + 8192L*512)
#define S_G1     (S_X2    + 8192L*384)
#define S_G2     (S_G1    + 8192L*128)
#define S_GATE   (S_G2    + 8192L*64)
#define S_POOL   (S_GATE  + 8192L)
#define S_WF1T   (S_POOL  + 8L*384)
#define S_WF2T   (S_WF1T  + 784L*1024)
#define S_WF3T   (S_WF2T  + 512L*784)
#define S_WA1T   (S_WF3T  + 512L*512)
#define S_WA2T   (S_WA1T  + 512L*640)
#define S_WG1T   (S_WA2T  + 384L*512)
#define S_WG2T   (S_WG1T  + 5L*512*512)
#define S_WP1T   (S_WG2T  + 5L*384*512)
#define S_FEAT   (S_WP1T  + 128L*384)
#define S_X1T    (S_FEAT  + 8L*512*1024)
#define S_TAT    (S_X1T   + 8L*512*1024)
#define S_TBT    (S_TAT   + 8L*512*1024)
#define S_TCT    (S_TBT   + 8L*512*1024)
#define S_TOTAL  (S_TCT   + 8L*512*1024)

__device__ float g_scratch[S_TOTAL];

#define CDIV(a,b) (((a)+(b)-1)/(b))

// ---------------------------------------------------------------------------
// Portable tensor-core helpers (sm_80+ PTX only; NO tcgen05 / arch-'a' features)
// ---------------------------------------------------------------------------
__device__ __forceinline__ uint32_t tf32r(float x) {
    uint32_t r;
    asm("cvt.rna.tf32.f32 %0, %1;" : "=r"(r) : "f"(x));
    return r;
}
__device__ __forceinline__ void mma8(float* c, const uint32_t* a, const uint32_t* b) {
    asm volatile(
        "mma.sync.aligned.m16n8k8.row.col.f32.tf32.tf32.f32 "
        "{%0,%1,%2,%3}, {%4,%5,%6,%7}, {%8,%9}, {%0,%1,%2,%3};"
        : "+f"(c[0]), "+f"(c[1]), "+f"(c[2]), "+f"(c[3])
        : "r"(a[0]), "r"(a[1]), "r"(a[2]), "r"(a[3]), "r"(b[0]), "r"(b[1]));
}

// smem float-unit offsets: As/Bs tiles are [128 rows][36 pad], double buffered
#define PADR 36
#define SM_A0 0
#define SM_A1 (128 * PADR)
#define SM_B0 (2 * 128 * PADR)
#define SM_B1 (3 * 128 * PADR)
#define SM_FLOATS (4 * 128 * PADR)
#define SM_BYTES  (SM_FLOATS * 4)

// ---------------------------------------------------------------------------
// tf32 mma.sync GEMM: D[m,n] = sum_k A[m,k]*B[n,k]   (B stored [N,K] K-major)
// epilogue: C = act(alpha*D + bias + cinCoef*Cin) * rowMask * colMask
// optional transposed dual-store into Ct (layout [.., N, 1024])
// requires M % 128 == 0, N % 16 == 0, K % 16 == 0.
// ---------------------------------------------------------------------------
__global__ void __launch_bounds__(256)
mma_gemm_kernel(const float* __restrict__ A, long sA,
                const float* __restrict__ B, long sB,
                const float* __restrict__ bias,
                const float* __restrict__ Cin, long sCin, float cinCoef,
                const float* __restrict__ rowMask,
                const float* __restrict__ colMask,
                float* __restrict__ C, long sC,
                float* __restrict__ Ct, long sCt,
                int M, int N, int K, float alpha, int act)
{
    extern __shared__ float sm[];
    uint32_t* smu = (uint32_t*)sm;

    const int tid = threadIdx.x, lane = tid & 31, wid = tid >> 5;
    const int wm = wid >> 2, wn = wid & 3;      // warp grid 2 x 4
    const int bz = blockIdx.z;
    A += (long)bz * sA;
    B += (long)bz * sB;
    C += (long)bz * sC;
    if (Cin) Cin += (long)bz * sCin;
    if (Ct)  Ct  += (long)bz * sCt;
    const int rowBase = blockIdx.y * 128;
    const int colBase = blockIdx.x * 128;

    // global-load layout: thread -> (row = tid>>1, k-quad = (tid&1)*16)
    const int lr = tid >> 1;
    const int lk = (tid & 1) * 16;
    const float4 z4 = make_float4(0.f, 0.f, 0.f, 0.f);

    float acc[4][4][4];
#pragma unroll
    for (int i = 0; i < 4; i++)
#pragma unroll
        for (int j = 0; j < 4; j++)
#pragma unroll
            for (int t = 0; t < 4; t++) acc[i][j][t] = 0.f;

    const int aoff[2] = {SM_A0, SM_A1};
    const int boff[2] = {SM_B0, SM_B1};
    const int nc = (K + 31) / 32;

    float4 ra[4], rb[4];
    // ---- load chunk 0 ----
    {
        const float* asrc = A + (long)(rowBase + lr) * K + lk;
        const int gnb = colBase + lr;
        const float* bsrc = B + (long)gnb * K + lk;
        const bool bok = gnb < N;
#pragma unroll
        for (int i = 0; i < 4; i++) {
            const int gk = lk + 4 * i;
            ra[i] = (gk < K) ? *(const float4*)(asrc + 4 * i) : z4;
            rb[i] = (bok && gk < K) ? *(const float4*)(bsrc + 4 * i) : z4;
        }
#pragma unroll
        for (int i = 0; i < 4; i++) {
            const int kq = lk + 4 * i;
            uint32_t* ap = smu + SM_A0 + lr * PADR + kq;
            ap[0] = tf32r(ra[i].x); ap[1] = tf32r(ra[i].y);
            ap[2] = tf32r(ra[i].z); ap[3] = tf32r(ra[i].w);
            uint32_t* bp = smu + SM_B0 + lr * PADR + kq;
            bp[0] = tf32r(rb[i].x); bp[1] = tf32r(rb[i].y);
            bp[2] = tf32r(rb[i].z); bp[3] = tf32r(rb[i].w);
        }
    }
    __syncthreads();

    int buf = 0;
    for (int c = 0; c < nc; c++) {
        const bool hasNext = (c + 1) < nc;
        if (hasNext) {
            const int k0 = (c + 1) * 32;
            const float* asrc = A + (long)(rowBase + lr) * K + k0 + lk;
            const int gnb = colBase + lr;
            const float* bsrc = B + (long)gnb * K + k0 + lk;
            const bool bok = gnb < N;
#pragma unroll
            for (int i = 0; i < 4; i++) {
                const int gk = k0 + lk + 4 * i;
                ra[i] = (gk < K) ? *(const float4*)(asrc + 4 * i) : z4;
                rb[i] = (bok && gk < K) ? *(const float4*)(bsrc + 4 * i) : z4;
            }
        }
        // ---- compute on buf ----
        const uint32_t* Ab = smu + aoff[buf];
        const uint32_t* Bb = smu + boff[buf];
#pragma unroll
        for (int ks = 0; ks < 4; ks++) {
            const int kq = ks * 8 + (lane & 3);
            uint32_t af[4][4];
#pragma unroll
            for (int i = 0; i < 4; i++) {
                const int r = wm * 64 + i * 16 + (lane >> 2);
                af[i][0] = Ab[r * PADR + kq];
                af[i][1] = Ab[(r + 8) * PADR + kq];
                af[i][2] = Ab[r * PADR + kq + 4];
                af[i][3] = Ab[(r + 8) * PADR + kq + 4];
            }
            uint32_t bf[4][2];
#pragma unroll
            for (int j = 0; j < 4; j++) {
                const int n = wn * 32 + j * 8 + (lane >> 2);
                bf[j][0] = Bb[n * PADR + kq];
                bf[j][1] = Bb[n * PADR + kq + 4];
            }
#pragma unroll
            for (int i = 0; i < 4; i++)
#pragma unroll
                for (int j = 0; j < 4; j++)
                    mma8(acc[i][j], af[i], bf[j]);
        }
        if (hasNext) {
            const int nb = buf ^ 1;
#pragma unroll
            for (int i = 0; i < 4; i++) {
                const int kq = lk + 4 * i;
                uint32_t* ap = smu + aoff[nb] + lr * PADR + kq;
                ap[0] = tf32r(ra[i].x); ap[1] = tf32r(ra[i].y);
                ap[2] = tf32r(ra[i].z); ap[3] = tf32r(ra[i].w);
                uint32_t* bp = smu + boff[nb] + lr * PADR + kq;
                bp[0] = tf32r(rb[i].x); bp[1] = tf32r(rb[i].y);
                bp[2] = tf32r(rb[i].z); bp[3] = tf32r(rb[i].w);
            }
            __syncthreads();
            buf = nb;
        }
    }

    // ---- epilogue ----
#pragma unroll
    for (int i = 0; i < 4; i++) {
        const int gr0 = rowBase + wm * 64 + i * 16 + (lane >> 2);
#pragma unroll
        for (int half = 0; half < 2; half++) {
            const int gr = gr0 + half * 8;
            const float rm = rowMask ? rowMask[(long)bz * M + gr] : 1.f;
            const long tbase = Ct ? (((long)(gr >> 10)) * ((long)N * 1024) + (gr & 1023)) : 0;
#pragma unroll
            for (int j = 0; j < 4; j++) {
                const int gcb = colBase + wn * 32 + j * 8;
                if (gcb >= N) continue;
                const int gc = gcb + 2 * (lane & 3);
                float v0 = alpha * acc[i][j][half * 2 + 0];
                float v1 = alpha * acc[i][j][half * 2 + 1];
                if (bias) { v0 += bias[gc]; v1 += bias[gc + 1]; }
                if (Cin) {
                    v0 += cinCoef * Cin[(long)gr * N + gc];
                    v1 += cinCoef * Cin[(long)gr * N + gc + 1];
                }
                v0 *= rm; v1 *= rm;
                if (colMask) {
                    v0 *= colMask[(long)bz * N + gc];
                    v1 *= colMask[(long)bz * N + gc + 1];
                }
                if (act == 1) { v0 = fmaxf(v0, 0.f); v1 = fmaxf(v1, 0.f); }
                else if (act == 2) { v0 = tanhf(v0); v1 = tanhf(v1); }
                *(float2*)(C + (long)gr * N + gc) = make_float2(v0, v1);
                if (Ct) {
                    Ct[tbase + (long)gc * 1024] = v0;
                    Ct[tbase + (long)(gc + 1) * 1024] = v1;
                }
            }
        }
    }
}

// ---------------------------------------------------------------------------
// Small GEMM (N < 128): 64x64 tile, B stored [K,N]
// ---------------------------------------------------------------------------
__global__ void gemm_kernel(const float* __restrict__ A,
                            const float* __restrict__ B,
                            const float* __restrict__ bias,
                            float* __restrict__ C,
                            int M, int N, int K, int act)
{
    __shared__ float As[16][64];
    __shared__ float Bs[16][64];

    const int rowBase = blockIdx.y * 64;
    const int colBase = blockIdx.x * 64;
    const int tid = threadIdx.x;
    const int tx = tid & 15, ty = tid >> 4;

    float acc[4][4];
#pragma unroll
    for (int i = 0; i < 4; i++)
#pragma unroll
        for (int j = 0; j < 4; j++) acc[i][j] = 0.f;

    const int ar  = tid >> 2, ak  = (tid & 3) * 4;
    const int bkr = tid >> 4, bnc = (tid & 15) * 4;

    for (int k0 = 0; k0 < K; k0 += 16) {
        const int gr = rowBase + ar;
#pragma unroll
        for (int i = 0; i < 4; i++) {
            const int gk = k0 + ak + i;
            As[ak + i][ar] = (gr < M && gk < K) ? A[(long)gr * K + gk] : 0.f;
        }
        const int gk = k0 + bkr;
#pragma unroll
        for (int i = 0; i < 4; i++) {
            const int gn = colBase + bnc + i;
            Bs[bkr][bnc + i] = (gk < K && gn < N) ? B[(long)gk * N + gn] : 0.f;
        }
        __syncthreads();
#pragma unroll
        for (int kk = 0; kk < 16; kk++) {
            float a0[4], b0[4];
#pragma unroll
            for (int i = 0; i < 4; i++) a0[i] = As[kk][ty * 4 + i];
#pragma unroll
            for (int j = 0; j < 4; j++) b0[j] = Bs[kk][tx * 4 + j];
#pragma unroll
            for (int i = 0; i < 4; i++)
#pragma unroll
                for (int j = 0; j < 4; j++) acc[i][j] += a0[i] * b0[j];
        }
        __syncthreads();
    }

#pragma unroll
    for (int i = 0; i < 4; i++) {
        const int gr = rowBase + ty * 4 + i;
        if (gr >= M) continue;
#pragma unroll
        for (int j = 0; j < 4; j++) {
            const int gc = colBase + tx * 4 + j;
            if (gc >= N) continue;
            float v = acc[i][j];
            if (bias) v += bias[gc];
            if (act == 1)      v = fmaxf(v, 0.f);
            else if (act == 2) v = tanhf(v);
            C[(long)gr * N + gc] = v;
        }
    }
}

// ---------------------------------------------------------------------------
// Transpose: in [R,C] -> out [C,R]
// ---------------------------------------------------------------------------
__global__ void transpose_kernel(const float* __restrict__ in, float* __restrict__ out,
                                 int R, int C)
{
    __shared__ float t[32][33];
    const int c0 = blockIdx.x * 32, r0 = blockIdx.y * 32;
    const int x = threadIdx.x, y = threadIdx.y;   // 32 x 8
#pragma unroll
    for (int i = y; i < 32; i += 8) {
        const int r = r0 + i, c = c0 + x;
        if (r < R && c < C) t[i][x] = in[(long)r * C + c];
    }
    __syncthreads();
#pragma unroll
    for (int i = y; i < 32; i += 8) {
        const int oc = c0 + i, orr = r0 + x;
        if (oc < C && orr < R) out[(long)oc * R + orr] = t[x][i];
    }
}

// ---------------------------------------------------------------------------
// Glue kernels
// ---------------------------------------------------------------------------
__global__ void mask_kernel(const float* __restrict__ inp, float* __restrict__ mask)
{
    const int row  = blockIdx.x * 8 + (threadIdx.x >> 5);
    const int lane = threadIdx.x & 31;
    const float* p = inp + (long)row * 1024;
    float s = 0.f;
    for (int k = lane; k < 1024; k += 32) s += p[k];
#pragma unroll
    for (int o = 16; o > 0; o >>= 1) s += __shfl_xor_sync(0xffffffffu, s, o);
    if (lane == 0) mask[row] = (s != 0.f) ? 1.f : 0.f;
}

__global__ void numel_kernel(const float* __restrict__ mask, float* __restrict__ numel)
{
    const int b = blockIdx.x, tid = threadIdx.x;
    __shared__ float sh[1024];
    sh[tid] = mask[b * 1024 + tid];
    __syncthreads();
    for (int s = 512; s > 0; s >>= 1) {
        if (tid < s) sh[tid] += sh[tid + s];
        __syncthreads();
    }
    if (tid == 0) numel[b] = sh[0];
}

__global__ void mean_kernel(const float* __restrict__ fea, const float* __restrict__ numel,
                            float* __restrict__ mean)
{
    const int b = blockIdx.y;
    const int f = blockIdx.x * blockDim.x + threadIdx.x;
    const float* p = fea + (long)b * 1024 * 512 + f;
    float s = 0.f;
    for (int n = 0; n < 1024; n++) s += p[(long)n * 512];
    mean[b * 512 + f] = s / numel[b];
}

__global__ void cvec_kernel(const float* __restrict__ mean, const float* __restrict__ Wc,
                            const float* __restrict__ bc, float* __restrict__ c)
{
    const int b = blockIdx.x, j = threadIdx.x;
    float s = bc[j];
    for (int k = 0; k < 512; k++) s += mean[b * 512 + k] * Wc[k * 128 + j];
    c[b * 128 + j] = fmaxf(s, 0.f);
}

__global__ void concat_kernel(const float* __restrict__ fea, const float* __restrict__ c,
                              float* __restrict__ q)
{
    const long idx = (long)blockIdx.x * blockDim.x + threadIdx.x;
    if (idx >= 8192L * 640) return;
    const int f = (int)(idx % 640);
    const long row = idx / 640;
    const int b = (int)(row >> 10);
    q[idx] = (f < 512) ? fea[row * 512 + f] : c[b * 128 + (f - 512)];
}

__global__ void deg_kernel(const float* __restrict__ A, float* __restrict__ dinv)
{
    const int row  = blockIdx.x * 8 + (threadIdx.x >> 5);
    const int lane = threadIdx.x & 31;
    const float* p = A + (long)row * 1024;
    float s = 0.f;
    for (int j = lane; j < 1024; j += 32) s += p[j];
#pragma unroll
    for (int o = 16; o > 0; o >>= 1) s += __shfl_xor_sync(0xffffffffu, s, o);
    if (lane == 0) dinv[row] = (s > 0.f) ? rsqrtf(fmaxf(s, 1e-30f)) : 0.f;
}

__global__ void lhat_kernel(float* __restrict__ A, const float* __restrict__ dinv)
{
    const long idx = (long)blockIdx.x * blockDim.x + threadIdx.x;
    if (idx >= 8L * 1024 * 1024) return;
    const long row = idx >> 10;
    const int  j   = (int)(idx & 1023);
    const int  b   = (int)(row >> 10);
    A[idx] *= -dinv[row] * dinv[(long)b * 1024 + j];
}

__global__ void pool_kernel(const float* __restrict__ gate, const float* __restrict__ mask,
                            const float* __restrict__ x, float* __restrict__ pooled)
{
    const int b = blockIdx.x, tid = threadIdx.x;
    __shared__ float sh[1024];
    const float g = (mask[b * 1024 + tid] > 0.f) ? gate[b * 1024 + tid] : -1e9f;
    sh[tid] = g;
    __syncthreads();
    for (int s = 512; s > 0; s >>= 1) {
        if (tid < s) sh[tid] = fmaxf(sh[tid], sh[tid + s]);
        __syncthreads();
    }
    const float maxv = sh[0];
    __syncthreads();
    const float e = expf(g - maxv);
    sh[tid] = e;
    __syncthreads();
    for (int s = 512; s > 0; s >>= 1) {
        if (tid < s) sh[tid] += sh[tid + s];
        __syncthreads();
    }
    const float sum = sh[0];
    __syncthreads();
    sh[tid] = e / sum;
    __syncthreads();
    if (tid < 384) {
        float s = 0.f;
        const float* xb = x + (long)b * 1024 * 384 + tid;
        for (int n = 0; n < 1024; n++) s += sh[n] * xb[(long)n * 384];
        pooled[b * 384 + tid] = s;
    }
}

__global__ void final_kernel(const float* __restrict__ pooled, const float* __restrict__ Wm1,
                             const float* __restrict__ bm1, const float* __restrict__ Wm2,
                             const float* __restrict__ bm2, float* __restrict__ out)
{
    const int b = blockIdx.x, tid = threadIdx.x;
    __shared__ float sh[256];
    float s = bm1[tid];
    const float* p = pooled + b * 384;
    for (int k = 0; k < 384; k++) s += p[k] * Wm1[k * 256 + tid];
    sh[tid] = fmaxf(s, 0.f) * Wm2[tid];
    __syncthreads();
    for (int r = 128; r > 0; r >>= 1) {
        if (tid < r) sh[tid] += sh[tid + r];
        __syncthreads();
    }
    if (tid == 0) out[b] = 1.f / (1.f + expf(-(sh[0] + bm2[0])));
}

// ---------------------------------------------------------------------------
// Host-side launchers
// ---------------------------------------------------------------------------
static void tgemm(const float* A, long sA, const float* B, long sB,
                  const float* bias, const float* Cin, long sCin, float cc,
                  const float* rM, const float* cM,
                  float* C, long sC, float* Ct, long sCt,
                  int M, int N, int K, float alpha, int act, int batch)
{
    static int smemSet = 0;
    if (!smemSet) {
        cudaFuncSetAttribute(mma_gemm_kernel, cudaFuncAttributeMaxDynamicSharedMemorySize, SM_BYTES);
        smemSet = 1;
    }
    dim3 grid(CDIV(N, 128), M / 128, batch);
    mma_gemm_kernel<<<grid, 256, SM_BYTES>>>(A, sA, B, sB, bias, Cin, sCin, cc,
                                             rM, cM, C, sC, Ct, sCt, M, N, K, alpha, act);
}

static void transpose(const float* in, float* out, int R, int C)
{
    dim3 grid(CDIV(C, 32), CDIV(R, 32));
    transpose_kernel<<<grid, dim3(32, 8)>>>(in, out, R, C);
}

// ---------------------------------------------------------------------------
// Entry point
// ---------------------------------------------------------------------------
extern "C" void kernel_launch(void* const* d_in, const int* in_sizes, int n_in,
                              void* d_out, int out_size)
{
    const float* inp = (const float*)d_in[0];
    const float* Wf1 = (const float*)d_in[2];  const float* bf1 = (const float*)d_in[3];
    const float* Wf2 = (const float*)d_in[4];  const float* bf2 = (const float*)d_in[5];
    const float* Wf3 = (const float*)d_in[6];  const float* bf3 = (const float*)d_in[7];
    const float* Wc  = (const float*)d_in[8];  const float* bc  = (const float*)d_in[9];
    const float* Wa1 = (const float*)d_in[10]; const float* ba1 = (const float*)d_in[11];
    const float* Wa2 = (const float*)d_in[12]; const float* ba2 = (const float*)d_in[13];
    const float* Wg1 = (const float*)d_in[14]; const float* bg1 = (const float*)d_in[15];
    const float* Wg2 = (const float*)d_in[16]; const float* bg2 = (const float*)d_in[17];
    const float* Wp1 = (const float*)d_in[18]; const float* bp1 = (const float*)d_in[19];
    const float* Wp2 = (const float*)d_in[20]; const float* bp2 = (const float*)d_in[21];
    const float* Wp3 = (const float*)d_in[22]; const float* bp3 = (const float*)d_in[23];
    const float* Wm1 = (const float*)d_in[24]; const float* bm1 = (const float*)d_in[25];
    const float* Wm2 = (const float*)d_in[26]; const float* bm2 = (const float*)d_in[27];
    float* out = (float*)d_out;

    float* base = nullptr;
    cudaGetSymbolAddress((void**)&base, g_scratch);

    float* mask  = base + S_MASK;
    float* numel = base + S_NUMEL;
    float* meanf = base + S_MEAN;
    float* cvec  = base + S_C;
    float* h1    = base + S_H1;
    float* h2    = base + S_H2;
    float* fea   = base + S_FEA;
    float* q     = base + S_Q;
    float* a1    = base + S_A1;
    float* af    = base + S_AF;
    float* adj   = base + S_ADJ;
    float* dinv  = base + S_DINV;
    float* Ta    = base + S_TA;
    float* Tb    = base + S_TB;
    float* Tc    = base + S_TC;
    float* x1    = base + S_X1;
    float* x2    = base + S_X2;
    float* g1    = base + S_G1;
    float* g2    = base + S_G2;
    float* gate  = base + S_GATE;
    float* pool  = base + S_POOL;
    float* Wf1t  = base + S_WF1T;
    float* Wf2t  = base + S_WF2T;
    float* Wf3t  = base + S_WF3T;
    float* Wa1t  = base + S_WA1T;
    float* Wa2t  = base + S_WA2T;
    float* Wg1t  = base + S_WG1T;
    float* Wg2t  = base + S_WG2T;
    float* Wp1t  = base + S_WP1T;
    float* feaT  = base + S_FEAT;
    float* x1T   = base + S_X1T;
    float* TaT   = base + S_TAT;
    float* TbT   = base + S_TBT;
    float* TcT   = base + S_TCT;

    // 0) weight transposes (B-operand format: [N,K])
    transpose(Wf1, Wf1t, 1024, 784);
    transpose(Wf2, Wf2t, 784, 512);
    transpose(Wf3, Wf3t, 512, 512);
    transpose(Wa1, Wa1t, 640, 512);
    transpose(Wa2, Wa2t, 512, 384);
    for (int k = 0; k < 5; k++) transpose(Wg1 + (long)k * 512 * 512, Wg1t + (long)k * 512 * 512, 512, 512);
    for (int k = 0; k < 5; k++) transpose(Wg2 + (long)k * 512 * 384, Wg2t + (long)k * 384 * 512, 512, 384);
    transpose(Wp1, Wp1t, 384, 128);

    // 1) node mask + numel
    mask_kernel<<<1024, 256>>>(inp, mask);
    numel_kernel<<<8, 1024>>>(mask, numel);

    // 2) feature extractor (fea dual-stored -> feaT)
    tgemm(inp, 0, Wf1t, 0, bf1, nullptr, 0, 0.f, mask, nullptr, h1, 0, nullptr, 0, MROWS, 784, 1024, 1.f, 1, 1);
    tgemm(h1,  0, Wf2t, 0, bf2, nullptr, 0, 0.f, mask, nullptr, h2, 0, nullptr, 0, MROWS, 512, 784,  1.f, 1, 1);
    tgemm(h2,  0, Wf3t, 0, bf3, nullptr, 0, 0.f, mask, nullptr, fea, 0, feaT, 0, MROWS, 512, 512,  1.f, 1, 1);

    // 3) c vector
    mean_kernel<<<dim3(4, 8), 128>>>(fea, numel, meanf);
    cvec_kernel<<<8, 128>>>(meanf, Wc, bc, cvec);

    // 4) adjacency net
    concat_kernel<<<(int)CDIV(8192L * 640, 256), 256>>>(fea, cvec, q);
    tgemm(q,  0, Wa1t, 0, ba1, nullptr, 0, 0.f, mask, nullptr, a1, 0, nullptr, 0, MROWS, 512, 640, 1.f, 1, 1);
    tgemm(a1, 0, Wa2t, 0, ba2, nullptr, 0, 0.f, mask, nullptr, af, 0, nullptr, 0, MROWS, 384, 512, 1.f, 1, 1);

    // 5) A = (a a^T) * pairMask ; Lhat in place.  af is its own [N,K] operand.
    tgemm(af, 1024L * 384, af, 1024L * 384, nullptr, nullptr, 0, 0.f,
          mask, mask, adj, 1024L * 1024, nullptr, 0, 1024, 1024, 384, 1.f, 0, 8);
    deg_kernel<<<1024, 256>>>(adj, dinv);
    lhat_kernel<<<(int)CDIV(8L * 1024 * 1024, 256), 256>>>(adj, dinv);

    const long sT = 1024L * 512, sL = 1024L * 1024;

    // 6) ChebConv 1: K=5, 512 -> 512 (Lhat symmetric => usable as [N,K] directly)
    {
        const long wk = 512L * 512;
        tgemm(fea, 0, Wg1t, 0, nullptr, nullptr, 0, 0.f, nullptr, nullptr, x1, 0, nullptr, 0, MROWS, 512, 512, 1.f, 0, 1);
        tgemm(adj, sL, feaT, sT, nullptr, nullptr, 0, 0.f, nullptr, nullptr, Tb, sT, TbT, sT, 1024, 512, 1024, 1.f, 0, 8);
        tgemm(Tb, 0, Wg1t + wk, 0, nullptr, x1, 0, 1.f, nullptr, nullptr, x1, 0, nullptr, 0, MROWS, 512, 512, 1.f, 0, 1);
        tgemm(adj, sL, TbT, sT, nullptr, fea, sT, -1.f, nullptr, nullptr, Tc, sT, TcT, sT, 1024, 512, 1024, 2.f, 0, 8);
        tgemm(Tc, 0, Wg1t + 2 * wk, 0, nullptr, x1, 0, 1.f, nullptr, nullptr, x1, 0, nullptr, 0, MROWS, 512, 512, 1.f, 0, 1);
        tgemm(adj, sL, TcT, sT, nullptr, Tb, sT, -1.f, nullptr, nullptr, Ta, sT, TaT, sT, 1024, 512, 1024, 2.f, 0, 8);
        tgemm(Ta, 0, Wg1t + 3 * wk, 0, nullptr, x1, 0, 1.f, nullptr, nullptr, x1, 0, nullptr, 0, MROWS, 512, 512, 1.f, 0, 1);
        tgemm(adj, sL, TaT, sT, nullptr, Tc, sT, -1.f, nullptr, nullptr, Tb, sT, nullptr, 0, 1024, 512, 1024, 2.f, 0, 8);
        tgemm(Tb, 0, Wg1t + 4 * wk, 0, bg1, x1, 0, 1.f, nullptr, nullptr, x1, 0, x1T, 0, MROWS, 512, 512, 1.f, 1, 1);
    }

    // 7) ChebConv 2: K=5, 512 -> 384
    {
        const long wk = 384L * 512;
        tgemm(x1, 0, Wg2t, 0, nullptr, nullptr, 0, 0.f, nullptr, nullptr, x2, 0, nullptr, 0, MROWS, 384, 512, 1.f, 0, 1);
        tgemm(adj, sL, x1T, sT, nullptr, nullptr, 0, 0.f, nullptr, nullptr, Tb, sT, TbT, sT, 1024, 512, 1024, 1.f, 0, 8);
        tgemm(Tb, 0, Wg2t + wk, 0, nullptr, x2, 0, 1.f, nullptr, nullptr, x2, 0, nullptr, 0, MROWS, 384, 512, 1.f, 0, 1);
        tgemm(adj, sL, TbT, sT, nullptr, x1, sT, -1.f, nullptr, nullptr, Tc, sT, TcT, sT, 1024, 512, 1024, 2.f, 0, 8);
        tgemm(Tc, 0, Wg2t + 2 * wk, 0, nullptr, x2, 0, 1.f, nullptr, nullptr, x2, 0, nullptr, 0, MROWS, 384, 512, 1.f, 0, 1);
        tgemm(adj, sL, TcT, sT, nullptr, Tb, sT, -1.f, nullptr, nullptr, Ta, sT, TaT, sT, 1024, 512, 1024, 2.f, 0, 8);
        tgemm(Ta, 0, Wg2t + 3 * wk, 0, nullptr, x2, 0, 1.f, nullptr, nullptr, x2, 0, nullptr, 0, MROWS, 384, 512, 1.f, 0, 1);
        tgemm(adj, sL, TaT, sT, nullptr, Tc, sT, -1.f, nullptr, nullptr, Tb, sT, nullptr, 0, 1024, 512, 1024, 2.f, 0, 8);
        tgemm(Tb, 0, Wg2t + 4 * wk, 0, bg2, x2, 0, 1.f, nullptr, nullptr, x2, 0, nullptr, 0, MROWS, 384, 512, 1.f, 1, 1);
    }

    // 8) attention gate
    tgemm(x2, 0, Wp1t, 0, bp1, nullptr, 0, 0.f, nullptr, nullptr, g1, 0, nullptr, 0, MROWS, 128, 384, 1.f, 1, 1);
    gemm_kernel<<<dim3(1, 128), 256>>>(g1, Wp2, bp2, g2, MROWS, 64, 128, 1);
    gemm_kernel<<<dim3(1, 128), 256>>>(g2, Wp3, bp3, gate, MROWS, 1, 64, 2);

    // 9) softmax pooling + output MLP
    pool_kernel<<<8, 1024>>>(gate, mask, x2, pool);
    final_kernel<<<8, 256>>>(pool, Wm1, bm1, Wm2, bm2, out);

    (void)in_sizes; (void)n_in; (void)out_size;
}

// round 5
// speedup vs baseline: 4.1579x; 1.3544x over previous
#include <cuda_runtime.h>
#include <math.h>
#include <stdint.h>

#define Bq 8
#define Nn 1024
#define MROWS (Bq * Nn)   // 8192

// ---------------------------------------------------------------------------
// Scratch
// ---------------------------------------------------------------------------
#define S_MASK   0L
#define S_NUMEL  (S_MASK  + 8192L)
#define S_MEAN   (S_NUMEL + 8L)
#define S_C      (S_MEAN  + 8L*512)
#define S_H1     (S_C     + 8L*128)
#define S_H2     (S_H1    + 8192L*784)
#define S_FEA    (S_H2    + 8192L*512)
#define S_Q      (S_FEA   + 8192L*512)
#define S_A1     (S_Q     + 8192L*640)
#define S_AF     (S_A1    + 8192L*512)
#define S_ADJ    (S_AF    + 8192L*384)
#define S_DINV   (S_ADJ   + 8L*1024*1024)
#define S_TA     (S_DINV  + 8192L)
#define S_TB     (S_TA    + 8192L*512)
#define S_TC     (S_TB    + 8192L*512)
#define S_X1     (S_TC    + 8192L*512)
#define S_X2     (S_X1    + 8192L*512)
#define S_G1     (S_X2    + 8192L*384)
#define S_G2     (S_G1    + 8192L*128)
#define S_GATE   (S_G2    + 8192L*64)
#define S_POOL   (S_GATE  + 8192L)
#define S_WF1T   (S_POOL  + 8L*384)
#define S_WF2T   (S_WF1T  + 784L*1024)
#define S_WF3T   (S_WF2T  + 512L*784)
#define S_WA1T   (S_WF3T  + 512L*512)
#define S_WA2T   (S_WA1T  + 512L*640)
#define S_WG1T   (S_WA2T  + 384L*512)
#define S_WG2T   (S_WG1T  + 5L*512*512)
#define S_WP1T   (S_WG2T  + 5L*384*512)
#define S_FEAT   (S_WP1T  + 128L*384)
#define S_X1T    (S_FEAT  + 8L*512*1024)
#define S_TAT    (S_X1T   + 8L*512*1024)
#define S_TBT    (S_TAT   + 8L*512*1024)
#define S_TCT    (S_TBT   + 8L*512*1024)
#define S_TOTAL  (S_TCT   + 8L*512*1024)

__device__ float g_scratch[S_TOTAL];

#define CDIV(a,b) (((a)+(b)-1)/(b))

// ---------------------------------------------------------------------------
// Portable bf16 tensor-core helpers (sm_80+ PTX; no arch-'a' features)
// ---------------------------------------------------------------------------
__device__ __forceinline__ uint32_t bfpack(float lo, float hi) {
    uint32_t r;
    asm("cvt.rn.bf16x2.f32 %0, %1, %2;" : "=r"(r) : "f"(hi), "f"(lo));
    return r;
}
__device__ __forceinline__ uint32_t sm_u32(const void* p) {
    uint32_t a;
    asm("{ .reg .u64 t; cvta.to.shared.u64 t, %1; cvt.u32.u64 %0, t; }"
        : "=r"(a) : "l"(p));
    return a;
}
__device__ __forceinline__ void ldmx4(uint32_t& r0, uint32_t& r1, uint32_t& r2,
                                      uint32_t& r3, uint32_t addr) {
    asm volatile("ldmatrix.sync.aligned.m8n8.x4.shared.b16 {%0,%1,%2,%3}, [%4];"
                 : "=r"(r0), "=r"(r1), "=r"(r2), "=r"(r3) : "r"(addr));
}
__device__ __forceinline__ void mma16(float* c, const uint32_t* a, const uint32_t* b) {
    asm volatile(
        "mma.sync.aligned.m16n8k16.row.col.f32.bf16.bf16.f32 "
        "{%0,%1,%2,%3}, {%4,%5,%6,%7}, {%8,%9}, {%0,%1,%2,%3};"
        : "+f"(c[0]), "+f"(c[1]), "+f"(c[2]), "+f"(c[3])
        : "r"(a[0]), "r"(a[1]), "r"(a[2]), "r"(a[3]), "r"(b[0]), "r"(b[1]));
}

// smem byte offsets: bf16 tiles [128 rows][32 k] = 8192B each, double buffered
#define SMB_A0 0
#define SMB_A1 8192
#define SMB_B0 16384
#define SMB_B1 24576

// ---------------------------------------------------------------------------
// bf16 mma.sync GEMM: D[m,n] = sum_k A[m,k]*B[n,k]   (A fp32 [M,K]; B fp32 [N,K])
// inputs converted to bf16 (rn) at smem fill; fp32 accumulate.
// epilogue: C = act(alpha*D + bias + cinCoef*Cin) * rowMask * colMask
// optional transposed dual-store into Ct (layout [.., N, 1024])
// requires M % 128 == 0, N % 16 == 0, K % 16 == 0.
// ---------------------------------------------------------------------------
__global__ void __launch_bounds__(256)
mma_gemm_kernel(const float* __restrict__ A, long sA,
                const float* __restrict__ B, long sB,
                const float* __restrict__ bias,
                const float* __restrict__ Cin, long sCin, float cinCoef,
                const float* __restrict__ rowMask,
                const float* __restrict__ colMask,
                float* __restrict__ C, long sC,
                float* __restrict__ Ct, long sCt,
                int M, int N, int K, float alpha, int act)
{
    __shared__ __align__(16) char smem[32768];
    const uint32_t sbase = sm_u32(smem);

    const int tid = threadIdx.x, lane = tid & 31, wid = tid >> 5;
    const int wm = wid >> 2, wn = wid & 3;      // warp grid 2 x 4 (64x32 per warp)
    const int bz = blockIdx.z;
    A += (long)bz * sA;
    B += (long)bz * sB;
    C += (long)bz * sC;
    if (Cin) Cin += (long)bz * sCin;
    if (Ct)  Ct  += (long)bz * sCt;
    const int rowBase = blockIdx.y * 128;
    const int colBase = blockIdx.x * 128;

    // global-load layout: thread -> (row = tid>>1, k-halfchunk = (tid&1)*16)
    const int lr = tid >> 1;
    const int lk = (tid & 1) * 16;
    const int swz = (lr >> 1) & 3;            // 16B-chunk XOR swizzle key
    const int c0 = (tid & 1) * 2;             // logical chunk of this thread's 16 k
    const float4 z4 = make_float4(0.f, 0.f, 0.f, 0.f);

    float acc[4][4][4];
#pragma unroll
    for (int i = 0; i < 4; i++)
#pragma unroll
        for (int j = 0; j < 4; j++)
#pragma unroll
            for (int t = 0; t < 4; t++) acc[i][j][t] = 0.f;

    const int aoff[2] = {SMB_A0, SMB_A1};
    const int boff[2] = {SMB_B0, SMB_B1};
    const int nc = (K + 31) / 32;

    // register staging for prefetch (already bf16-packed)
    uint4 ua0, ua1, ub0, ub1;

    // ---- load + convert chunk 0 ----
    {
        const bool aok = lk < K;
        const float* asrc = A + (long)(rowBase + lr) * K + lk;
        float4 v0 = aok ? *(const float4*)(asrc)      : z4;
        float4 v1 = aok ? *(const float4*)(asrc + 4)  : z4;
        float4 v2 = aok ? *(const float4*)(asrc + 8)  : z4;
        float4 v3 = aok ? *(const float4*)(asrc + 12) : z4;
        ua0 = make_uint4(bfpack(v0.x, v0.y), bfpack(v0.z, v0.w),
                         bfpack(v1.x, v1.y), bfpack(v1.z, v1.w));
        ua1 = make_uint4(bfpack(v2.x, v2.y), bfpack(v2.z, v2.w),
                         bfpack(v3.x, v3.y), bfpack(v3.z, v3.w));
        const int gn = colBase + lr;
        const bool bok = (gn < N) && (lk < K);
        const float* bsrc = B + (long)gn * K + lk;
        v0 = bok ? *(const float4*)(bsrc)      : z4;
        v1 = bok ? *(const float4*)(bsrc + 4)  : z4;
        v2 = bok ? *(const float4*)(bsrc + 8)  : z4;
        v3 = bok ? *(const float4*)(bsrc + 12) : z4;
        ub0 = make_uint4(bfpack(v0.x, v0.y), bfpack(v0.z, v0.w),
                         bfpack(v1.x, v1.y), bfpack(v1.z, v1.w));
        ub1 = make_uint4(bfpack(v2.x, v2.y), bfpack(v2.z, v2.w),
                         bfpack(v3.x, v3.y), bfpack(v3.z, v3.w));
        char* ap = smem + SMB_A0 + lr * 64;
        *(uint4*)(ap + (((c0 + 0) ^ swz) << 4)) = ua0;
        *(uint4*)(ap + (((c0 + 1) ^ swz) << 4)) = ua1;
        char* bp = smem + SMB_B0 + lr * 64;
        *(uint4*)(bp + (((c0 + 0) ^ swz) << 4)) = ub0;
        *(uint4*)(bp + (((c0 + 1) ^ swz) << 4)) = ub1;
    }
    __syncthreads();

    // precomputed ldmatrix lane geometry
    const int lj = lane >> 3;                 // matrix index 0..3
    const int lr8 = lane & 7;                 // row within 8
    const int amrow = (lj & 1) * 8 + lr8;      // A: +8 rows for odd matrices
    const int akc  = lj >> 1;                  // A: k-chunk select (0: k0-7, 1: k8-15)
    const int bnrow = (lj >> 1) * 8 + lr8;     // B: +8 n for matrices 2,3
    const int bkc  = lj & 1;                   // B: k-chunk select

    int buf = 0;
    for (int c = 0; c < nc; c++) {
        const bool hasNext = (c + 1) < nc;
        if (hasNext) {
            const int k0 = (c + 1) * 32;
            const bool aok = (k0 + lk) < K;
            const float* asrc = A + (long)(rowBase + lr) * K + k0 + lk;
            float4 v0 = aok ? *(const float4*)(asrc)      : z4;
            float4 v1 = aok ? *(const float4*)(asrc + 4)  : z4;
            float4 v2 = aok ? *(const float4*)(asrc + 8)  : z4;
            float4 v3 = aok ? *(const float4*)(asrc + 12) : z4;
            ua0 = make_uint4(bfpack(v0.x, v0.y), bfpack(v0.z, v0.w),
                             bfpack(v1.x, v1.y), bfpack(v1.z, v1.w));
            ua1 = make_uint4(bfpack(v2.x, v2.y), bfpack(v2.z, v2.w),
                             bfpack(v3.x, v3.y), bfpack(v3.z, v3.w));
            const int gn = colBase + lr;
            const bool bok = (gn < N) && ((k0 + lk) < K);
            const float* bsrc = B + (long)gn * K + k0 + lk;
            v0 = bok ? *(const float4*)(bsrc)      : z4;
            v1 = bok ? *(const float4*)(bsrc + 4)  : z4;
            v2 = bok ? *(const float4*)(bsrc + 8)  : z4;
            v3 = bok ? *(const float4*)(bsrc + 12) : z4;
            ub0 = make_uint4(bfpack(v0.x, v0.y), bfpack(v0.z, v0.w),
                             bfpack(v1.x, v1.y), bfpack(v1.z, v1.w));
            ub1 = make_uint4(bfpack(v2.x, v2.y), bfpack(v2.z, v2.w),
                             bfpack(v3.x, v3.y), bfpack(v3.z, v3.w));
        }

        // ---- compute on buf ----
        const uint32_t abase = sbase + aoff[buf];
        const uint32_t bbase = sbase + boff[buf];
#pragma unroll
        for (int ks = 0; ks < 2; ks++) {
            uint32_t af[4][4];
#pragma unroll
            for (int i = 0; i < 4; i++) {
                const int row = wm * 64 + i * 16 + amrow;
                const int logc = ks * 2 + akc;
                const uint32_t addr = abase + row * 64 +
                                      (((logc ^ ((row >> 1) & 3)) << 4));
                ldmx4(af[i][0], af[i][1], af[i][2], af[i][3], addr);
            }
            uint32_t bf[4][2];
#pragma unroll
            for (int jj = 0; jj < 4; jj += 2) {
                const int n = wn * 32 + jj * 8 + bnrow;
                const int logc = ks * 2 + bkc;
                const uint32_t addr = bbase + n * 64 +
                                      (((logc ^ ((n >> 1) & 3)) << 4));
                ldmx4(bf[jj][0], bf[jj][1], bf[jj + 1][0], bf[jj + 1][1], addr);
            }
#pragma unroll
            for (int i = 0; i < 4; i++)
#pragma unroll
                for (int j = 0; j < 4; j++)
                    mma16(acc[i][j], af[i], bf[j]);
        }

        if (hasNext) {
            const int nb = buf ^ 1;
            __syncthreads();   // all reads of nb's previous contents done
            char* ap = smem + aoff[nb] + lr * 64;
            *(uint4*)(ap + (((c0 + 0) ^ swz) << 4)) = ua0;
            *(uint4*)(ap + (((c0 + 1) ^ swz) << 4)) = ua1;
            char* bp = smem + boff[nb] + lr * 64;
            *(uint4*)(bp + (((c0 + 0) ^ swz) << 4)) = ub0;
            *(uint4*)(bp + (((c0 + 1) ^ swz) << 4)) = ub1;
            __syncthreads();
            buf = nb;
        }
    }

    // ---- epilogue ----
#pragma unroll
    for (int i = 0; i < 4; i++) {
        const int gr0 = rowBase + wm * 64 + i * 16 + (lane >> 2);
#pragma unroll
        for (int half = 0; half < 2; half++) {
            const int gr = gr0 + half * 8;
            const float rm = rowMask ? rowMask[(long)bz * M + gr] : 1.f;
            const long tbase = Ct ? (((long)(gr >> 10)) * ((long)N * 1024) + (gr & 1023)) : 0;
#pragma unroll
            for (int j = 0; j < 4; j++) {
                const int gcb = colBase + wn * 32 + j * 8;
                if (gcb >= N) continue;
                const int gc = gcb + 2 * (lane & 3);
                float v0 = alpha * acc[i][j][half * 2 + 0];
                float v1 = alpha * acc[i][j][half * 2 + 1];
                if (bias) { v0 += bias[gc]; v1 += bias[gc + 1]; }
                if (Cin) {
                    v0 += cinCoef * Cin[(long)gr * N + gc];
                    v1 += cinCoef * Cin[(long)gr * N + gc + 1];
                }
                v0 *= rm; v1 *= rm;
                if (colMask) {
                    v0 *= colMask[(long)bz * N + gc];
                    v1 *= colMask[(long)bz * N + gc + 1];
                }
                if (act == 1) { v0 = fmaxf(v0, 0.f); v1 = fmaxf(v1, 0.f); }
                else if (act == 2) { v0 = tanhf(v0); v1 = tanhf(v1); }
                *(float2*)(C + (long)gr * N + gc) = make_float2(v0, v1);
                if (Ct) {
                    Ct[tbase + (long)gc * 1024] = v0;
                    Ct[tbase + (long)(gc + 1) * 1024] = v1;
                }
            }
        }
    }
}

// ---------------------------------------------------------------------------
// Small GEMM (N < 128): 64x64 tile, B stored [K,N]
// ---------------------------------------------------------------------------
__global__ void gemm_kernel(const float* __restrict__ A,
                            const float* __restrict__ B,
                            const float* __restrict__ bias,
                            float* __restrict__ C,
                            int M, int N, int K, int act)
{
    __shared__ float As[16][64];
    __shared__ float Bs[16][64];

    const int rowBase = blockIdx.y * 64;
    const int colBase = blockIdx.x * 64;
    const int tid = threadIdx.x;
    const int tx = tid & 15, ty = tid >> 4;

    float acc[4][4];
#pragma unroll
    for (int i = 0; i < 4; i++)
#pragma unroll
        for (int j = 0; j < 4; j++) acc[i][j] = 0.f;

    const int ar  = tid >> 2, ak  = (tid & 3) * 4;
    const int bkr = tid >> 4, bnc = (tid & 15) * 4;

    for (int k0 = 0; k0 < K; k0 += 16) {
        const int gr = rowBase + ar;
#pragma unroll
        for (int i = 0; i < 4; i++) {
            const int gk = k0 + ak + i;
            As[ak + i][ar] = (gr < M && gk < K) ? A[(long)gr * K + gk] : 0.f;
        }
        const int gk = k0 + bkr;
#pragma unroll
        for (int i = 0; i < 4; i++) {
            const int gn = colBase + bnc + i;
            Bs[bkr][bnc + i] = (gk < K && gn < N) ? B[(long)gk * N + gn] : 0.f;
        }
        __syncthreads();
#pragma unroll
        for (int kk = 0; kk < 16; kk++) {
            float a0[4], b0[4];
#pragma unroll
            for (int i = 0; i < 4; i++) a0[i] = As[kk][ty * 4 + i];
#pragma unroll
            for (int j = 0; j < 4; j++) b0[j] = Bs[kk][tx * 4 + j];
#pragma unroll
            for (int i = 0; i < 4; i++)
#pragma unroll
                for (int j = 0; j < 4; j++) acc[i][j] += a0[i] * b0[j];
        }
        __syncthreads();
    }

#pragma unroll
    for (int i = 0; i < 4; i++) {
        const int gr = rowBase + ty * 4 + i;
        if (gr >= M) continue;
#pragma unroll
        for (int j = 0; j < 4; j++) {
            const int gc = colBase + tx * 4 + j;
            if (gc >= N) continue;
            float v = acc[i][j];
            if (bias) v += bias[gc];
            if (act == 1)      v = fmaxf(v, 0.f);
            else if (act == 2) v = tanhf(v);
            C[(long)gr * N + gc] = v;
        }
    }
}

// ---------------------------------------------------------------------------
// Transpose: in [R,C] -> out [C,R]
// ---------------------------------------------------------------------------
__global__ void transpose_kernel(const float* __restrict__ in, float* __restrict__ out,
                                 int R, int C)
{
    __shared__ float t[32][33];
    const int c0 = blockIdx.x * 32, r0 = blockIdx.y * 32;
    const int x = threadIdx.x, y = threadIdx.y;   // 32 x 8
#pragma unroll
    for (int i = y; i < 32; i += 8) {
        const int r = r0 + i, c = c0 + x;
        if (r < R && c < C) t[i][x] = in[(long)r * C + c];
    }
    __syncthreads();
#pragma unroll
    for (int i = y; i < 32; i += 8) {
        const int oc = c0 + i, orr = r0 + x;
        if (oc < C && orr < R) out[(long)oc * R + orr] = t[x][i];
    }
}

// ---------------------------------------------------------------------------
// Glue kernels
// ---------------------------------------------------------------------------
__global__ void mask_kernel(const float* __restrict__ inp, float* __restrict__ mask)
{
    const int row  = blockIdx.x * 8 + (threadIdx.x >> 5);
    const int lane = threadIdx.x & 31;
    const float* p = inp + (long)row * 1024;
    float s = 0.f;
    for (int k = lane; k < 1024; k += 32) s += p[k];
#pragma unroll
    for (int o = 16; o > 0; o >>= 1) s += __shfl_xor_sync(0xffffffffu, s, o);
    if (lane == 0) mask[row] = (s != 0.f) ? 1.f : 0.f;
}

__global__ void numel_kernel(const float* __restrict__ mask, float* __restrict__ numel)
{
    const int b = blockIdx.x, tid = threadIdx.x;
    __shared__ float sh[1024];
    sh[tid] = mask[b * 1024 + tid];
    __syncthreads();
    for (int s = 512; s > 0; s >>= 1) {
        if (tid < s) sh[tid] += sh[tid + s];
        __syncthreads();
    }
    if (tid == 0) numel[b] = sh[0];
}

__global__ void mean_kernel(const float* __restrict__ fea, const float* __restrict__ numel,
                            float* __restrict__ mean)
{
    const int b = blockIdx.y;
    const int f = blockIdx.x * blockDim.x + threadIdx.x;
    const float* p = fea + (long)b * 1024 * 512 + f;
    float s = 0.f;
    for (int n = 0; n < 1024; n++) s += p[(long)n * 512];
    mean[b * 512 + f] = s / numel[b];
}

__global__ void cvec_kernel(const float* __restrict__ mean, const float* __restrict__ Wc,
                            const float* __restrict__ bc, float* __restrict__ c)
{
    const int b = blockIdx.x, j = threadIdx.x;
    float s = bc[j];
    for (int k = 0; k < 512; k++) s += mean[b * 512 + k] * Wc[k * 128 + j];
    c[b * 128 + j] = fmaxf(s, 0.f);
}

__global__ void concat_kernel(const float* __restrict__ fea, const float* __restrict__ c,
                              float* __restrict__ q)
{
    const long idx = (long)blockIdx.x * blockDim.x + threadIdx.x;
    if (idx >= 8192L * 640) return;
    const int f = (int)(idx % 640);
    const long row = idx / 640;
    const int b = (int)(row >> 10);
    q[idx] = (f < 512) ? fea[row * 512 + f] : c[b * 128 + (f - 512)];
}

__global__ void deg_kernel(const float* __restrict__ A, float* __restrict__ dinv)
{
    const int row  = blockIdx.x * 8 + (threadIdx.x >> 5);
    const int lane = threadIdx.x & 31;
    const float* p = A + (long)row * 1024;
    float s = 0.f;
    for (int j = lane; j < 1024; j += 32) s += p[j];
#pragma unroll
    for (int o = 16; o > 0; o >>= 1) s += __shfl_xor_sync(0xffffffffu, s, o);
    if (lane == 0) dinv[row] = (s > 0.f) ? rsqrtf(fmaxf(s, 1e-30f)) : 0.f;
}

__global__ void lhat_kernel(float* __restrict__ A, const float* __restrict__ dinv)
{
    const long idx = (long)blockIdx.x * blockDim.x + threadIdx.x;
    if (idx >= 8L * 1024 * 1024) return;
    const long row = idx >> 10;
    const int  j   = (int)(idx & 1023);
    const int  b   = (int)(row >> 10);
    A[idx] *= -dinv[row] * dinv[(long)b * 1024 + j];
}

__global__ void pool_kernel(const float* __restrict__ gate, const float* __restrict__ mask,
                            const float* __restrict__ x, float* __restrict__ pooled)
{
    const int b = blockIdx.x, tid = threadIdx.x;
    __shared__ float sh[1024];
    const float g = (mask[b * 1024 + tid] > 0.f) ? gate[b * 1024 + tid] : -1e9f;
    sh[tid] = g;
    __syncthreads();
    for (int s = 512; s > 0; s >>= 1) {
        if (tid < s) sh[tid] = fmaxf(sh[tid], sh[tid + s]);
        __syncthreads();
    }
    const float maxv = sh[0];
    __syncthreads();
    const float e = expf(g - maxv);
    sh[tid] = e;
    __syncthreads();
    for (int s = 512; s > 0; s >>= 1) {
        if (tid < s) sh[tid] += sh[tid + s];
        __syncthreads();
    }
    const float sum = sh[0];
    __syncthreads();
    sh[tid] = e / sum;
    __syncthreads();
    if (tid < 384) {
        float s = 0.f;
        const float* xb = x + (long)b * 1024 * 384 + tid;
        for (int n = 0; n < 1024; n++) s += sh[n] * xb[(long)n * 384];
        pooled[b * 384 + tid] = s;
    }
}

__global__ void final_kernel(const float* __restrict__ pooled, const float* __restrict__ Wm1,
                             const float* __restrict__ bm1, const float* __restrict__ Wm2,
                             const float* __restrict__ bm2, float* __restrict__ out)
{
    const int b = blockIdx.x, tid = threadIdx.x;
    __shared__ float sh[256];
    float s = bm1[tid];
    const float* p = pooled + b * 384;
    for (int k = 0; k < 384; k++) s += p[k] * Wm1[k * 256 + tid];
    sh[tid] = fmaxf(s, 0.f) * Wm2[tid];
    __syncthreads();
    for (int r = 128; r > 0; r >>= 1) {
        if (tid < r) sh[tid] += sh[tid + r];
        __syncthreads();
    }
    if (tid == 0) out[b] = 1.f / (1.f + expf(-(sh[0] + bm2[0])));
}

// ---------------------------------------------------------------------------
// Host-side launchers
// ---------------------------------------------------------------------------
static void tgemm(const float* A, long sA, const float* B, long sB,
                  const float* bias, const float* Cin, long sCin, float cc,
                  const float* rM, const float* cM,
                  float* C, long sC, float* Ct, long sCt,
                  int M, int N, int K, float alpha, int act, int batch)
{
    dim3 grid(CDIV(N, 128), M / 128, batch);
    mma_gemm_kernel<<<grid, 256>>>(A, sA, B, sB, bias, Cin, sCin, cc,
                                   rM, cM, C, sC, Ct, sCt, M, N, K, alpha, act);
}

static void transpose(const float* in, float* out, int R, int C)
{
    dim3 grid(CDIV(C, 32), CDIV(R, 32));
    transpose_kernel<<<grid, dim3(32, 8)>>>(in, out, R, C);
}

// ---------------------------------------------------------------------------
// Entry point
// ---------------------------------------------------------------------------
extern "C" void kernel_launch(void* const* d_in, const int* in_sizes, int n_in,
                              void* d_out, int out_size)
{
    const float* inp = (const float*)d_in[0];
    const float* Wf1 = (const float*)d_in[2];  const float* bf1 = (const float*)d_in[3];
    const float* Wf2 = (const float*)d_in[4];  const float* bf2 = (const float*)d_in[5];
    const float* Wf3 = (const float*)d_in[6];  const float* bf3 = (const float*)d_in[7];
    const float* Wc  = (const float*)d_in[8];  const float* bc  = (const float*)d_in[9];
    const float* Wa1 = (const float*)d_in[10]; const float* ba1 = (const float*)d_in[11];
    const float* Wa2 = (const float*)d_in[12]; const float* ba2 = (const float*)d_in[13];
    const float* Wg1 = (const float*)d_in[14]; const float* bg1 = (const float*)d_in[15];
    const float* Wg2 = (const float*)d_in[16]; const float* bg2 = (const float*)d_in[17];
    const float* Wp1 = (const float*)d_in[18]; const float* bp1 = (const float*)d_in[19];
    const float* Wp2 = (const float*)d_in[20]; const float* bp2 = (const float*)d_in[21];
    const float* Wp3 = (const float*)d_in[22]; const float* bp3 = (const float*)d_in[23];
    const float* Wm1 = (const float*)d_in[24]; const float* bm1 = (const float*)d_in[25];
    const float* Wm2 = (const float*)d_in[26]; const float* bm2 = (const float*)d_in[27];
    float* out = (float*)d_out;

    float* base = nullptr;
    cudaGetSymbolAddress((void**)&base, g_scratch);

    float* mask  = base + S_MASK;
    float* numel = base + S_NUMEL;
    float* meanf = base + S_MEAN;
    float* cvec  = base + S_C;
    float* h1    = base + S_H1;
    float* h2    = base + S_H2;
    float* fea   = base + S_FEA;
    float* q     = base + S_Q;
    float* a1    = base + S_A1;
    float* af    = base + S_AF;
    float* adj   = base + S_ADJ;
    float* dinv  = base + S_DINV;
    float* Ta    = base + S_TA;
    float* Tb    = base + S_TB;
    float* Tc    = base + S_TC;
    float* x1    = base + S_X1;
    float* x2    = base + S_X2;
    float* g1    = base + S_G1;
    float* g2    = base + S_G2;
    float* gate  = base + S_GATE;
    float* pool  = base + S_POOL;
    float* Wf1t  = base + S_WF1T;
    float* Wf2t  = base + S_WF2T;
    float* Wf3t  = base + S_WF3T;
    float* Wa1t  = base + S_WA1T;
    float* Wa2t  = base + S_WA2T;
    float* Wg1t  = base + S_WG1T;
    float* Wg2t  = base + S_WG2T;
    float* Wp1t  = base + S_WP1T;
    float* feaT  = base + S_FEAT;
    float* x1T   = base + S_X1T;
    float* TaT   = base + S_TAT;
    float* TbT   = base + S_TBT;
    float* TcT   = base + S_TCT;

    // 0) weight transposes (B-operand format: [N,K])
    transpose(Wf1, Wf1t, 1024, 784);
    transpose(Wf2, Wf2t, 784, 512);
    transpose(Wf3, Wf3t, 512, 512);
    transpose(Wa1, Wa1t, 640, 512);
    transpose(Wa2, Wa2t, 512, 384);
    for (int k = 0; k < 5; k++) transpose(Wg1 + (long)k * 512 * 512, Wg1t + (long)k * 512 * 512, 512, 512);
    for (int k = 0; k < 5; k++) transpose(Wg2 + (long)k * 512 * 384, Wg2t + (long)k * 384 * 512, 512, 384);
    transpose(Wp1, Wp1t, 384, 128);

    // 1) node mask + numel
    mask_kernel<<<1024, 256>>>(inp, mask);
    numel_kernel<<<8, 1024>>>(mask, numel);

    // 2) feature extractor (fea dual-stored -> feaT)
    tgemm(inp, 0, Wf1t, 0, bf1, nullptr, 0, 0.f, mask, nullptr, h1, 0, nullptr, 0, MROWS, 784, 1024, 1.f, 1, 1);
    tgemm(h1,  0, Wf2t, 0, bf2, nullptr, 0, 0.f, mask, nullptr, h2, 0, nullptr, 0, MROWS, 512, 784,  1.f, 1, 1);
    tgemm(h2,  0, Wf3t, 0, bf3, nullptr, 0, 0.f, mask, nullptr, fea, 0, feaT, 0, MROWS, 512, 512,  1.f, 1, 1);

    // 3) c vector
    mean_kernel<<<dim3(4, 8), 128>>>(fea, numel, meanf);
    cvec_kernel<<<8, 128>>>(meanf, Wc, bc, cvec);

    // 4) adjacency net
    concat_kernel<<<(int)CDIV(8192L * 640, 256), 256>>>(fea, cvec, q);
    tgemm(q,  0, Wa1t, 0, ba1, nullptr, 0, 0.f, mask, nullptr, a1, 0, nullptr, 0, MROWS, 512, 640, 1.f, 1, 1);
    tgemm(a1, 0, Wa2t, 0, ba2, nullptr, 0, 0.f, mask, nullptr, af, 0, nullptr, 0, MROWS, 384, 512, 1.f, 1, 1);

    // 5) A = (a a^T) * pairMask ; Lhat in place.  af is its own [N,K] operand.
    tgemm(af, 1024L * 384, af, 1024L * 384, nullptr, nullptr, 0, 0.f,
          mask, mask, adj, 1024L * 1024, nullptr, 0, 1024, 1024, 384, 1.f, 0, 8);
    deg_kernel<<<1024, 256>>>(adj, dinv);
    lhat_kernel<<<(int)CDIV(8L * 1024 * 1024, 256), 256>>>(adj, dinv);

    const long sT = 1024L * 512, sL = 1024L * 1024;

    // 6) ChebConv 1: K=5, 512 -> 512 (Lhat symmetric => usable as [N,K] directly)
    {
        const long wk = 512L * 512;
        tgemm(fea, 0, Wg1t, 0, nullptr, nullptr, 0, 0.f, nullptr, nullptr, x1, 0, nullptr, 0, MROWS, 512, 512, 1.f, 0, 1);
        tgemm(adj, sL, feaT, sT, nullptr, nullptr, 0, 0.f, nullptr, nullptr, Tb, sT, TbT, sT, 1024, 512, 1024, 1.f, 0, 8);
        tgemm(Tb, 0, Wg1t + wk, 0, nullptr, x1, 0, 1.f, nullptr, nullptr, x1, 0, nullptr, 0, MROWS, 512, 512, 1.f, 0, 1);
        tgemm(adj, sL, TbT, sT, nullptr, fea, sT, -1.f, nullptr, nullptr, Tc, sT, TcT, sT, 1024, 512, 1024, 2.f, 0, 8);
        tgemm(Tc, 0, Wg1t + 2 * wk, 0, nullptr, x1, 0, 1.f, nullptr, nullptr, x1, 0, nullptr, 0, MROWS, 512, 512, 1.f, 0, 1);
        tgemm(adj, sL, TcT, sT, nullptr, Tb, sT, -1.f, nullptr, nullptr, Ta, sT, TaT, sT, 1024, 512, 1024, 2.f, 0, 8);
        tgemm(Ta, 0, Wg1t + 3 * wk, 0, nullptr, x1, 0, 1.f, nullptr, nullptr, x1, 0, nullptr, 0, MROWS, 512, 512, 1.f, 0, 1);
        tgemm(adj, sL, TaT, sT, nullptr, Tc, sT, -1.f, nullptr, nullptr, Tb, sT, nullptr, 0, 1024, 512, 1024, 2.f, 0, 8);
        tgemm(Tb, 0, Wg1t + 4 * wk, 0, bg1, x1, 0, 1.f, nullptr, nullptr, x1, 0, x1T, 0, MROWS, 512, 512, 1.f, 1, 1);
    }

    // 7) ChebConv 2: K=5, 512 -> 384
    {
        const long wk = 384L * 512;
        tgemm(x1, 0, Wg2t, 0, nullptr, nullptr, 0, 0.f, nullptr, nullptr, x2, 0, nullptr, 0, MROWS, 384, 512, 1.f, 0, 1);
        tgemm(adj, sL, x1T, sT, nullptr, nullptr, 0, 0.f, nullptr, nullptr, Tb, sT, TbT, sT, 1024, 512, 1024, 1.f, 0, 8);
        tgemm(Tb, 0, Wg2t + wk, 0, nullptr, x2, 0, 1.f, nullptr, nullptr, x2, 0, nullptr, 0, MROWS, 384, 512, 1.f, 0, 1);
        tgemm(adj, sL, TbT, sT, nullptr, x1, sT, -1.f, nullptr, nullptr, Tc, sT, TcT, sT, 1024, 512, 1024, 2.f, 0, 8);
        tgemm(Tc, 0, Wg2t + 2 * wk, 0, nullptr, x2, 0, 1.f, nullptr, nullptr, x2, 0, nullptr, 0, MROWS, 384, 512, 1.f, 0, 1);
        tgemm(adj, sL, TcT, sT, nullptr, Tb, sT, -1.f, nullptr, nullptr, Ta, sT, TaT, sT, 1024, 512, 1024, 2.f, 0, 8);
        tgemm(Ta, 0, Wg2t + 3 * wk, 0, nullptr, x2, 0, 1.f, nullptr, nullptr, x2, 0, nullptr, 0, MROWS, 384, 512, 1.f, 0, 1);
        tgemm(adj, sL, TaT, sT, nullptr, Tc, sT, -1.f, nullptr, nullptr, Tb, sT, nullptr, 0, 1024, 512, 1024, 2.f, 0, 8);
        tgemm(Tb, 0, Wg2t + 4 * wk, 0, bg2, x2, 0, 1.f, nullptr, nullptr, x2, 0, nullptr, 0, MROWS, 384, 512, 1.f, 1, 1);
    }

    // 8) attention gate
    tgemm(x2, 0, Wp1t, 0, bp1, nullptr, 0, 0.f, nullptr, nullptr, g1, 0, nullptr, 0, MROWS, 128, 384, 1.f, 1, 1);
    gemm_kernel<<<dim3(1, 128), 256>>>(g1, Wp2, bp2, g2, MROWS, 64, 128, 1);
    gemm_kernel<<<dim3(1, 128), 256>>>(g2, Wp3, bp3, gate, MROWS, 1, 64, 2);

    // 9) softmax pooling + output MLP
    pool_kernel<<<8, 1024>>>(gate, mask, x2, pool);
    final_kernel<<<8, 256>>>(pool, Wm1, bm1, Wm2, bm2, out);

    (void)in_sizes; (void)n_in; (void)out_size;
}

// round 6
// speedup vs baseline: 5.3602x; 1.2892x over previous
#include <cuda_runtime.h>
#include <cuda_bf16.h>
#include <math.h>
#include <stdint.h>

#define Bq 8
#define Nn 1024
#define MROWS (Bq * Nn)   // 8192

// ---------------------------------------------------------------------------
// Scratch layout (float units; bf16 buffers use count/2 float slots)
// ---------------------------------------------------------------------------
#define S_MASK   0L
#define S_NUMEL  (S_MASK  + 8192L)
#define S_MEAN   (S_NUMEL + 8L)
#define S_CVEC   (S_MEAN  + 4096L)
#define S_POOL   (S_CVEC  + 1024L)
#define S_DINV   (S_POOL  + 3072L)
#define S_GATE   (S_DINV  + 8192L)
#define S_G2     (S_GATE  + 8192L)
#define S_G1     (S_G2    + 8192L*64)
#define S_FEA    (S_G1    + 8192L*128)
#define S_ADJ    (S_FEA   + 8192L*512)
#define S_X1     (S_ADJ   + 8388608L)
#define S_X2     (S_X1    + 8192L*512)
#define S_TAF    (S_X2    + 8192L*384)
#define S_TBF    (S_TAF   + 8192L*512)
#define S_TCF    (S_TBF   + 8192L*512)
// bf16 region
#define S_INPB   (S_TCF   + 8192L*512)
#define S_H1B    (S_INPB  + 4194304L)
#define S_H2B    (S_H1B   + 3211264L)
#define S_FEAB   (S_H2B   + 2097152L)
#define S_FEABT  (S_FEAB  + 2097152L)
#define S_QB     (S_FEABT + 2097152L)
#define S_A1B    (S_QB    + 2621440L)
#define S_AFB    (S_A1B   + 2097152L)
#define S_LHATB  (S_AFB   + 1572864L)
#define S_TAB    (S_LHATB + 4194304L)
#define S_TABT   (S_TAB   + 2097152L)
#define S_TBB    (S_TABT  + 2097152L)
#define S_TBBT   (S_TBB   + 2097152L)
#define S_TCB    (S_TBBT  + 2097152L)
#define S_TCBT   (S_TCB   + 2097152L)
#define S_X1B    (S_TCBT  + 2097152L)
#define S_X1BT   (S_X1B   + 2097152L)
#define S_X2B    (S_X1BT  + 2097152L)
#define S_WF1B   (S_X2B   + 1572864L)
#define S_WF2B   (S_WF1B  + 401408L)
#define S_WF3B   (S_WF2B  + 200704L)
#define S_WA1B   (S_WF3B  + 131072L)
#define S_WA2B   (S_WA1B  + 163840L)
#define S_WG1B   (S_WA2B  + 98304L)
#define S_WG2B   (S_WG1B  + 655360L)
#define S_WP1B   (S_WG2B  + 491520L)
#define S_TOTAL  (S_WP1B  + 24576L)

__device__ float g_scratch[S_TOTAL];

#define CDIV(a,b) (((a)+(b)-1)/(b))

// ---------------------------------------------------------------------------
// Portable PTX helpers (sm_80+; no arch-'a' features)
// ---------------------------------------------------------------------------
__device__ __forceinline__ uint32_t bfpack(float lo, float hi) {
    uint32_t r;
    asm("cvt.rn.bf16x2.f32 %0, %1, %2;" : "=r"(r) : "f"(hi), "f"(lo));
    return r;
}
__device__ __forceinline__ uint32_t sm_u32(const void* p) {
    uint32_t a;
    asm("{ .reg .u64 t; cvta.to.shared.u64 t, %1; cvt.u32.u64 %0, t; }"
        : "=r"(a) : "l"(p));
    return a;
}
__device__ __forceinline__ void ldmx4(uint32_t& r0, uint32_t& r1, uint32_t& r2,
                                      uint32_t& r3, uint32_t addr) {
    asm volatile("ldmatrix.sync.aligned.m8n8.x4.shared.b16 {%0,%1,%2,%3}, [%4];"
                 : "=r"(r0), "=r"(r1), "=r"(r2), "=r"(r3) : "r"(addr));
}
__device__ __forceinline__ void mma16(float* c, const uint32_t* a, const uint32_t* b) {
    asm volatile(
        "mma.sync.aligned.m16n8k16.row.col.f32.bf16.bf16.f32 "
        "{%0,%1,%2,%3}, {%4,%5,%6,%7}, {%8,%9}, {%0,%1,%2,%3};"
        : "+f"(c[0]), "+f"(c[1]), "+f"(c[2]), "+f"(c[3])
        : "r"(a[0]), "r"(a[1]), "r"(a[2]), "r"(a[3]), "r"(b[0]), "r"(b[1]));
}
__device__ __forceinline__ void cpa16(uint32_t dst, const void* src, int srcBytes) {
    asm volatile("cp.async.cg.shared.global [%0], [%1], 16, %2;\n"
                 :: "r"(dst), "l"(src), "r"(srcBytes));
}
#define CP_COMMIT() asm volatile("cp.async.commit_group;\n" ::: "memory")
#define CP_WAIT1()  asm volatile("cp.async.wait_group 1;\n" ::: "memory")
#define CP_WAIT0()  asm volatile("cp.async.wait_group 0;\n" ::: "memory")

// ---------------------------------------------------------------------------
// bf16 cp.async-pipelined mma.sync GEMM
//   D[m,n] = sum_k A[m,k]*B[n,k]; A bf16 [M,K], B bf16 [N,K]
//   v = act(alpha*D + bias + cinCoef*Cin) * rowMask * colMask
//   outputs (each optional): C fp32 [M,N]; Cb bf16 [M,N]; CbT bf16 [.., N, 1024]
//   requires M % 128 == 0, N % 16 == 0, K % 16 == 0
// ---------------------------------------------------------------------------
__global__ void __launch_bounds__(256)
mma_gemm_bf(const __nv_bfloat16* __restrict__ A, long sA,
            const __nv_bfloat16* __restrict__ B, long sB,
            const float* __restrict__ bias,
            const float* __restrict__ Cin, long sCin, float cinCoef,
            const float* __restrict__ rowMask, const float* __restrict__ colMask,
            float* __restrict__ C, long sC,
            __nv_bfloat16* __restrict__ Cb,
            unsigned short* __restrict__ CbT, long sCt,
            int M, int N, int K, float alpha, int act)
{
    __shared__ __align__(16) char smem[49152];   // 3 stages x (A 8KB + B 8KB)
    const uint32_t sbase = sm_u32(smem);

    const int tid = threadIdx.x, lane = tid & 31, wid = tid >> 5;
    const int wm = wid >> 2, wn = wid & 3;       // warp grid 2 x 4 (64x32 per warp)
    const int bz = blockIdx.z;
    A += (long)bz * sA;
    B += (long)bz * sB;
    if (C)   C   += (long)bz * sC;
    if (Cb)  Cb  += (long)bz * sC;
    if (CbT) CbT += (long)bz * sCt;
    if (Cin) Cin += (long)bz * sCin;
    const int rowBase = blockIdx.y * 128;
    const int colBase = blockIdx.x * 128;

    // load geometry: row = tid>>1, two 16B chunks per thread
    const int lr  = tid >> 1;
    const int c0  = (tid & 1) * 2;
    const int swz = (lr >> 1) & 3;
    const int gn  = colBase + lr;
    const bool nok = gn < N;
    const __nv_bfloat16* arow = A + (long)(rowBase + lr) * K;
    const __nv_bfloat16* brow = B + (long)(nok ? gn : 0) * K;

    float acc[4][4][4];
#pragma unroll
    for (int i = 0; i < 4; i++)
#pragma unroll
        for (int j = 0; j < 4; j++)
#pragma unroll
            for (int t = 0; t < 4; t++) acc[i][j][t] = 0.f;

    const int nc = (K + 31) / 32;

    auto issue = [&](int cc) {
        const int st = cc % 3;
        const uint32_t ab = sbase + st * 16384 + lr * 64;
#pragma unroll
        for (int j2 = 0; j2 < 2; j2++) {
            const int j = c0 + j2;
            const int k = cc * 32 + j * 8;
            cpa16(ab + ((j ^ swz) << 4), arow + (k < K ? k : 0), (k < K) ? 16 : 0);
        }
#pragma unroll
        for (int j2 = 0; j2 < 2; j2++) {
            const int j = c0 + j2;
            const int k = cc * 32 + j * 8;
            cpa16(ab + 8192 + ((j ^ swz) << 4), brow + (k < K ? k : 0),
                  (nok && k < K) ? 16 : 0);
        }
        CP_COMMIT();
    };

    issue(0);
    if (nc > 1) issue(1);

    // ldmatrix lane geometry
    const int lj = lane >> 3, lr8 = lane & 7;
    const int amrow = (lj & 1) * 8 + lr8, akc = lj >> 1;
    const int bnrow = (lj >> 1) * 8 + lr8, bkc = lj & 1;

    for (int c = 0; c < nc; c++) {
        if (c + 1 < nc) { CP_WAIT1(); } else { CP_WAIT0(); }
        __syncthreads();
        if (c + 2 < nc) issue(c + 2);

        const uint32_t abase = sbase + (c % 3) * 16384;
        const uint32_t bbase = abase + 8192;
#pragma unroll
        for (int ks = 0; ks < 2; ks++) {
            uint32_t af[4][4];
#pragma unroll
            for (int i = 0; i < 4; i++) {
                const int row = wm * 64 + i * 16 + amrow;
                const int logc = ks * 2 + akc;
                ldmx4(af[i][0], af[i][1], af[i][2], af[i][3],
                      abase + row * 64 + ((logc ^ ((row >> 1) & 3)) << 4));
            }
            uint32_t bf[4][2];
#pragma unroll
            for (int jj = 0; jj < 4; jj += 2) {
                const int n = wn * 32 + jj * 8 + bnrow;
                const int logc = ks * 2 + bkc;
                ldmx4(bf[jj][0], bf[jj][1], bf[jj + 1][0], bf[jj + 1][1],
                      bbase + n * 64 + ((logc ^ ((n >> 1) & 3)) << 4));
            }
#pragma unroll
            for (int i = 0; i < 4; i++)
#pragma unroll
                for (int j = 0; j < 4; j++)
                    mma16(acc[i][j], af[i], bf[j]);
        }
    }

    // ---- epilogue ----
#pragma unroll
    for (int i = 0; i < 4; i++) {
        const int gr0 = rowBase + wm * 64 + i * 16 + (lane >> 2);
#pragma unroll
        for (int half = 0; half < 2; half++) {
            const int gr = gr0 + half * 8;
            const float rm = rowMask ? rowMask[(long)bz * M + gr] : 1.f;
            const long tb = CbT ? (((long)(gr >> 10)) * ((long)N * 1024) + (gr & 1023)) : 0;
#pragma unroll
            for (int j = 0; j < 4; j++) {
                const int gcb = colBase + wn * 32 + j * 8;
                if (gcb >= N) continue;
                const int gc = gcb + 2 * (lane & 3);
                float v0 = alpha * acc[i][j][half * 2 + 0];
                float v1 = alpha * acc[i][j][half * 2 + 1];
                if (bias) { v0 += bias[gc]; v1 += bias[gc + 1]; }
                if (Cin) {
                    v0 += cinCoef * Cin[(long)gr * N + gc];
                    v1 += cinCoef * Cin[(long)gr * N + gc + 1];
                }
                v0 *= rm; v1 *= rm;
                if (colMask) {
                    v0 *= colMask[(long)bz * N + gc];
                    v1 *= colMask[(long)bz * N + gc + 1];
                }
                if (act == 1) { v0 = fmaxf(v0, 0.f); v1 = fmaxf(v1, 0.f); }
                else if (act == 2) { v0 = tanhf(v0); v1 = tanhf(v1); }
                if (C) *(float2*)(C + (long)gr * N + gc) = make_float2(v0, v1);
                const uint32_t u = bfpack(v0, v1);
                if (Cb) *(uint32_t*)((char*)Cb + ((long)gr * N + gc) * 2) = u;
                if (CbT) {
                    CbT[tb + (long)gc * 1024] = (unsigned short)u;
                    CbT[tb + (long)(gc + 1) * 1024] = (unsigned short)(u >> 16);
                }
            }
        }
    }
}

// ---------------------------------------------------------------------------
// Small GEMM (N < 128): fp32 SIMT, B stored [K,N]
// ---------------------------------------------------------------------------
__global__ void gemm_kernel(const float* __restrict__ A,
                            const float* __restrict__ B,
                            const float* __restrict__ bias,
                            float* __restrict__ C,
                            int M, int N, int K, int act)
{
    __shared__ float As[16][64];
    __shared__ float Bs[16][64];

    const int rowBase = blockIdx.y * 64;
    const int colBase = blockIdx.x * 64;
    const int tid = threadIdx.x;
    const int tx = tid & 15, ty = tid >> 4;

    float acc[4][4];
#pragma unroll
    for (int i = 0; i < 4; i++)
#pragma unroll
        for (int j = 0; j < 4; j++) acc[i][j] = 0.f;

    const int ar  = tid >> 2, ak  = (tid & 3) * 4;
    const int bkr = tid >> 4, bnc = (tid & 15) * 4;

    for (int k0 = 0; k0 < K; k0 += 16) {
        const int gr = rowBase + ar;
#pragma unroll
        for (int i = 0; i < 4; i++) {
            const int gk = k0 + ak + i;
            As[ak + i][ar] = (gr < M && gk < K) ? A[(long)gr * K + gk] : 0.f;
        }
        const int gk = k0 + bkr;
#pragma unroll
        for (int i = 0; i < 4; i++) {
            const int gnn = colBase + bnc + i;
            Bs[bkr][bnc + i] = (gk < K && gnn < N) ? B[(long)gk * N + gnn] : 0.f;
        }
        __syncthreads();
#pragma unroll
        for (int kk = 0; kk < 16; kk++) {
            float a0[4], b0[4];
#pragma unroll
            for (int i = 0; i < 4; i++) a0[i] = As[kk][ty * 4 + i];
#pragma unroll
            for (int j = 0; j < 4; j++) b0[j] = Bs[kk][tx * 4 + j];
#pragma unroll
            for (int i = 0; i < 4; i++)
#pragma unroll
                for (int j = 0; j < 4; j++) acc[i][j] += a0[i] * b0[j];
        }
        __syncthreads();
    }

#pragma unroll
    for (int i = 0; i < 4; i++) {
        const int gr = rowBase + ty * 4 + i;
        if (gr >= M) continue;
#pragma unroll
        for (int j = 0; j < 4; j++) {
            const int gc = colBase + tx * 4 + j;
            if (gc >= N) continue;
            float v = acc[i][j];
            if (bias) v += bias[gc];
            if (act == 1)      v = fmaxf(v, 0.f);
            else if (act == 2) v = tanhf(v);
            C[(long)gr * N + gc] = v;
        }
    }
}

// ---------------------------------------------------------------------------
// Conversion / glue kernels
// ---------------------------------------------------------------------------
__global__ void f2bf_kernel(const float* __restrict__ in, __nv_bfloat16* __restrict__ out,
                            long n)
{
    const long i = ((long)blockIdx.x * blockDim.x + threadIdx.x) * 4;
    if (i >= n) return;
    const float4 v = *(const float4*)(in + i);
    uint2 u;
    u.x = bfpack(v.x, v.y);
    u.y = bfpack(v.z, v.w);
    *(uint2*)(out + i) = u;
}

// fp32 [R,C] -> bf16 [C,R]
__global__ void transpose_bf_kernel(const float* __restrict__ in,
                                    __nv_bfloat16* __restrict__ out, int R, int C)
{
    __shared__ float t[32][33];
    const int c0 = blockIdx.x * 32, r0 = blockIdx.y * 32;
    const int x = threadIdx.x, y = threadIdx.y;   // 32 x 8
#pragma unroll
    for (int i = y; i < 32; i += 8) {
        const int r = r0 + i, c = c0 + x;
        if (r < R && c < C) t[i][x] = in[(long)r * C + c];
    }
    __syncthreads();
#pragma unroll
    for (int i = y; i < 32; i += 8) {
        const int oc = c0 + i, orr = r0 + x;
        if (oc < C && orr < R) out[(long)oc * R + orr] = __float2bfloat16(t[x][i]);
    }
}

__global__ void mask_kernel(const float* __restrict__ inp, float* __restrict__ mask)
{
    const int row  = blockIdx.x * 8 + (threadIdx.x >> 5);
    const int lane = threadIdx.x & 31;
    const float* p = inp + (long)row * 1024;
    float s = 0.f;
    for (int k = lane; k < 1024; k += 32) s += p[k];
#pragma unroll
    for (int o = 16; o > 0; o >>= 1) s += __shfl_xor_sync(0xffffffffu, s, o);
    if (lane == 0) mask[row] = (s != 0.f) ? 1.f : 0.f;
}

__global__ void numel_kernel(const float* __restrict__ mask, float* __restrict__ numel)
{
    const int b = blockIdx.x, tid = threadIdx.x;
    __shared__ float sh[1024];
    sh[tid] = mask[b * 1024 + tid];
    __syncthreads();
    for (int s = 512; s > 0; s >>= 1) {
        if (tid < s) sh[tid] += sh[tid + s];
        __syncthreads();
    }
    if (tid == 0) numel[b] = sh[0];
}

__global__ void mean_kernel(const float* __restrict__ fea, const float* __restrict__ numel,
                            float* __restrict__ mean)
{
    const int b = blockIdx.y;
    const int f = blockIdx.x * blockDim.x + threadIdx.x;
    const float* p = fea + (long)b * 1024 * 512 + f;
    float s = 0.f;
    for (int n = 0; n < 1024; n++) s += p[(long)n * 512];
    mean[b * 512 + f] = s / numel[b];
}

__global__ void cvec_kernel(const float* __restrict__ mean, const float* __restrict__ Wc,
                            const float* __restrict__ bc, float* __restrict__ c)
{
    const int b = blockIdx.x, j = threadIdx.x;
    float s = bc[j];
    for (int k = 0; k < 512; k++) s += mean[b * 512 + k] * Wc[k * 128 + j];
    c[b * 128 + j] = fmaxf(s, 0.f);
}

__global__ void concat_bf_kernel(const __nv_bfloat16* __restrict__ feab,
                                 const float* __restrict__ cvec,
                                 __nv_bfloat16* __restrict__ q)
{
    const long idx = (long)blockIdx.x * blockDim.x + threadIdx.x;
    if (idx >= 8192L * 640) return;
    const int f = (int)(idx % 640);
    const long row = idx / 640;
    const int b = (int)(row >> 10);
    q[idx] = (f < 512) ? feab[row * 512 + f] : __float2bfloat16(cvec[b * 128 + (f - 512)]);
}

__global__ void deg_kernel(const float* __restrict__ A, float* __restrict__ dinv)
{
    const int row  = blockIdx.x * 8 + (threadIdx.x >> 5);
    const int lane = threadIdx.x & 31;
    const float* p = A + (long)row * 1024;
    float s = 0.f;
    for (int j = lane; j < 1024; j += 32) s += p[j];
#pragma unroll
    for (int o = 16; o > 0; o >>= 1) s += __shfl_xor_sync(0xffffffffu, s, o);
    if (lane == 0) dinv[row] = (s > 0.f) ? rsqrtf(fmaxf(s, 1e-30f)) : 0.f;
}

__global__ void lhat_bf_kernel(const float* __restrict__ adj, const float* __restrict__ dinv,
                               __nv_bfloat16* __restrict__ lb)
{
    const long idx = (long)blockIdx.x * blockDim.x + threadIdx.x;
    if (idx >= 8L * 1024 * 1024) return;
    const long row = idx >> 10;
    const int  j   = (int)(idx & 1023);
    const int  b   = (int)(row >> 10);
    lb[idx] = __float2bfloat16(-adj[idx] * dinv[row] * dinv[(long)b * 1024 + j]);
}

__global__ void pool_kernel(const float* __restrict__ gate, const float* __restrict__ mask,
                            const float* __restrict__ x, float* __restrict__ pooled)
{
    const int b = blockIdx.x, tid = threadIdx.x;
    __shared__ float sh[1024];
    const float g = (mask[b * 1024 + tid] > 0.f) ? gate[b * 1024 + tid] : -1e9f;
    sh[tid] = g;
    __syncthreads();
    for (int s = 512; s > 0; s >>= 1) {
        if (tid < s) sh[tid] = fmaxf(sh[tid], sh[tid + s]);
        __syncthreads();
    }
    const float maxv = sh[0];
    __syncthreads();
    const float e = expf(g - maxv);
    sh[tid] = e;
    __syncthreads();
    for (int s = 512; s > 0; s >>= 1) {
        if (tid < s) sh[tid] += sh[tid + s];
        __syncthreads();
    }
    const float sum = sh[0];
    __syncthreads();
    sh[tid] = e / sum;
    __syncthreads();
    if (tid < 384) {
        float s = 0.f;
        const float* xb = x + (long)b * 1024 * 384 + tid;
        for (int n = 0; n < 1024; n++) s += sh[n] * xb[(long)n * 384];
        pooled[b * 384 + tid] = s;
    }
}

__global__ void final_kernel(const float* __restrict__ pooled, const float* __restrict__ Wm1,
                             const float* __restrict__ bm1, const float* __restrict__ Wm2,
                             const float* __restrict__ bm2, float* __restrict__ out)
{
    const int b = blockIdx.x, tid = threadIdx.x;
    __shared__ float sh[256];
    float s = bm1[tid];
    const float* p = pooled + b * 384;
    for (int k = 0; k < 384; k++) s += p[k] * Wm1[k * 256 + tid];
    sh[tid] = fmaxf(s, 0.f) * Wm2[tid];
    __syncthreads();
    for (int r = 128; r > 0; r >>= 1) {
        if (tid < r) sh[tid] += sh[tid + r];
        __syncthreads();
    }
    if (tid == 0) out[b] = 1.f / (1.f + expf(-(sh[0] + bm2[0])));
}

// ---------------------------------------------------------------------------
// Host launchers
// ---------------------------------------------------------------------------
static void tg(const __nv_bfloat16* A, long sA, const __nv_bfloat16* B, long sB,
               const float* bias, const float* Cin, long sCin, float cc,
               const float* rM, const float* cM,
               float* C, long sC, __nv_bfloat16* Cb, unsigned short* CbT, long sCt,
               int M, int N, int K, float alpha, int act, int batch)
{
    dim3 grid(CDIV(N, 128), M / 128, batch);
    mma_gemm_bf<<<grid, 256>>>(A, sA, B, sB, bias, Cin, sCin, cc, rM, cM,
                               C, sC, Cb, CbT, sCt, M, N, K, alpha, act);
}

static void transposeBf(const float* in, __nv_bfloat16* out, int R, int C)
{
    dim3 grid(CDIV(C, 32), CDIV(R, 32));
    transpose_bf_kernel<<<grid, dim3(32, 8)>>>(in, out, R, C);
}

// ---------------------------------------------------------------------------
// Entry point
// ---------------------------------------------------------------------------
extern "C" void kernel_launch(void* const* d_in, const int* in_sizes, int n_in,
                              void* d_out, int out_size)
{
    const float* inp = (const float*)d_in[0];
    const float* Wf1 = (const float*)d_in[2];  const float* bf1 = (const float*)d_in[3];
    const float* Wf2 = (const float*)d_in[4];  const float* bf2 = (const float*)d_in[5];
    const float* Wf3 = (const float*)d_in[6];  const float* bf3 = (const float*)d_in[7];
    const float* Wc  = (const float*)d_in[8];  const float* bc  = (const float*)d_in[9];
    const float* Wa1 = (const float*)d_in[10]; const float* ba1 = (const float*)d_in[11];
    const float* Wa2 = (const float*)d_in[12]; const float* ba2 = (const float*)d_in[13];
    const float* Wg1 = (const float*)d_in[14]; const float* bg1 = (const float*)d_in[15];
    const float* Wg2 = (const float*)d_in[16]; const float* bg2 = (const float*)d_in[17];
    const float* Wp1 = (const float*)d_in[18]; const float* bp1 = (const float*)d_in[19];
    const float* Wp2 = (const float*)d_in[20]; const float* bp2 = (const float*)d_in[21];
    const float* Wp3 = (const float*)d_in[22]; const float* bp3 = (const float*)d_in[23];
    const float* Wm1 = (const float*)d_in[24]; const float* bm1 = (const float*)d_in[25];
    const float* Wm2 = (const float*)d_in[26]; const float* bm2 = (const float*)d_in[27];
    float* out = (float*)d_out;

    float* base = nullptr;
    cudaGetSymbolAddress((void**)&base, g_scratch);

    float* mask  = base + S_MASK;
    float* numel = base + S_NUMEL;
    float* meanf = base + S_MEAN;
    float* cvec  = base + S_CVEC;
    float* pool  = base + S_POOL;
    float* dinv  = base + S_DINV;
    float* gate  = base + S_GATE;
    float* g2    = base + S_G2;
    float* g1    = base + S_G1;
    float* fea   = base + S_FEA;
    float* adj   = base + S_ADJ;
    float* x1    = base + S_X1;
    float* x2    = base + S_X2;
    float* Taf   = base + S_TAF;
    float* Tbf   = base + S_TBF;
    float* Tcf   = base + S_TCF;

    __nv_bfloat16* inpb  = (__nv_bfloat16*)(base + S_INPB);
    __nv_bfloat16* h1b   = (__nv_bfloat16*)(base + S_H1B);
    __nv_bfloat16* h2b   = (__nv_bfloat16*)(base + S_H2B);
    __nv_bfloat16* feab  = (__nv_bfloat16*)(base + S_FEAB);
    __nv_bfloat16* feabT = (__nv_bfloat16*)(base + S_FEABT);
    __nv_bfloat16* qb    = (__nv_bfloat16*)(base + S_QB);
    __nv_bfloat16* a1b   = (__nv_bfloat16*)(base + S_A1B);
    __nv_bfloat16* afb   = (__nv_bfloat16*)(base + S_AFB);
    __nv_bfloat16* lhatb = (__nv_bfloat16*)(base + S_LHATB);
    __nv_bfloat16* Tab   = (__nv_bfloat16*)(base + S_TAB);
    __nv_bfloat16* TabT  = (__nv_bfloat16*)(base + S_TABT);
    __nv_bfloat16* Tbb   = (__nv_bfloat16*)(base + S_TBB);
    __nv_bfloat16* TbbT  = (__nv_bfloat16*)(base + S_TBBT);
    __nv_bfloat16* Tcb   = (__nv_bfloat16*)(base + S_TCB);
    __nv_bfloat16* TcbT  = (__nv_bfloat16*)(base + S_TCBT);
    __nv_bfloat16* x1b   = (__nv_bfloat16*)(base + S_X1B);
    __nv_bfloat16* x1bT  = (__nv_bfloat16*)(base + S_X1BT);
    __nv_bfloat16* x2b   = (__nv_bfloat16*)(base + S_X2B);
    __nv_bfloat16* wf1b  = (__nv_bfloat16*)(base + S_WF1B);
    __nv_bfloat16* wf2b  = (__nv_bfloat16*)(base + S_WF2B);
    __nv_bfloat16* wf3b  = (__nv_bfloat16*)(base + S_WF3B);
    __nv_bfloat16* wa1b  = (__nv_bfloat16*)(base + S_WA1B);
    __nv_bfloat16* wa2b  = (__nv_bfloat16*)(base + S_WA2B);
    __nv_bfloat16* wg1b  = (__nv_bfloat16*)(base + S_WG1B);
    __nv_bfloat16* wg2b  = (__nv_bfloat16*)(base + S_WG2B);
    __nv_bfloat16* wp1b  = (__nv_bfloat16*)(base + S_WP1B);

    // 0) convert inputs/weights to bf16 ([N,K] for weights)
    f2bf_kernel<<<(int)CDIV(8192L * 1024 / 4, 256), 256>>>(inp, inpb, 8192L * 1024);
    transposeBf(Wf1, wf1b, 1024, 784);
    transposeBf(Wf2, wf2b, 784, 512);
    transposeBf(Wf3, wf3b, 512, 512);
    transposeBf(Wa1, wa1b, 640, 512);
    transposeBf(Wa2, wa2b, 512, 384);
    for (int k = 0; k < 5; k++) transposeBf(Wg1 + (long)k * 512 * 512, wg1b + (long)k * 512 * 512, 512, 512);
    for (int k = 0; k < 5; k++) transposeBf(Wg2 + (long)k * 512 * 384, wg2b + (long)k * 384 * 512, 512, 384);
    transposeBf(Wp1, wp1b, 384, 128);

    // 1) node mask + numel
    mask_kernel<<<1024, 256>>>(inp, mask);
    numel_kernel<<<8, 1024>>>(mask, numel);

    // 2) feature extractor
    tg(inpb, 0, wf1b, 0, bf1, nullptr, 0, 0.f, mask, nullptr,
       nullptr, 0, h1b, nullptr, 0, MROWS, 784, 1024, 1.f, 1, 1);
    tg(h1b, 0, wf2b, 0, bf2, nullptr, 0, 0.f, mask, nullptr,
       nullptr, 0, h2b, nullptr, 0, MROWS, 512, 784, 1.f, 1, 1);
    tg(h2b, 0, wf3b, 0, bf3, nullptr, 0, 0.f, mask, nullptr,
       fea, 0, feab, (unsigned short*)feabT, 0, MROWS, 512, 512, 1.f, 1, 1);

    // 3) c vector
    mean_kernel<<<dim3(4, 8), 128>>>(fea, numel, meanf);
    cvec_kernel<<<8, 128>>>(meanf, Wc, bc, cvec);

    // 4) adjacency net
    concat_bf_kernel<<<(int)CDIV(8192L * 640, 256), 256>>>(feab, cvec, qb);
    tg(qb, 0, wa1b, 0, ba1, nullptr, 0, 0.f, mask, nullptr,
       nullptr, 0, a1b, nullptr, 0, MROWS, 512, 640, 1.f, 1, 1);
    tg(a1b, 0, wa2b, 0, ba2, nullptr, 0, 0.f, mask, nullptr,
       nullptr, 0, afb, nullptr, 0, MROWS, 384, 512, 1.f, 1, 1);

    // 5) A = (a a^T) * pairMask -> Lhat (bf16)
    tg(afb, 1024L * 384, afb, 1024L * 384, nullptr, nullptr, 0, 0.f,
       mask, mask, adj, 1024L * 1024, nullptr, nullptr, 0, 1024, 1024, 384, 1.f, 0, 8);
    deg_kernel<<<1024, 256>>>(adj, dinv);
    lhat_bf_kernel<<<(int)CDIV(8L * 1024 * 1024, 256), 256>>>(adj, dinv, lhatb);

    const long sT = 1024L * 512, sL = 1024L * 1024;

    // 6) ChebConv 1: K=5, 512 -> 512
    {
        const long wk = 512L * 512;
        tg(feab, 0, wg1b, 0, nullptr, nullptr, 0, 0.f, nullptr, nullptr,
           x1, 0, nullptr, nullptr, 0, MROWS, 512, 512, 1.f, 0, 1);
        tg(lhatb, sL, feabT, sT, nullptr, nullptr, 0, 0.f, nullptr, nullptr,
           Tbf, sT, Tbb, (unsigned short*)TbbT, sT, 1024, 512, 1024, 1.f, 0, 8);
        tg(Tbb, 0, wg1b + wk, 0, nullptr, x1, 0, 1.f, nullptr, nullptr,
           x1, 0, nullptr, nullptr, 0, MROWS, 512, 512, 1.f, 0, 1);
        tg(lhatb, sL, TbbT, sT, nullptr, fea, sT, -1.f, nullptr, nullptr,
           Tcf, sT, Tcb, (unsigned short*)TcbT, sT, 1024, 512, 1024, 2.f, 0, 8);
        tg(Tcb, 0, wg1b + 2 * wk, 0, nullptr, x1, 0, 1.f, nullptr, nullptr,
           x1, 0, nullptr, nullptr, 0, MROWS, 512, 512, 1.f, 0, 1);
        tg(lhatb, sL, TcbT, sT, nullptr, Tbf, sT, -1.f, nullptr, nullptr,
           Taf, sT, Tab, (unsigned short*)TabT, sT, 1024, 512, 1024, 2.f, 0, 8);
        tg(Tab, 0, wg1b + 3 * wk, 0, nullptr, x1, 0, 1.f, nullptr, nullptr,
           x1, 0, nullptr, nullptr, 0, MROWS, 512, 512, 1.f, 0, 1);
        tg(lhatb, sL, TabT, sT, nullptr, Tcf, sT, -1.f, nullptr, nullptr,
           Tbf, sT, Tbb, nullptr, 0, 1024, 512, 1024, 2.f, 0, 8);
        tg(Tbb, 0, wg1b + 4 * wk, 0, bg1, x1, 0, 1.f, nullptr, nullptr,
           x1, 0, x1b, (unsigned short*)x1bT, 0, MROWS, 512, 512, 1.f, 1, 1);
    }

    // 7) ChebConv 2: K=5, 512 -> 384
    {
        const long wk = 384L * 512;
        tg(x1b, 0, wg2b, 0, nullptr, nullptr, 0, 0.f, nullptr, nullptr,
           x2, 0, nullptr, nullptr, 0, MROWS, 384, 512, 1.f, 0, 1);
        tg(lhatb, sL, x1bT, sT, nullptr, nullptr, 0, 0.f, nullptr, nullptr,
           Tbf, sT, Tbb, (unsigned short*)TbbT, sT, 1024, 512, 1024, 1.f, 0, 8);
        tg(Tbb, 0, wg2b + wk, 0, nullptr, x2, 0, 1.f, nullptr, nullptr,
           x2, 0, nullptr, nullptr, 0, MROWS, 384, 512, 1.f, 0, 1);
        tg(lhatb, sL, TbbT, sT, nullptr, x1, sT, -1.f, nullptr, nullptr,
           Tcf, sT, Tcb, (unsigned short*)TcbT, sT, 1024, 512, 1024, 2.f, 0, 8);
        tg(Tcb, 0, wg2b + 2 * wk, 0, nullptr, x2, 0, 1.f, nullptr, nullptr,
           x2, 0, nullptr, nullptr, 0, MROWS, 384, 512, 1.f, 0, 1);
        tg(lhatb, sL, TcbT, sT, nullptr, Tbf, sT, -1.f, nullptr, nullptr,
           Taf, sT, Tab, (unsigned short*)TabT, sT, 1024, 512, 1024, 2.f, 0, 8);
        tg(Tab, 0, wg2b + 3 * wk, 0, nullptr, x2, 0, 1.f, nullptr, nullptr,
           x2, 0, nullptr, nullptr, 0, MROWS, 384, 512, 1.f, 0, 1);
        tg(lhatb, sL, TabT, sT, nullptr, Tcf, sT, -1.f, nullptr, nullptr,
           Tbf, sT, Tbb, nullptr, 0, 1024, 512, 1024, 2.f, 0, 8);
        tg(Tbb, 0, wg2b + 4 * wk, 0, bg2, x2, 0, 1.f, nullptr, nullptr,
           x2, 0, x2b, nullptr, 0, MROWS, 384, 512, 1.f, 1, 1);
    }

    // 8) attention gate
    tg(x2b, 0, wp1b, 0, bp1, nullptr, 0, 0.f, nullptr, nullptr,
       g1, 0, nullptr, nullptr, 0, MROWS, 128, 384, 1.f, 1, 1);
    gemm_kernel<<<dim3(1, 128), 256>>>(g1, Wp2, bp2, g2, MROWS, 64, 128, 1);
    gemm_kernel<<<dim3(1, 128), 256>>>(g2, Wp3, bp3, gate, MROWS, 1, 64, 2);

    // 9) softmax pooling + output MLP
    pool_kernel<<<8, 1024>>>(gate, mask, x2, pool);
    final_kernel<<<8, 256>>>(pool, Wm1, bm1, Wm2, bm2, out);

    (void)in_sizes; (void)n_in; (void)out_size;
}

// round 7
// speedup vs baseline: 5.3754x; 1.0028x over previous
#include <cuda_runtime.h>
#include <cuda_bf16.h>
#include <math.h>
#include <stdint.h>

#define Bq 8
#define Nn 1024
#define MROWS (Bq * Nn)   // 8192

// ---------------------------------------------------------------------------
// Scratch layout (float units; bf16 buffers use count/2 float slots)
// ---------------------------------------------------------------------------
#define S_MASK   0L
#define S_NUMEL  (S_MASK  + 8192L)
#define S_MEAN   (S_NUMEL + 8L)
#define S_CVEC   (S_MEAN  + 4096L)
#define S_POOL   (S_CVEC  + 1024L)
#define S_DINV   (S_POOL  + 3072L)
#define S_GATE   (S_DINV  + 8192L)
#define S_G2     (S_GATE  + 8192L)
#define S_G1     (S_G2    + 8192L*64)
#define S_FEA    (S_G1    + 8192L*128)
#define S_ADJ    (S_FEA   + 8192L*512)
#define S_X1     (S_ADJ   + 8388608L)
#define S_X2     (S_X1    + 8192L*512)
#define S_TAF    (S_X2    + 8192L*384)
#define S_TBF    (S_TAF   + 8192L*512)
#define S_TCF    (S_TBF   + 8192L*512)
// bf16 region
#define S_INPB   (S_TCF   + 8192L*512)
#define S_H1B    (S_INPB  + 4194304L)
#define S_H2B    (S_H1B   + 3211264L)
#define S_FEAB   (S_H2B   + 2097152L)
#define S_FEABT  (S_FEAB  + 2097152L)
#define S_QB     (S_FEABT + 2097152L)
#define S_A1B    (S_QB    + 2621440L)
#define S_AFB    (S_A1B   + 2097152L)
#define S_LHATB  (S_AFB   + 1572864L)
#define S_TAB    (S_LHATB + 4194304L)
#define S_TABT   (S_TAB   + 2097152L)
#define S_TBB    (S_TABT  + 2097152L)
#define S_TBBT   (S_TBB   + 2097152L)
#define S_TCB    (S_TBBT  + 2097152L)
#define S_TCBT   (S_TCB   + 2097152L)
#define S_X1B    (S_TCBT  + 2097152L)
#define S_X1BT   (S_X1B   + 2097152L)
#define S_X2B    (S_X1BT  + 2097152L)
#define S_WF1B   (S_X2B   + 1572864L)
#define S_WF2B   (S_WF1B  + 401408L)
#define S_WF3B   (S_WF2B  + 200704L)
#define S_WA1B   (S_WF3B  + 131072L)
#define S_WA2B   (S_WA1B  + 163840L)
#define S_WG1B   (S_WA2B  + 98304L)
#define S_WG2B   (S_WG1B  + 655360L)
#define S_WP1B   (S_WG2B  + 491520L)
#define S_TOTAL  (S_WP1B  + 24576L)

__device__ float g_scratch[S_TOTAL];

#define CDIV(a,b) (((a)+(b)-1)/(b))

// ---------------------------------------------------------------------------
// Portable PTX helpers (sm_80+; no arch-'a' features)
// ---------------------------------------------------------------------------
__device__ __forceinline__ uint32_t bfpack(float lo, float hi) {
    uint32_t r;
    asm("cvt.rn.bf16x2.f32 %0, %1, %2;" : "=r"(r) : "f"(hi), "f"(lo));
    return r;
}
__device__ __forceinline__ uint32_t sm_u32(const void* p) {
    uint32_t a;
    asm("{ .reg .u64 t; cvta.to.shared.u64 t, %1; cvt.u32.u64 %0, t; }"
        : "=r"(a) : "l"(p));
    return a;
}
__device__ __forceinline__ void ldmx4(uint32_t& r0, uint32_t& r1, uint32_t& r2,
                                      uint32_t& r3, uint32_t addr) {
    asm volatile("ldmatrix.sync.aligned.m8n8.x4.shared.b16 {%0,%1,%2,%3}, [%4];"
                 : "=r"(r0), "=r"(r1), "=r"(r2), "=r"(r3) : "r"(addr));
}
__device__ __forceinline__ void mma16(float* c, const uint32_t* a, const uint32_t* b) {
    asm volatile(
        "mma.sync.aligned.m16n8k16.row.col.f32.bf16.bf16.f32 "
        "{%0,%1,%2,%3}, {%4,%5,%6,%7}, {%8,%9}, {%0,%1,%2,%3};"
        : "+f"(c[0]), "+f"(c[1]), "+f"(c[2]), "+f"(c[3])
        : "r"(a[0]), "r"(a[1]), "r"(a[2]), "r"(a[3]), "r"(b[0]), "r"(b[1]));
}
__device__ __forceinline__ void cpa16(uint32_t dst, const void* src, int srcBytes) {
    asm volatile("cp.async.cg.shared.global [%0], [%1], 16, %2;\n"
                 :: "r"(dst), "l"(src), "r"(srcBytes));
}
#define CP_COMMIT() asm volatile("cp.async.commit_group;\n" ::: "memory")
#define CP_WAIT1()  asm volatile("cp.async.wait_group 1;\n" ::: "memory")
#define CP_WAIT0()  asm volatile("cp.async.wait_group 0;\n" ::: "memory")

// ---------------------------------------------------------------------------
// Wide bf16 GEMM: 128x256 tile, 512 threads, 3-stage cp.async pipeline.
//   D[m,n] = sum_k A[m,k]*B[n,k]; A bf16 [M,K], B bf16 [N,K]
//   v = act(alpha*D + bias + cinCoef*Cin) * rowMask * colMask
//   outputs (optional): C fp32; Cb bf16; CbT bf16 transposed [.., N, 1024]
//   requires M % 128 == 0, N % 16 == 0, K % 8 == 0
// ---------------------------------------------------------------------------
#define STG_BYTES 24576   // A 8KB + B 16KB per stage
__global__ void __launch_bounds__(512, 1)
mma_gemm_w(const __nv_bfloat16* __restrict__ A, long sA,
           const __nv_bfloat16* __restrict__ B, long sB,
           const float* __restrict__ bias,
           const float* __restrict__ Cin, long sCin, float cinCoef,
           const float* __restrict__ rowMask, const float* __restrict__ colMask,
           float* __restrict__ C, long sC,
           __nv_bfloat16* __restrict__ Cb,
           unsigned short* __restrict__ CbT, long sCt,
           int M, int N, int K, float alpha, int act)
{
    extern __shared__ char smem[];
    const uint32_t sbase = sm_u32(smem);

    const int tid = threadIdx.x, lane = tid & 31, wid = tid >> 5;
    const int wm = wid >> 2, wn = wid & 3;     // 4 x 4 warps; warp tile 32 x 64
    const int bz = blockIdx.z;
    A += (long)bz * sA;
    B += (long)bz * sB;
    if (C)   C   += (long)bz * sC;
    if (Cb)  Cb  += (long)bz * sC;
    if (CbT) CbT += (long)bz * sCt;
    if (Cin) Cin += (long)bz * sCin;
    const int rowBase = blockIdx.y * 128;
    const int colBase = blockIdx.x * 256;

    // A load: 512 chunks of 16B -> 1/thread. row = tid>>2, chunk j = tid&3
    const int alr = tid >> 2, alj = tid & 3;
    const int aswz = (alr >> 1) & 3;
    const __nv_bfloat16* arow = A + (long)(rowBase + alr) * K;
    // B load: 1024 chunks -> 2/thread. row = tid>>1, chunks c0, c0+1
    const int blr = tid >> 1, bc0 = (tid & 1) * 2;
    const int bswz = (blr >> 1) & 3;
    const int gnb = colBase + blr;
    const bool nok = gnb < N;
    const __nv_bfloat16* brow = B + (long)(nok ? gnb : 0) * K;

    float acc[2][8][4];
#pragma unroll
    for (int i = 0; i < 2; i++)
#pragma unroll
        for (int j = 0; j < 8; j++)
#pragma unroll
            for (int t = 0; t < 4; t++) acc[i][j][t] = 0.f;

    const int nc = (K + 31) / 32;

    auto issue = [&](int cc) {
        const int st = cc % 3;
        const uint32_t ab = sbase + st * STG_BYTES;
        {
            const int k = cc * 32 + alj * 8;
            cpa16(ab + alr * 64 + ((alj ^ aswz) << 4),
                  arow + (k < K ? k : 0), (k < K) ? 16 : 0);
        }
#pragma unroll
        for (int j2 = 0; j2 < 2; j2++) {
            const int j = bc0 + j2;
            const int k = cc * 32 + j * 8;
            cpa16(ab + 8192 + blr * 64 + ((j ^ bswz) << 4),
                  brow + (k < K ? k : 0), (nok && k < K) ? 16 : 0);
        }
        CP_COMMIT();
    };

    issue(0);
    if (nc > 1) issue(1);

    // ldmatrix lane geometry
    const int lj = lane >> 3, lr8 = lane & 7;
    const int amrow = (lj & 1) * 8 + lr8, akc = lj >> 1;
    const int bnrow = (lj >> 1) * 8 + lr8, bkc = lj & 1;

    for (int c = 0; c < nc; c++) {
        if (c + 1 < nc) { CP_WAIT1(); } else { CP_WAIT0(); }
        __syncthreads();
        if (c + 2 < nc) issue(c + 2);

        const uint32_t abase = sbase + (c % 3) * STG_BYTES;
        const uint32_t bbase = abase + 8192;
#pragma unroll
        for (int ks = 0; ks < 2; ks++) {
            uint32_t af[2][4];
#pragma unroll
            for (int i = 0; i < 2; i++) {
                const int row = wm * 32 + i * 16 + amrow;
                const int logc = ks * 2 + akc;
                ldmx4(af[i][0], af[i][1], af[i][2], af[i][3],
                      abase + row * 64 + ((logc ^ ((row >> 1) & 3)) << 4));
            }
            uint32_t bf[8][2];
#pragma unroll
            for (int jj = 0; jj < 8; jj += 2) {
                const int n = wn * 64 + jj * 8 + bnrow;
                const int logc = ks * 2 + bkc;
                ldmx4(bf[jj][0], bf[jj][1], bf[jj + 1][0], bf[jj + 1][1],
                      bbase + n * 64 + ((logc ^ ((n >> 1) & 3)) << 4));
            }
#pragma unroll
            for (int i = 0; i < 2; i++)
#pragma unroll
                for (int j = 0; j < 8; j++)
                    mma16(acc[i][j], af[i], bf[j]);
        }
    }

    // ---- epilogue ----
#pragma unroll
    for (int i = 0; i < 2; i++) {
        const int gr0 = rowBase + wm * 32 + i * 16 + (lane >> 2);
#pragma unroll
        for (int half = 0; half < 2; half++) {
            const int gr = gr0 + half * 8;
            const float rm = rowMask ? rowMask[(long)bz * M + gr] : 1.f;
            const long tb = CbT ? (((long)(gr >> 10)) * ((long)N * 1024) + (gr & 1023)) : 0;
#pragma unroll
            for (int j = 0; j < 8; j++) {
                const int gcb = colBase + wn * 64 + j * 8;
                if (gcb >= N) continue;
                const int gc = gcb + 2 * (lane & 3);
                float v0 = alpha * acc[i][j][half * 2 + 0];
                float v1 = alpha * acc[i][j][half * 2 + 1];
                if (bias) { v0 += bias[gc]; v1 += bias[gc + 1]; }
                if (Cin) {
                    v0 += cinCoef * Cin[(long)gr * N + gc];
                    v1 += cinCoef * Cin[(long)gr * N + gc + 1];
                }
                v0 *= rm; v1 *= rm;
                if (colMask) {
                    v0 *= colMask[(long)bz * N + gc];
                    v1 *= colMask[(long)bz * N + gc + 1];
                }
                if (act == 1) { v0 = fmaxf(v0, 0.f); v1 = fmaxf(v1, 0.f); }
                else if (act == 2) { v0 = tanhf(v0); v1 = tanhf(v1); }
                if (C) *(float2*)(C + (long)gr * N + gc) = make_float2(v0, v1);
                const uint32_t u = bfpack(v0, v1);
                if (Cb) *(uint32_t*)((char*)Cb + ((long)gr * N + gc) * 2) = u;
                if (CbT) {
                    CbT[tb + (long)gc * 1024] = (unsigned short)u;
                    CbT[tb + (long)(gc + 1) * 1024] = (unsigned short)(u >> 16);
                }
            }
        }
    }
}

// ---------------------------------------------------------------------------
// Narrow bf16 GEMM (N <= 128): 128x128 tile, 256 threads (round-6 kernel)
// ---------------------------------------------------------------------------
__global__ void __launch_bounds__(256)
mma_gemm_bf(const __nv_bfloat16* __restrict__ A, long sA,
            const __nv_bfloat16* __restrict__ B, long sB,
            const float* __restrict__ bias,
            const float* __restrict__ Cin, long sCin, float cinCoef,
            const float* __restrict__ rowMask, const float* __restrict__ colMask,
            float* __restrict__ C, long sC,
            __nv_bfloat16* __restrict__ Cb,
            unsigned short* __restrict__ CbT, long sCt,
            int M, int N, int K, float alpha, int act)
{
    __shared__ __align__(16) char smem[49152];
    const uint32_t sbase = sm_u32(smem);

    const int tid = threadIdx.x, lane = tid & 31, wid = tid >> 5;
    const int wm = wid >> 2, wn = wid & 3;
    const int bz = blockIdx.z;
    A += (long)bz * sA;
    B += (long)bz * sB;
    if (C)   C   += (long)bz * sC;
    if (Cb)  Cb  += (long)bz * sC;
    if (CbT) CbT += (long)bz * sCt;
    if (Cin) Cin += (long)bz * sCin;
    const int rowBase = blockIdx.y * 128;
    const int colBase = blockIdx.x * 128;

    const int lr  = tid >> 1;
    const int c0  = (tid & 1) * 2;
    const int swz = (lr >> 1) & 3;
    const int gn  = colBase + lr;
    const bool nok = gn < N;
    const __nv_bfloat16* arow = A + (long)(rowBase + lr) * K;
    const __nv_bfloat16* brow = B + (long)(nok ? gn : 0) * K;

    float acc[4][4][4];
#pragma unroll
    for (int i = 0; i < 4; i++)
#pragma unroll
        for (int j = 0; j < 4; j++)
#pragma unroll
            for (int t = 0; t < 4; t++) acc[i][j][t] = 0.f;

    const int nc = (K + 31) / 32;

    auto issue = [&](int cc) {
        const int st = cc % 3;
        const uint32_t ab = sbase + st * 16384 + lr * 64;
#pragma unroll
        for (int j2 = 0; j2 < 2; j2++) {
            const int j = c0 + j2;
            const int k = cc * 32 + j * 8;
            cpa16(ab + ((j ^ swz) << 4), arow + (k < K ? k : 0), (k < K) ? 16 : 0);
        }
#pragma unroll
        for (int j2 = 0; j2 < 2; j2++) {
            const int j = c0 + j2;
            const int k = cc * 32 + j * 8;
            cpa16(ab + 8192 + ((j ^ swz) << 4), brow + (k < K ? k : 0),
                  (nok && k < K) ? 16 : 0);
        }
        CP_COMMIT();
    };

    issue(0);
    if (nc > 1) issue(1);

    const int lj = lane >> 3, lr8 = lane & 7;
    const int amrow = (lj & 1) * 8 + lr8, akc = lj >> 1;
    const int bnrow = (lj >> 1) * 8 + lr8, bkc = lj & 1;

    for (int c = 0; c < nc; c++) {
        if (c + 1 < nc) { CP_WAIT1(); } else { CP_WAIT0(); }
        __syncthreads();
        if (c + 2 < nc) issue(c + 2);

        const uint32_t abase = sbase + (c % 3) * 16384;
        const uint32_t bbase = abase + 8192;
#pragma unroll
        for (int ks = 0; ks < 2; ks++) {
            uint32_t af[4][4];
#pragma unroll
            for (int i = 0; i < 4; i++) {
                const int row = wm * 64 + i * 16 + amrow;
                const int logc = ks * 2 + akc;
                ldmx4(af[i][0], af[i][1], af[i][2], af[i][3],
                      abase + row * 64 + ((logc ^ ((row >> 1) & 3)) << 4));
            }
            uint32_t bf[4][2];
#pragma unroll
            for (int jj = 0; jj < 4; jj += 2) {
                const int n = wn * 32 + jj * 8 + bnrow;
                const int logc = ks * 2 + bkc;
                ldmx4(bf[jj][0], bf[jj][1], bf[jj + 1][0], bf[jj + 1][1],
                      bbase + n * 64 + ((logc ^ ((n >> 1) & 3)) << 4));
            }
#pragma unroll
            for (int i = 0; i < 4; i++)
#pragma unroll
                for (int j = 0; j < 4; j++)
                    mma16(acc[i][j], af[i], bf[j]);
        }
    }

#pragma unroll
    for (int i = 0; i < 4; i++) {
        const int gr0 = rowBase + wm * 64 + i * 16 + (lane >> 2);
#pragma unroll
        for (int half = 0; half < 2; half++) {
            const int gr = gr0 + half * 8;
            const float rm = rowMask ? rowMask[(long)bz * M + gr] : 1.f;
            const long tb = CbT ? (((long)(gr >> 10)) * ((long)N * 1024) + (gr & 1023)) : 0;
#pragma unroll
            for (int j = 0; j < 4; j++) {
                const int gcb = colBase + wn * 32 + j * 8;
                if (gcb >= N) continue;
                const int gc = gcb + 2 * (lane & 3);
                float v0 = alpha * acc[i][j][half * 2 + 0];
                float v1 = alpha * acc[i][j][half * 2 + 1];
                if (bias) { v0 += bias[gc]; v1 += bias[gc + 1]; }
                if (Cin) {
                    v0 += cinCoef * Cin[(long)gr * N + gc];
                    v1 += cinCoef * Cin[(long)gr * N + gc + 1];
                }
                v0 *= rm; v1 *= rm;
                if (colMask) {
                    v0 *= colMask[(long)bz * N + gc];
                    v1 *= colMask[(long)bz * N + gc + 1];
                }
                if (act == 1) { v0 = fmaxf(v0, 0.f); v1 = fmaxf(v1, 0.f); }
                else if (act == 2) { v0 = tanhf(v0); v1 = tanhf(v1); }
                if (C) *(float2*)(C + (long)gr * N + gc) = make_float2(v0, v1);
                const uint32_t u = bfpack(v0, v1);
                if (Cb) *(uint32_t*)((char*)Cb + ((long)gr * N + gc) * 2) = u;
                if (CbT) {
                    CbT[tb + (long)gc * 1024] = (unsigned short)u;
                    CbT[tb + (long)(gc + 1) * 1024] = (unsigned short)(u >> 16);
                }
            }
        }
    }
}

// ---------------------------------------------------------------------------
// Small GEMM (N < 128): fp32 SIMT, B stored [K,N]
// ---------------------------------------------------------------------------
__global__ void gemm_kernel(const float* __restrict__ A,
                            const float* __restrict__ B,
                            const float* __restrict__ bias,
                            float* __restrict__ C,
                            int M, int N, int K, int act)
{
    __shared__ float As[16][64];
    __shared__ float Bs[16][64];

    const int rowBase = blockIdx.y * 64;
    const int colBase = blockIdx.x * 64;
    const int tid = threadIdx.x;
    const int tx = tid & 15, ty = tid >> 4;

    float acc[4][4];
#pragma unroll
    for (int i = 0; i < 4; i++)
#pragma unroll
        for (int j = 0; j < 4; j++) acc[i][j] = 0.f;

    const int ar  = tid >> 2, ak  = (tid & 3) * 4;
    const int bkr = tid >> 4, bnc = (tid & 15) * 4;

    for (int k0 = 0; k0 < K; k0 += 16) {
        const int gr = rowBase + ar;
#pragma unroll
        for (int i = 0; i < 4; i++) {
            const int gk = k0 + ak + i;
            As[ak + i][ar] = (gr < M && gk < K) ? A[(long)gr * K + gk] : 0.f;
        }
        const int gk = k0 + bkr;
#pragma unroll
        for (int i = 0; i < 4; i++) {
            const int gnn = colBase + bnc + i;
            Bs[bkr][bnc + i] = (gk < K && gnn < N) ? B[(long)gk * N + gnn] : 0.f;
        }
        __syncthreads();
#pragma unroll
        for (int kk = 0; kk < 16; kk++) {
            float a0[4], b0[4];
#pragma unroll
            for (int i = 0; i < 4; i++) a0[i] = As[kk][ty * 4 + i];
#pragma unroll
            for (int j = 0; j < 4; j++) b0[j] = Bs[kk][tx * 4 + j];
#pragma unroll
            for (int i = 0; i < 4; i++)
#pragma unroll
                for (int j = 0; j < 4; j++) acc[i][j] += a0[i] * b0[j];
        }
        __syncthreads();
    }

#pragma unroll
    for (int i = 0; i < 4; i++) {
        const int gr = rowBase + ty * 4 + i;
        if (gr >= M) continue;
#pragma unroll
        for (int j = 0; j < 4; j++) {
            const int gc = colBase + tx * 4 + j;
            if (gc >= N) continue;
            float v = acc[i][j];
            if (bias) v += bias[gc];
            if (act == 1)      v = fmaxf(v, 0.f);
            else if (act == 2) v = tanhf(v);
            C[(long)gr * N + gc] = v;
        }
    }
}

// ---------------------------------------------------------------------------
// Conversion / glue kernels
// ---------------------------------------------------------------------------
__global__ void f2bf_kernel(const float* __restrict__ in, __nv_bfloat16* __restrict__ out,
                            long n)
{
    const long i = ((long)blockIdx.x * blockDim.x + threadIdx.x) * 4;
    if (i >= n) return;
    const float4 v = *(const float4*)(in + i);
    uint2 u;
    u.x = bfpack(v.x, v.y);
    u.y = bfpack(v.z, v.w);
    *(uint2*)(out + i) = u;
}

__global__ void transpose_bf_kernel(const float* __restrict__ in,
                                    __nv_bfloat16* __restrict__ out, int R, int C)
{
    __shared__ float t[32][33];
    const int c0 = blockIdx.x * 32, r0 = blockIdx.y * 32;
    const int x = threadIdx.x, y = threadIdx.y;
#pragma unroll
    for (int i = y; i < 32; i += 8) {
        const int r = r0 + i, c = c0 + x;
        if (r < R && c < C) t[i][x] = in[(long)r * C + c];
    }
    __syncthreads();
#pragma unroll
    for (int i = y; i < 32; i += 8) {
        const int oc = c0 + i, orr = r0 + x;
        if (oc < C && orr < R) out[(long)oc * R + orr] = __float2bfloat16(t[x][i]);
    }
}

__global__ void mask_kernel(const float* __restrict__ inp, float* __restrict__ mask)
{
    const int row  = blockIdx.x * 8 + (threadIdx.x >> 5);
    const int lane = threadIdx.x & 31;
    const float* p = inp + (long)row * 1024;
    float s = 0.f;
    for (int k = lane; k < 1024; k += 32) s += p[k];
#pragma unroll
    for (int o = 16; o > 0; o >>= 1) s += __shfl_xor_sync(0xffffffffu, s, o);
    if (lane == 0) mask[row] = (s != 0.f) ? 1.f : 0.f;
}

__global__ void numel_kernel(const float* __restrict__ mask, float* __restrict__ numel)
{
    const int b = blockIdx.x, tid = threadIdx.x;
    __shared__ float sh[1024];
    sh[tid] = mask[b * 1024 + tid];
    __syncthreads();
    for (int s = 512; s > 0; s >>= 1) {
        if (tid < s) sh[tid] += sh[tid + s];
        __syncthreads();
    }
    if (tid == 0) numel[b] = sh[0];
}

__global__ void mean_kernel(const float* __restrict__ fea, const float* __restrict__ numel,
                            float* __restrict__ mean)
{
    const int b = blockIdx.y;
    const int f = blockIdx.x * blockDim.x + threadIdx.x;
    const float* p = fea + (long)b * 1024 * 512 + f;
    float s = 0.f;
    for (int n = 0; n < 1024; n++) s += p[(long)n * 512];
    mean[b * 512 + f] = s / numel[b];
}

__global__ void cvec_kernel(const float* __restrict__ mean, const float* __restrict__ Wc,
                            const float* __restrict__ bc, float* __restrict__ c)
{
    const int b = blockIdx.x, j = threadIdx.x;
    float s = bc[j];
    for (int k = 0; k < 512; k++) s += mean[b * 512 + k] * Wc[k * 128 + j];
    c[b * 128 + j] = fmaxf(s, 0.f);
}

__global__ void concat_bf_kernel(const __nv_bfloat16* __restrict__ feab,
                                 const float* __restrict__ cvec,
                                 __nv_bfloat16* __restrict__ q)
{
    const long idx = (long)blockIdx.x * blockDim.x + threadIdx.x;
    if (idx >= 8192L * 640) return;
    const int f = (int)(idx % 640);
    const long row = idx / 640;
    const int b = (int)(row >> 10);
    q[idx] = (f < 512) ? feab[row * 512 + f] : __float2bfloat16(cvec[b * 128 + (f - 512)]);
}

__global__ void deg_kernel(const float* __restrict__ A, float* __restrict__ dinv)
{
    const int row  = blockIdx.x * 8 + (threadIdx.x >> 5);
    const int lane = threadIdx.x & 31;
    const float* p = A + (long)row * 1024;
    float s = 0.f;
    for (int j = lane; j < 1024; j += 32) s += p[j];
#pragma unroll
    for (int o = 16; o > 0; o >>= 1) s += __shfl_xor_sync(0xffffffffu, s, o);
    if (lane == 0) dinv[row] = (s > 0.f) ? rsqrtf(fmaxf(s, 1e-30f)) : 0.f;
}

__global__ void lhat_bf_kernel(const float* __restrict__ adj, const float* __restrict__ dinv,
                               __nv_bfloat16* __restrict__ lb)
{
    const long idx = (long)blockIdx.x * blockDim.x + threadIdx.x;
    if (idx >= 8L * 1024 * 1024) return;
    const long row = idx >> 10;
    const int  j   = (int)(idx & 1023);
    const int  b   = (int)(row >> 10);
    lb[idx] = __float2bfloat16(-adj[idx] * dinv[row] * dinv[(long)b * 1024 + j]);
}

__global__ void pool_kernel(const float* __restrict__ gate, const float* __restrict__ mask,
                            const float* __restrict__ x, float* __restrict__ pooled)
{
    const int b = blockIdx.x, tid = threadIdx.x;
    __shared__ float sh[1024];
    const float g = (mask[b * 1024 + tid] > 0.f) ? gate[b * 1024 + tid] : -1e9f;
    sh[tid] = g;
    __syncthreads();
    for (int s = 512; s > 0; s >>= 1) {
        if (tid < s) sh[tid] = fmaxf(sh[tid], sh[tid + s]);
        __syncthreads();
    }
    const float maxv = sh[0];
    __syncthreads();
    const float e = expf(g - maxv);
    sh[tid] = e;
    __syncthreads();
    for (int s = 512; s > 0; s >>= 1) {
        if (tid < s) sh[tid] += sh[tid + s];
        __syncthreads();
    }
    const float sum = sh[0];
    __syncthreads();
    sh[tid] = e / sum;
    __syncthreads();
    if (tid < 384) {
        float s = 0.f;
        const float* xb = x + (long)b * 1024 * 384 + tid;
        for (int n = 0; n < 1024; n++) s += sh[n] * xb[(long)n * 384];
        pooled[b * 384 + tid] = s;
    }
}

__global__ void final_kernel(const float* __restrict__ pooled, const float* __restrict__ Wm1,
                             const float* __restrict__ bm1, const float* __restrict__ Wm2,
                             const float* __restrict__ bm2, float* __restrict__ out)
{
    const int b = blockIdx.x, tid = threadIdx.x;
    __shared__ float sh[256];
    float s = bm1[tid];
    const float* p = pooled + b * 384;
    for (int k = 0; k < 384; k++) s += p[k] * Wm1[k * 256 + tid];
    sh[tid] = fmaxf(s, 0.f) * Wm2[tid];
    __syncthreads();
    for (int r = 128; r > 0; r >>= 1) {
        if (tid < r) sh[tid] += sh[tid + r];
        __syncthreads();
    }
    if (tid == 0) out[b] = 1.f / (1.f + expf(-(sh[0] + bm2[0])));
}

// ---------------------------------------------------------------------------
// Host launchers
// ---------------------------------------------------------------------------
static void tg(const __nv_bfloat16* A, long sA, const __nv_bfloat16* B, long sB,
               const float* bias, const float* Cin, long sCin, float cc,
               const float* rM, const float* cM,
               float* C, long sC, __nv_bfloat16* Cb, unsigned short* CbT, long sCt,
               int M, int N, int K, float alpha, int act, int batch)
{
    if (N > 128) {
        static int attrSet = 0;
        if (!attrSet) {
            cudaFuncSetAttribute(mma_gemm_w, cudaFuncAttributeMaxDynamicSharedMemorySize,
                                 3 * STG_BYTES);
            attrSet = 1;
        }
        dim3 grid(CDIV(N, 256), M / 128, batch);
        mma_gemm_w<<<grid, 512, 3 * STG_BYTES>>>(A, sA, B, sB, bias, Cin, sCin, cc,
                                                 rM, cM, C, sC, Cb, CbT, sCt,
                                                 M, N, K, alpha, act);
    } else {
        dim3 grid(CDIV(N, 128), M / 128, batch);
        mma_gemm_bf<<<grid, 256>>>(A, sA, B, sB, bias, Cin, sCin, cc, rM, cM,
                                   C, sC, Cb, CbT, sCt, M, N, K, alpha, act);
    }
}

static void transposeBf(const float* in, __nv_bfloat16* out, int R, int C)
{
    dim3 grid(CDIV(C, 32), CDIV(R, 32));
    transpose_bf_kernel<<<grid, dim3(32, 8)>>>(in, out, R, C);
}

// ---------------------------------------------------------------------------
// Entry point
// ---------------------------------------------------------------------------
extern "C" void kernel_launch(void* const* d_in, const int* in_sizes, int n_in,
                              void* d_out, int out_size)
{
    const float* inp = (const float*)d_in[0];
    const float* Wf1 = (const float*)d_in[2];  const float* bf1 = (const float*)d_in[3];
    const float* Wf2 = (const float*)d_in[4];  const float* bf2 = (const float*)d_in[5];
    const float* Wf3 = (const float*)d_in[6];  const float* bf3 = (const float*)d_in[7];
    const float* Wc  = (const float*)d_in[8];  const float* bc  = (const float*)d_in[9];
    const float* Wa1 = (const float*)d_in[10]; const float* ba1 = (const float*)d_in[11];
    const float* Wa2 = (const float*)d_in[12]; const float* ba2 = (const float*)d_in[13];
    const float* Wg1 = (const float*)d_in[14]; const float* bg1 = (const float*)d_in[15];
    const float* Wg2 = (const float*)d_in[16]; const float* bg2 = (const float*)d_in[17];
    const float* Wp1 = (const float*)d_in[18]; const float* bp1 = (const float*)d_in[19];
    const float* Wp2 = (const float*)d_in[20]; const float* bp2 = (const float*)d_in[21];
    const float* Wp3 = (const float*)d_in[22]; const float* bp3 = (const float*)d_in[23];
    const float* Wm1 = (const float*)d_in[24]; const float* bm1 = (const float*)d_in[25];
    const float* Wm2 = (const float*)d_in[26]; const float* bm2 = (const float*)d_in[27];
    float* out = (float*)d_out;

    float* base = nullptr;
    cudaGetSymbolAddress((void**)&base, g_scratch);

    float* mask  = base + S_MASK;
    float* numel = base + S_NUMEL;
    float* meanf = base + S_MEAN;
    float* cvec  = base + S_CVEC;
    float* pool  = base + S_POOL;
    float* dinv  = base + S_DINV;
    float* gate  = base + S_GATE;
    float* g2    = base + S_G2;
    float* g1    = base + S_G1;
    float* fea   = base + S_FEA;
    float* adj   = base + S_ADJ;
    float* x1    = base + S_X1;
    float* x2    = base + S_X2;
    float* Taf   = base + S_TAF;
    float* Tbf   = base + S_TBF;
    float* Tcf   = base + S_TCF;

    __nv_bfloat16* inpb  = (__nv_bfloat16*)(base + S_INPB);
    __nv_bfloat16* h1b   = (__nv_bfloat16*)(base + S_H1B);
    __nv_bfloat16* h2b   = (__nv_bfloat16*)(base + S_H2B);
    __nv_bfloat16* feab  = (__nv_bfloat16*)(base + S_FEAB);
    __nv_bfloat16* feabT = (__nv_bfloat16*)(base + S_FEABT);
    __nv_bfloat16* qb    = (__nv_bfloat16*)(base + S_QB);
    __nv_bfloat16* a1b   = (__nv_bfloat16*)(base + S_A1B);
    __nv_bfloat16* afb   = (__nv_bfloat16*)(base + S_AFB);
    __nv_bfloat16* lhatb = (__nv_bfloat16*)(base + S_LHATB);
    __nv_bfloat16* Tab   = (__nv_bfloat16*)(base + S_TAB);
    __nv_bfloat16* TabT  = (__nv_bfloat16*)(base + S_TABT);
    __nv_bfloat16* Tbb   = (__nv_bfloat16*)(base + S_TBB);
    __nv_bfloat16* TbbT  = (__nv_bfloat16*)(base + S_TBBT);
    __nv_bfloat16* Tcb   = (__nv_bfloat16*)(base + S_TCB);
    __nv_bfloat16* TcbT  = (__nv_bfloat16*)(base + S_TCBT);
    __nv_bfloat16* x1b   = (__nv_bfloat16*)(base + S_X1B);
    __nv_bfloat16* x1bT  = (__nv_bfloat16*)(base + S_X1BT);
    __nv_bfloat16* x2b   = (__nv_bfloat16*)(base + S_X2B);
    __nv_bfloat16* wf1b  = (__nv_bfloat16*)(base + S_WF1B);
    __nv_bfloat16* wf2b  = (__nv_bfloat16*)(base + S_WF2B);
    __nv_bfloat16* wf3b  = (__nv_bfloat16*)(base + S_WF3B);
    __nv_bfloat16* wa1b  = (__nv_bfloat16*)(base + S_WA1B);
    __nv_bfloat16* wa2b  = (__nv_bfloat16*)(base + S_WA2B);
    __nv_bfloat16* wg1b  = (__nv_bfloat16*)(base + S_WG1B);
    __nv_bfloat16* wg2b  = (__nv_bfloat16*)(base + S_WG2B);
    __nv_bfloat16* wp1b  = (__nv_bfloat16*)(base + S_WP1B);

    // 0) convert inputs/weights to bf16 ([N,K] for weights)
    f2bf_kernel<<<(int)CDIV(8192L * 1024 / 4, 256), 256>>>(inp, inpb, 8192L * 1024);
    transposeBf(Wf1, wf1b, 1024, 784);
    transposeBf(Wf2, wf2b, 784, 512);
    transposeBf(Wf3, wf3b, 512, 512);
    transposeBf(Wa1, wa1b, 640, 512);
    transposeBf(Wa2, wa2b, 512, 384);
    for (int k = 0; k < 5; k++) transposeBf(Wg1 + (long)k * 512 * 512, wg1b + (long)k * 512 * 512, 512, 512);
    for (int k = 0; k < 5; k++) transposeBf(Wg2 + (long)k * 512 * 384, wg2b + (long)k * 384 * 512, 512, 384);
    transposeBf(Wp1, wp1b, 384, 128);

    // 1) node mask + numel
    mask_kernel<<<1024, 256>>>(inp, mask);
    numel_kernel<<<8, 1024>>>(mask, numel);

    // 2) feature extractor
    tg(inpb, 0, wf1b, 0, bf1, nullptr, 0, 0.f, mask, nullptr,
       nullptr, 0, h1b, nullptr, 0, MROWS, 784, 1024, 1.f, 1, 1);
    tg(h1b, 0, wf2b, 0, bf2, nullptr, 0, 0.f, mask, nullptr,
       nullptr, 0, h2b, nullptr, 0, MROWS, 512, 784, 1.f, 1, 1);
    tg(h2b, 0, wf3b, 0, bf3, nullptr, 0, 0.f, mask, nullptr,
       fea, 0, feab, (unsigned short*)feabT, 0, MROWS, 512, 512, 1.f, 1, 1);

    // 3) c vector
    mean_kernel<<<dim3(4, 8), 128>>>(fea, numel, meanf);
    cvec_kernel<<<8, 128>>>(meanf, Wc, bc, cvec);

    // 4) adjacency net
    concat_bf_kernel<<<(int)CDIV(8192L * 640, 256), 256>>>(feab, cvec, qb);
    tg(qb, 0, wa1b, 0, ba1, nullptr, 0, 0.f, mask, nullptr,
       nullptr, 0, a1b, nullptr, 0, MROWS, 512, 640, 1.f, 1, 1);
    tg(a1b, 0, wa2b, 0, ba2, nullptr, 0, 0.f, mask, nullptr,
       nullptr, 0, afb, nullptr, 0, MROWS, 384, 512, 1.f, 1, 1);

    // 5) A = (a a^T) * pairMask -> Lhat (bf16)
    tg(afb, 1024L * 384, afb, 1024L * 384, nullptr, nullptr, 0, 0.f,
       mask, mask, adj, 1024L * 1024, nullptr, nullptr, 0, 1024, 1024, 384, 1.f, 0, 8);
    deg_kernel<<<1024, 256>>>(adj, dinv);
    lhat_bf_kernel<<<(int)CDIV(8L * 1024 * 1024, 256), 256>>>(adj, dinv, lhatb);

    const long sT = 1024L * 512, sL = 1024L * 1024;

    // 6) ChebConv 1: K=5, 512 -> 512
    {
        const long wk = 512L * 512;
        tg(feab, 0, wg1b, 0, nullptr, nullptr, 0, 0.f, nullptr, nullptr,
           x1, 0, nullptr, nullptr, 0, MROWS, 512, 512, 1.f, 0, 1);
        tg(lhatb, sL, feabT, sT, nullptr, nullptr, 0, 0.f, nullptr, nullptr,
           Tbf, sT, Tbb, (unsigned short*)TbbT, sT, 1024, 512, 1024, 1.f, 0, 8);
        tg(Tbb, 0, wg1b + wk, 0, nullptr, x1, 0, 1.f, nullptr, nullptr,
           x1, 0, nullptr, nullptr, 0, MROWS, 512, 512, 1.f, 0, 1);
        tg(lhatb, sL, TbbT, sT, nullptr, fea, sT, -1.f, nullptr, nullptr,
           Tcf, sT, Tcb, (unsigned short*)TcbT, sT, 1024, 512, 1024, 2.f, 0, 8);
        tg(Tcb, 0, wg1b + 2 * wk, 0, nullptr, x1, 0, 1.f, nullptr, nullptr,
           x1, 0, nullptr, nullptr, 0, MROWS, 512, 512, 1.f, 0, 1);
        tg(lhatb, sL, TcbT, sT, nullptr, Tbf, sT, -1.f, nullptr, nullptr,
           Taf, sT, Tab, (unsigned short*)TabT, sT, 1024, 512, 1024, 2.f, 0, 8);
        tg(Tab, 0, wg1b + 3 * wk, 0, nullptr, x1, 0, 1.f, nullptr, nullptr,
           x1, 0, nullptr, nullptr, 0, MROWS, 512, 512, 1.f, 0, 1);
        tg(lhatb, sL, TabT, sT, nullptr, Tcf, sT, -1.f, nullptr, nullptr,
           Tbf, sT, Tbb, nullptr, 0, 1024, 512, 1024, 2.f, 0, 8);
        tg(Tbb, 0, wg1b + 4 * wk, 0, bg1, x1, 0, 1.f, nullptr, nullptr,
           x1, 0, x1b, (unsigned short*)x1bT, 0, MROWS, 512, 512, 1.f, 1, 1);
    }

    // 7) ChebConv 2: K=5, 512 -> 384
    {
        const long wk = 384L * 512;
        tg(x1b, 0, wg2b, 0, nullptr, nullptr, 0, 0.f, nullptr, nullptr,
           x2, 0, nullptr, nullptr, 0, MROWS, 384, 512, 1.f, 0, 1);
        tg(lhatb, sL, x1bT, sT, nullptr, nullptr, 0, 0.f, nullptr, nullptr,
           Tbf, sT, Tbb, (unsigned short*)TbbT, sT, 1024, 512, 1024, 1.f, 0, 8);
        tg(Tbb, 0, wg2b + wk, 0, nullptr, x2, 0, 1.f, nullptr, nullptr,
           x2, 0, nullptr, nullptr, 0, MROWS, 384, 512, 1.f, 0, 1);
        tg(lhatb, sL, TbbT, sT, nullptr, x1, sT, -1.f, nullptr, nullptr,
           Tcf, sT, Tcb, (unsigned short*)TcbT, sT, 1024, 512, 1024, 2.f, 0, 8);
        tg(Tcb, 0, wg2b + 2 * wk, 0, nullptr, x2, 0, 1.f, nullptr, nullptr,
           x2, 0, nullptr, nullptr, 0, MROWS, 384, 512, 1.f, 0, 1);
        tg(lhatb, sL, TcbT, sT, nullptr, Tbf, sT, -1.f, nullptr, nullptr,
           Taf, sT, Tab, (unsigned short*)TabT, sT, 1024, 512, 1024, 2.f, 0, 8);
        tg(Tab, 0, wg2b + 3 * wk, 0, nullptr, x2, 0, 1.f, nullptr, nullptr,
           x2, 0, nullptr, nullptr, 0, MROWS, 384, 512, 1.f, 0, 1);
        tg(lhatb, sL, TabT, sT, nullptr, Tcf, sT, -1.f, nullptr, nullptr,
           Tbf, sT, Tbb, nullptr, 0, 1024, 512, 1024, 2.f, 0, 8);
        tg(Tbb, 0, wg2b + 4 * wk, 0, bg2, x2, 0, 1.f, nullptr, nullptr,
           x2, 0, x2b, nullptr, 0, MROWS, 384, 512, 1.f, 1, 1);
    }

    // 8) attention gate
    tg(x2b, 0, wp1b, 0, bp1, nullptr, 0, 0.f, nullptr, nullptr,
       g1, 0, nullptr, nullptr, 0, MROWS, 128, 384, 1.f, 1, 1);
    gemm_kernel<<<dim3(1, 128), 256>>>(g1, Wp2, bp2, g2, MROWS, 64, 128, 1);
    gemm_kernel<<<dim3(1, 128), 256>>>(g2, Wp3, bp3, gate, MROWS, 1, 64, 2);

    // 9) softmax pooling + output MLP
    pool_kernel<<<8, 1024>>>(gate, mask, x2, pool);
    final_kernel<<<8, 256>>>(pool, Wm1, bm1, Wm2, bm2, out);

    (void)in_sizes; (void)n_in; (void)out_size;
}

// round 8
// speedup vs baseline: 6.1051x; 1.1358x over previous
#include <cuda_runtime.h>
#include <cuda_bf16.h>
#include <math.h>
#include <stdint.h>

#define Bq 8
#define Nn 1024
#define MROWS (Bq * Nn)   // 8192

// ---------------------------------------------------------------------------
// Scratch layout (float units; bf16 buffers use count/2 float slots)
// ---------------------------------------------------------------------------
#define S_MASK   0L
#define S_NUMEL  (S_MASK  + 8192L)
#define S_MEAN   (S_NUMEL + 8L)
#define S_CVEC   (S_MEAN  + 4096L)
#define S_POOL   (S_CVEC  + 1024L)
#define S_DINV   (S_POOL  + 3072L)
#define S_GATE   (S_DINV  + 8192L)
#define S_G2     (S_GATE  + 8192L)
#define S_G1     (S_G2    + 8192L*64)
#define S_FEA    (S_G1    + 8192L*128)
#define S_ADJ    (S_FEA   + 8192L*512)
#define S_X1     (S_ADJ   + 8388608L)
#define S_X2     (S_X1    + 8192L*512)
#define S_TAF    (S_X2    + 8192L*384)
#define S_TBF    (S_TAF   + 8192L*512)
#define S_TCF    (S_TBF   + 8192L*512)
// bf16 region (float slots = half the element count)
#define S_INPB   (S_TCF   + 8192L*512)
#define S_H1B    (S_INPB  + 4194304L)
#define S_H2B    (S_H1B   + 3211264L)
#define S_QB     (S_H2B   + 2097152L)
#define S_A1B    (S_QB    + 2621440L)
#define S_AFB    (S_A1B   + 2097152L)
#define S_LHATB  (S_AFB   + 1572864L)
#define S_TCH1   (S_LHATB + 4194304L)   // [8192, 2560] bf16
#define S_TCH2   (S_TCH1  + 10485760L)  // [8192, 2560] bf16
#define S_X2B    (S_TCH2  + 10485760L)
#define S_WF1B   (S_X2B   + 1572864L)
#define S_WF2B   (S_WF1B  + 401408L)
#define S_WF3B   (S_WF2B  + 200704L)
#define S_WA1B   (S_WF3B  + 131072L)
#define S_WA2B   (S_WA1B  + 163840L)
#define S_WG1C   (S_WA2B  + 98304L)     // [512, 2560] bf16 concat
#define S_WG2C   (S_WG1C  + 655360L)    // [384, 2560] bf16 concat
#define S_WP1B   (S_WG2C  + 491520L)
#define S_TOTAL  (S_WP1B  + 24576L)

__device__ float g_scratch[S_TOTAL];

#define CDIV(a,b) (((a)+(b)-1)/(b))

// ---------------------------------------------------------------------------
// Portable PTX helpers (sm_80+; no arch-'a' features)
// ---------------------------------------------------------------------------
__device__ __forceinline__ uint32_t bfpack(float lo, float hi) {
    uint32_t r;
    asm("cvt.rn.bf16x2.f32 %0, %1, %2;" : "=r"(r) : "f"(hi), "f"(lo));
    return r;
}
__device__ __forceinline__ uint32_t sm_u32(const void* p) {
    uint32_t a;
    asm("{ .reg .u64 t; cvta.to.shared.u64 t, %1; cvt.u32.u64 %0, t; }"
        : "=r"(a) : "l"(p));
    return a;
}
__device__ __forceinline__ void ldmx4(uint32_t& r0, uint32_t& r1, uint32_t& r2,
                                      uint32_t& r3, uint32_t addr) {
    asm volatile("ldmatrix.sync.aligned.m8n8.x4.shared.b16 {%0,%1,%2,%3}, [%4];"
                 : "=r"(r0), "=r"(r1), "=r"(r2), "=r"(r3) : "r"(addr));
}
__device__ __forceinline__ void ldmx4t(uint32_t& r0, uint32_t& r1, uint32_t& r2,
                                       uint32_t& r3, uint32_t addr) {
    asm volatile("ldmatrix.sync.aligned.m8n8.x4.trans.shared.b16 {%0,%1,%2,%3}, [%4];"
                 : "=r"(r0), "=r"(r1), "=r"(r2), "=r"(r3) : "r"(addr));
}
__device__ __forceinline__ void mma16(float* c, const uint32_t* a, const uint32_t* b) {
    asm volatile(
        "mma.sync.aligned.m16n8k16.row.col.f32.bf16.bf16.f32 "
        "{%0,%1,%2,%3}, {%4,%5,%6,%7}, {%8,%9}, {%0,%1,%2,%3};"
        : "+f"(c[0]), "+f"(c[1]), "+f"(c[2]), "+f"(c[3])
        : "r"(a[0]), "r"(a[1]), "r"(a[2]), "r"(a[3]), "r"(b[0]), "r"(b[1]));
}
__device__ __forceinline__ void cpa16(uint32_t dst, const void* src, int srcBytes) {
    asm volatile("cp.async.cg.shared.global [%0], [%1], 16, %2;\n"
                 :: "r"(dst), "l"(src), "r"(srcBytes));
}
#define CP_COMMIT() asm volatile("cp.async.commit_group;\n" ::: "memory")
#define CP_WAIT1()  asm volatile("cp.async.wait_group 1;\n" ::: "memory")
#define CP_WAIT0()  asm volatile("cp.async.wait_group 0;\n" ::: "memory")

// ---------------------------------------------------------------------------
// bf16 cp.async-pipelined mma.sync GEMM, 128x128 tile, 256 threads, 3 stages.
//   transB==0: B stored [N,K] K-major (row stride ldB)
//   transB==1: B stored [K,N] N-major (row stride ldB)  -> D = A @ B
//   v = act(alpha*D + bias + cinCoef*Cin) * rowMask * colMask
//   outputs (optional): C fp32 [M,N] row stride N; Cb bf16 row stride ldCb
//   requires M % 128 == 0, N % 16 == 0 (fp32/bf16 writes need even cols)
// ---------------------------------------------------------------------------
__global__ void __launch_bounds__(256)
mma_gemm_bf(const __nv_bfloat16* __restrict__ A, long sA,
            const __nv_bfloat16* __restrict__ B, long sB, int ldB, int transB,
            const float* __restrict__ bias,
            const float* __restrict__ Cin, long sCin, float cinCoef,
            const float* __restrict__ rowMask, const float* __restrict__ colMask,
            float* __restrict__ C, long sC,
            __nv_bfloat16* __restrict__ Cb, int ldCb, long sCb,
            int M, int N, int K, float alpha, int act)
{
    __shared__ __align__(16) char smem[49152];   // 3 stages x (A 8KB + B 8KB)
    const uint32_t sbase = sm_u32(smem);

    const int tid = threadIdx.x, lane = tid & 31, wid = tid >> 5;
    const int wm = wid >> 2, wn = wid & 3;       // warp grid 2 x 4 (64x32 per warp)
    const int bz = blockIdx.z;
    A += (long)bz * sA;
    B += (long)bz * sB;
    if (C)   C   += (long)bz * sC;
    if (Cb)  Cb  += (long)bz * sCb;
    if (Cin) Cin += (long)bz * sCin;
    const int rowBase = blockIdx.y * 128;
    const int colBase = blockIdx.x * 128;

    // A load geometry (always [M,K] K-major, row stride K)
    const int lr  = tid >> 1;
    const int c0  = (tid & 1) * 2;
    const int swz = (lr >> 1) & 3;
    const __nv_bfloat16* arow = A + (long)(rowBase + lr) * K;
    // B K-major geometry
    const int gn  = colBase + lr;
    const bool nok = gn < N;
    const __nv_bfloat16* browK = B + (long)(nok ? gn : 0) * ldB;
    // B trans geometry: smem tile [32 k-rows][256 B]
    const int tkr = tid >> 3;     // k row 0..31
    const int tct = tid & 7;      // chunk base 0..7 (chunks tct, tct+8)

    float acc[4][4][4];
#pragma unroll
    for (int i = 0; i < 4; i++)
#pragma unroll
        for (int j = 0; j < 4; j++)
#pragma unroll
            for (int t = 0; t < 4; t++) acc[i][j][t] = 0.f;

    const int nc = (K + 31) / 32;

    auto issue = [&](int cc) {
        const int st = cc % 3;
        const uint32_t ab = sbase + st * 16384;
#pragma unroll
        for (int j2 = 0; j2 < 2; j2++) {
            const int j = c0 + j2;
            const int k = cc * 32 + j * 8;
            cpa16(ab + lr * 64 + ((j ^ swz) << 4), arow + (k < K ? k : 0),
                  (k < K) ? 16 : 0);
        }
        if (!transB) {
#pragma unroll
            for (int j2 = 0; j2 < 2; j2++) {
                const int j = c0 + j2;
                const int k = cc * 32 + j * 8;
                cpa16(ab + 8192 + lr * 64 + ((j ^ swz) << 4),
                      browK + (k < K ? k : 0), (nok && k < K) ? 16 : 0);
            }
        } else {
            const int k = cc * 32 + tkr;
            const long krow = (long)(k < K ? k : 0) * ldB;
#pragma unroll
            for (int j2 = 0; j2 < 2; j2++) {
                const int ct = tct + j2 * 8;
                const int n = colBase + ct * 8;
                const bool ok = (k < K) && (n < N);
                cpa16(ab + 8192 + tkr * 256 + (((ct ^ (tkr & 7))) << 4),
                      B + (ok ? krow + n : 0), ok ? 16 : 0);
            }
        }
        CP_COMMIT();
    };

    issue(0);
    if (nc > 1) issue(1);

    // ldmatrix lane geometry
    const int lj = lane >> 3, lr8 = lane & 7;
    const int amrow = (lj & 1) * 8 + lr8, akc = lj >> 1;
    const int bnrow = (lj >> 1) * 8 + lr8, bkc = lj & 1;    // K-major B
    const int tbkr0 = ((lj & 1) << 3) + lr8;                // trans B: k sub-row
    const int tbcs  = lj >> 1;                              // trans B: chunk select

    for (int c = 0; c < nc; c++) {
        if (c + 1 < nc) { CP_WAIT1(); } else { CP_WAIT0(); }
        __syncthreads();
        if (c + 2 < nc) issue(c + 2);

        const uint32_t abase = sbase + (c % 3) * 16384;
        const uint32_t bbase = abase + 8192;
#pragma unroll
        for (int ks = 0; ks < 2; ks++) {
            uint32_t af[4][4];
#pragma unroll
            for (int i = 0; i < 4; i++) {
                const int row = wm * 64 + i * 16 + amrow;
                const int logc = ks * 2 + akc;
                ldmx4(af[i][0], af[i][1], af[i][2], af[i][3],
                      abase + row * 64 + ((logc ^ ((row >> 1) & 3)) << 4));
            }
            uint32_t bf[4][2];
            if (!transB) {
#pragma unroll
                for (int jj = 0; jj < 4; jj += 2) {
                    const int n = wn * 32 + jj * 8 + bnrow;
                    const int logc = ks * 2 + bkc;
                    ldmx4(bf[jj][0], bf[jj][1], bf[jj + 1][0], bf[jj + 1][1],
                          bbase + n * 64 + ((logc ^ ((n >> 1) & 3)) << 4));
                }
            } else {
#pragma unroll
                for (int jp = 0; jp < 2; jp++) {
                    const int krow = ks * 16 + tbkr0;
                    const int chunk = wn * 4 + jp * 2 + tbcs;
                    ldmx4t(bf[jp * 2][0], bf[jp * 2][1],
                           bf[jp * 2 + 1][0], bf[jp * 2 + 1][1],
                           bbase + krow * 256 + ((chunk ^ (krow & 7)) << 4));
                }
            }
#pragma unroll
            for (int i = 0; i < 4; i++)
#pragma unroll
                for (int j = 0; j < 4; j++)
                    mma16(acc[i][j], af[i], bf[j]);
        }
    }

    // ---- epilogue ----
#pragma unroll
    for (int i = 0; i < 4; i++) {
        const int gr0 = rowBase + wm * 64 + i * 16 + (lane >> 2);
#pragma unroll
        for (int half = 0; half < 2; half++) {
            const int gr = gr0 + half * 8;
            const float rm = rowMask ? rowMask[(long)bz * M + gr] : 1.f;
#pragma unroll
            for (int j = 0; j < 4; j++) {
                const int gcb = colBase + wn * 32 + j * 8;
                if (gcb >= N) continue;
                const int gc = gcb + 2 * (lane & 3);
                float v0 = alpha * acc[i][j][half * 2 + 0];
                float v1 = alpha * acc[i][j][half * 2 + 1];
                if (bias) { v0 += bias[gc]; v1 += bias[gc + 1]; }
                if (Cin) {
                    v0 += cinCoef * Cin[(long)gr * N + gc];
                    v1 += cinCoef * Cin[(long)gr * N + gc + 1];
                }
                v0 *= rm; v1 *= rm;
                if (colMask) {
                    v0 *= colMask[(long)bz * N + gc];
                    v1 *= colMask[(long)bz * N + gc + 1];
                }
                if (act == 1) { v0 = fmaxf(v0, 0.f); v1 = fmaxf(v1, 0.f); }
                else if (act == 2) { v0 = tanhf(v0); v1 = tanhf(v1); }
                if (C) *(float2*)(C + (long)gr * N + gc) = make_float2(v0, v1);
                if (Cb)
                    *(uint32_t*)((char*)Cb + ((long)gr * ldCb + gc) * 2) =
                        bfpack(v0, v1);
            }
        }
    }
}

// ---------------------------------------------------------------------------
// Small GEMM (N < 128): fp32 SIMT, B stored [K,N]
// ---------------------------------------------------------------------------
__global__ void gemm_kernel(const float* __restrict__ A,
                            const float* __restrict__ B,
                            const float* __restrict__ bias,
                            float* __restrict__ C,
                            int M, int N, int K, int act)
{
    __shared__ float As[16][64];
    __shared__ float Bs[16][64];

    const int rowBase = blockIdx.y * 64;
    const int colBase = blockIdx.x * 64;
    const int tid = threadIdx.x;
    const int tx = tid & 15, ty = tid >> 4;

    float acc[4][4];
#pragma unroll
    for (int i = 0; i < 4; i++)
#pragma unroll
        for (int j = 0; j < 4; j++) acc[i][j] = 0.f;

    const int ar  = tid >> 2, ak  = (tid & 3) * 4;
    const int bkr = tid >> 4, bnc = (tid & 15) * 4;

    for (int k0 = 0; k0 < K; k0 += 16) {
        const int gr = rowBase + ar;
#pragma unroll
        for (int i = 0; i < 4; i++) {
            const int gk = k0 + ak + i;
            As[ak + i][ar] = (gr < M && gk < K) ? A[(long)gr * K + gk] : 0.f;
        }
        const int gk = k0 + bkr;
#pragma unroll
        for (int i = 0; i < 4; i++) {
            const int gnn = colBase + bnc + i;
            Bs[bkr][bnc + i] = (gk < K && gnn < N) ? B[(long)gk * N + gnn] : 0.f;
        }
        __syncthreads();
#pragma unroll
        for (int kk = 0; kk < 16; kk++) {
            float a0[4], b0[4];
#pragma unroll
            for (int i = 0; i < 4; i++) a0[i] = As[kk][ty * 4 + i];
#pragma unroll
            for (int j = 0; j < 4; j++) b0[j] = Bs[kk][tx * 4 + j];
#pragma unroll
            for (int i = 0; i < 4; i++)
#pragma unroll
                for (int j = 0; j < 4; j++) acc[i][j] += a0[i] * b0[j];
        }
        __syncthreads();
    }

#pragma unroll
    for (int i = 0; i < 4; i++) {
        const int gr = rowBase + ty * 4 + i;
        if (gr >= M) continue;
#pragma unroll
        for (int j = 0; j < 4; j++) {
            const int gc = colBase + tx * 4 + j;
            if (gc >= N) continue;
            float v = acc[i][j];
            if (bias) v += bias[gc];
            if (act == 1)      v = fmaxf(v, 0.f);
            else if (act == 2) v = tanhf(v);
            C[(long)gr * N + gc] = v;
        }
    }
}

// ---------------------------------------------------------------------------
// Conversion / glue kernels
// ---------------------------------------------------------------------------
__global__ void f2bf_kernel(const float* __restrict__ in, __nv_bfloat16* __restrict__ out,
                            long n)
{
    const long i = ((long)blockIdx.x * blockDim.x + threadIdx.x) * 4;
    if (i >= n) return;
    const float4 v = *(const float4*)(in + i);
    uint2 u;
    u.x = bfpack(v.x, v.y);
    u.y = bfpack(v.z, v.w);
    *(uint2*)(out + i) = u;
}

// fp32 [R,C] -> bf16 [C,R] (out row stride ldOut); optional z-batch
__global__ void transpose_bf_kernel(const float* __restrict__ in,
                                    __nv_bfloat16* __restrict__ out,
                                    int R, int C, int ldOut,
                                    long inStrideZ, int outColOffZ)
{
    const int z = blockIdx.z;
    in  += (long)z * inStrideZ;
    out += (long)z * outColOffZ;
    __shared__ float t[32][33];
    const int c0 = blockIdx.x * 32, r0 = blockIdx.y * 32;
    const int x = threadIdx.x, y = threadIdx.y;
#pragma unroll
    for (int i = y; i < 32; i += 8) {
        const int r = r0 + i, c = c0 + x;
        if (r < R && c < C) t[i][x] = in[(long)r * C + c];
    }
    __syncthreads();
#pragma unroll
    for (int i = y; i < 32; i += 8) {
        const int oc = c0 + i, orr = r0 + x;
        if (oc < C && orr < R) out[(long)oc * ldOut + orr] = __float2bfloat16(t[x][i]);
    }
}

__global__ void mask_kernel(const float* __restrict__ inp, float* __restrict__ mask)
{
    const int row  = blockIdx.x * 8 + (threadIdx.x >> 5);
    const int lane = threadIdx.x & 31;
    const float* p = inp + (long)row * 1024;
    float s = 0.f;
    for (int k = lane; k < 1024; k += 32) s += p[k];
#pragma unroll
    for (int o = 16; o > 0; o >>= 1) s += __shfl_xor_sync(0xffffffffu, s, o);
    if (lane == 0) mask[row] = (s != 0.f) ? 1.f : 0.f;
}

__global__ void numel_kernel(const float* __restrict__ mask, float* __restrict__ numel)
{
    const int b = blockIdx.x, tid = threadIdx.x;
    __shared__ float sh[1024];
    sh[tid] = mask[b * 1024 + tid];
    __syncthreads();
    for (int s = 512; s > 0; s >>= 1) {
        if (tid < s) sh[tid] += sh[tid + s];
        __syncthreads();
    }
    if (tid == 0) numel[b] = sh[0];
}

__global__ void mean_kernel(const float* __restrict__ fea, const float* __restrict__ numel,
                            float* __restrict__ mean)
{
    const int b = blockIdx.y;
    const int f = blockIdx.x * blockDim.x + threadIdx.x;
    const float* p = fea + (long)b * 1024 * 512 + f;
    float s = 0.f;
    for (int n = 0; n < 1024; n++) s += p[(long)n * 512];
    mean[b * 512 + f] = s / numel[b];
}

__global__ void cvec_kernel(const float* __restrict__ mean, const float* __restrict__ Wc,
                            const float* __restrict__ bc, float* __restrict__ c)
{
    const int b = blockIdx.x, j = threadIdx.x;
    float s = bc[j];
    for (int k = 0; k < 512; k++) s += mean[b * 512 + k] * Wc[k * 128 + j];
    c[b * 128 + j] = fmaxf(s, 0.f);
}

// q[row, 0:512) = feab(row) (bf16, row stride ldFea), q[row, 512:640) = cvec(batch)
__global__ void concat_bf_kernel(const __nv_bfloat16* __restrict__ feab, int ldFea,
                                 const float* __restrict__ cvec,
                                 __nv_bfloat16* __restrict__ q)
{
    const long idx = (long)blockIdx.x * blockDim.x + threadIdx.x;
    if (idx >= 8192L * 640) return;
    const int f = (int)(idx % 640);
    const long row = idx / 640;
    const int b = (int)(row >> 10);
    q[idx] = (f < 512) ? feab[row * ldFea + f]
                       : __float2bfloat16(cvec[b * 128 + (f - 512)]);
}

__global__ void deg_kernel(const float* __restrict__ A, float* __restrict__ dinv)
{
    const int row  = blockIdx.x * 8 + (threadIdx.x >> 5);
    const int lane = threadIdx.x & 31;
    const float* p = A + (long)row * 1024;
    float s = 0.f;
    for (int j = lane; j < 1024; j += 32) s += p[j];
#pragma unroll
    for (int o = 16; o > 0; o >>= 1) s += __shfl_xor_sync(0xffffffffu, s, o);
    if (lane == 0) dinv[row] = (s > 0.f) ? rsqrtf(fmaxf(s, 1e-30f)) : 0.f;
}

__global__ void lhat_bf_kernel(const float* __restrict__ adj, const float* __restrict__ dinv,
                               __nv_bfloat16* __restrict__ lb)
{
    const long idx = (long)blockIdx.x * blockDim.x + threadIdx.x;
    if (idx >= 8L * 1024 * 1024) return;
    const long row = idx >> 10;
    const int  j   = (int)(idx & 1023);
    const int  b   = (int)(row >> 10);
    lb[idx] = __float2bfloat16(-adj[idx] * dinv[row] * dinv[(long)b * 1024 + j]);
}

__global__ void pool_kernel(const float* __restrict__ gate, const float* __restrict__ mask,
                            const float* __restrict__ x, float* __restrict__ pooled)
{
    const int b = blockIdx.x, tid = threadIdx.x;
    __shared__ float sh[1024];
    const float g = (mask[b * 1024 + tid] > 0.f) ? gate[b * 1024 + tid] : -1e9f;
    sh[tid] = g;
    __syncthreads();
    for (int s = 512; s > 0; s >>= 1) {
        if (tid < s) sh[tid] = fmaxf(sh[tid], sh[tid + s]);
        __syncthreads();
    }
    const float maxv = sh[0];
    __syncthreads();
    const float e = expf(g - maxv);
    sh[tid] = e;
    __syncthreads();
    for (int s = 512; s > 0; s >>= 1) {
        if (tid < s) sh[tid] += sh[tid + s];
        __syncthreads();
    }
    const float sum = sh[0];
    __syncthreads();
    sh[tid] = e / sum;
    __syncthreads();
    if (tid < 384) {
        float s = 0.f;
        const float* xb = x + (long)b * 1024 * 384 + tid;
        for (int n = 0; n < 1024; n++) s += sh[n] * xb[(long)n * 384];
        pooled[b * 384 + tid] = s;
    }
}

__global__ void final_kernel(const float* __restrict__ pooled, const float* __restrict__ Wm1,
                             const float* __restrict__ bm1, const float* __restrict__ Wm2,
                             const float* __restrict__ bm2, float* __restrict__ out)
{
    const int b = blockIdx.x, tid = threadIdx.x;
    __shared__ float sh[256];
    float s = bm1[tid];
    const float* p = pooled + b * 384;
    for (int k = 0; k < 384; k++) s += p[k] * Wm1[k * 256 + tid];
    sh[tid] = fmaxf(s, 0.f) * Wm2[tid];
    __syncthreads();
    for (int r = 128; r > 0; r >>= 1) {
        if (tid < r) sh[tid] += sh[tid + r];
        __syncthreads();
    }
    if (tid == 0) out[b] = 1.f / (1.f + expf(-(sh[0] + bm2[0])));
}

// ---------------------------------------------------------------------------
// Host launchers
// ---------------------------------------------------------------------------
static void tg(const __nv_bfloat16* A, long sA,
               const __nv_bfloat16* B, long sB, int ldB, int transB,
               const float* bias, const float* Cin, long sCin, float cc,
               const float* rM, const float* cM,
               float* C, long sC, __nv_bfloat16* Cb, int ldCb, long sCb,
               int M, int N, int K, float alpha, int act, int batch)
{
    dim3 grid(CDIV(N, 128), M / 128, batch);
    mma_gemm_bf<<<grid, 256>>>(A, sA, B, sB, ldB, transB, bias, Cin, sCin, cc,
                               rM, cM, C, sC, Cb, ldCb, sCb, M, N, K, alpha, act);
}

static void transposeBf(const float* in, __nv_bfloat16* out, int R, int C,
                        int ldOut, int nz = 1, long inStrideZ = 0, int outColOffZ = 0)
{
    dim3 grid(CDIV(C, 32), CDIV(R, 32), nz);
    transpose_bf_kernel<<<grid, dim3(32, 8)>>>(in, out, R, C, ldOut, inStrideZ, outColOffZ);
}

// ---------------------------------------------------------------------------
// Entry point
// ---------------------------------------------------------------------------
extern "C" void kernel_launch(void* const* d_in, const int* in_sizes, int n_in,
                              void* d_out, int out_size)
{
    const float* inp = (const float*)d_in[0];
    const float* Wf1 = (const float*)d_in[2];  const float* bf1 = (const float*)d_in[3];
    const float* Wf2 = (const float*)d_in[4];  const float* bf2 = (const float*)d_in[5];
    const float* Wf3 = (const float*)d_in[6];  const float* bf3 = (const float*)d_in[7];
    const float* Wc  = (const float*)d_in[8];  const float* bc  = (const float*)d_in[9];
    const float* Wa1 = (const float*)d_in[10]; const float* ba1 = (const float*)d_in[11];
    const float* Wa2 = (const float*)d_in[12]; const float* ba2 = (const float*)d_in[13];
    const float* Wg1 = (const float*)d_in[14]; const float* bg1 = (const float*)d_in[15];
    const float* Wg2 = (const float*)d_in[16]; const float* bg2 = (const float*)d_in[17];
    const float* Wp1 = (const float*)d_in[18]; const float* bp1 = (const float*)d_in[19];
    const float* Wp2 = (const float*)d_in[20]; const float* bp2 = (const float*)d_in[21];
    const float* Wp3 = (const float*)d_in[22]; const float* bp3 = (const float*)d_in[23];
    const float* Wm1 = (const float*)d_in[24]; const float* bm1 = (const float*)d_in[25];
    const float* Wm2 = (const float*)d_in[26]; const float* bm2 = (const float*)d_in[27];
    float* out = (float*)d_out;

    float* base = nullptr;
    cudaGetSymbolAddress((void**)&base, g_scratch);

    float* mask  = base + S_MASK;
    float* numel = base + S_NUMEL;
    float* meanf = base + S_MEAN;
    float* cvec  = base + S_CVEC;
    float* pool  = base + S_POOL;
    float* dinv  = base + S_DINV;
    float* gate  = base + S_GATE;
    float* g2    = base + S_G2;
    float* g1    = base + S_G1;
    float* fea   = base + S_FEA;
    float* adj   = base + S_ADJ;
    float* x1    = base + S_X1;
    float* x2    = base + S_X2;
    float* Taf   = base + S_TAF;
    float* Tbf   = base + S_TBF;
    float* Tcf   = base + S_TCF;

    __nv_bfloat16* inpb  = (__nv_bfloat16*)(base + S_INPB);
    __nv_bfloat16* h1b   = (__nv_bfloat16*)(base + S_H1B);
    __nv_bfloat16* h2b   = (__nv_bfloat16*)(base + S_H2B);
    __nv_bfloat16* qb    = (__nv_bfloat16*)(base + S_QB);
    __nv_bfloat16* a1b   = (__nv_bfloat16*)(base + S_A1B);
    __nv_bfloat16* afb   = (__nv_bfloat16*)(base + S_AFB);
    __nv_bfloat16* lhatb = (__nv_bfloat16*)(base + S_LHATB);
    __nv_bfloat16* tch1  = (__nv_bfloat16*)(base + S_TCH1);   // [8192, 2560]
    __nv_bfloat16* tch2  = (__nv_bfloat16*)(base + S_TCH2);   // [8192, 2560]
    __nv_bfloat16* x2b   = (__nv_bfloat16*)(base + S_X2B);
    __nv_bfloat16* wf1b  = (__nv_bfloat16*)(base + S_WF1B);
    __nv_bfloat16* wf2b  = (__nv_bfloat16*)(base + S_WF2B);
    __nv_bfloat16* wf3b  = (__nv_bfloat16*)(base + S_WF3B);
    __nv_bfloat16* wa1b  = (__nv_bfloat16*)(base + S_WA1B);
    __nv_bfloat16* wa2b  = (__nv_bfloat16*)(base + S_WA2B);
    __nv_bfloat16* wg1c  = (__nv_bfloat16*)(base + S_WG1C);   // [512, 2560]
    __nv_bfloat16* wg2c  = (__nv_bfloat16*)(base + S_WG2C);   // [384, 2560]
    __nv_bfloat16* wp1b  = (__nv_bfloat16*)(base + S_WP1B);

    const long sL  = 1024L * 1024;      // lhat batch stride (elems)
    const long sT  = 1024L * 512;       // fp32 T batch stride
    const long sTc = 1024L * 2560;      // tch batch stride (bf16 elems)

    // 0) conversions: inp + weights to bf16; Wg concatenated along K
    f2bf_kernel<<<(int)CDIV(8192L * 1024 / 4, 256), 256>>>(inp, inpb, 8192L * 1024);
    transposeBf(Wf1, wf1b, 1024, 784, 1024);
    transposeBf(Wf2, wf2b, 784, 512, 784);
    transposeBf(Wf3, wf3b, 512, 512, 512);
    transposeBf(Wa1, wa1b, 640, 512, 640);
    transposeBf(Wa2, wa2b, 512, 384, 512);
    transposeBf(Wp1, wp1b, 384, 128, 384);
    transposeBf(Wg1, wg1c, 512, 512, 2560, 5, 512L * 512, 512);
    transposeBf(Wg2, wg2c, 512, 384, 2560, 5, 512L * 384, 512);

    // 1) node mask + numel
    mask_kernel<<<1024, 256>>>(inp, mask);
    numel_kernel<<<8, 1024>>>(mask, numel);

    // 2) feature extractor (fea bf16 lands in tch1 slot 0, ld 2560)
    tg(inpb, 0, wf1b, 0, 1024, 0, bf1, nullptr, 0, 0.f, mask, nullptr,
       nullptr, 0, h1b, 784, 0, MROWS, 784, 1024, 1.f, 1, 1);
    tg(h1b, 0, wf2b, 0, 784, 0, bf2, nullptr, 0, 0.f, mask, nullptr,
       nullptr, 0, h2b, 512, 0, MROWS, 512, 784, 1.f, 1, 1);
    tg(h2b, 0, wf3b, 0, 512, 0, bf3, nullptr, 0, 0.f, mask, nullptr,
       fea, 0, tch1, 2560, 0, MROWS, 512, 512, 1.f, 1, 1);

    // 3) c vector
    mean_kernel<<<dim3(4, 8), 128>>>(fea, numel, meanf);
    cvec_kernel<<<8, 128>>>(meanf, Wc, bc, cvec);

    // 4) adjacency net
    concat_bf_kernel<<<(int)CDIV(8192L * 640, 256), 256>>>(tch1, 2560, cvec, qb);
    tg(qb, 0, wa1b, 0, 640, 0, ba1, nullptr, 0, 0.f, mask, nullptr,
       nullptr, 0, a1b, 512, 0, MROWS, 512, 640, 1.f, 1, 1);
    tg(a1b, 0, wa2b, 0, 512, 0, ba2, nullptr, 0, 0.f, mask, nullptr,
       nullptr, 0, afb, 384, 0, MROWS, 384, 512, 1.f, 1, 1);

    // 5) A = (a a^T) * pairMask -> Lhat bf16
    tg(afb, 1024L * 384, afb, 1024L * 384, 384, 0, nullptr, nullptr, 0, 0.f,
       mask, mask, adj, sL, nullptr, 0, 0, 1024, 1024, 384, 1.f, 0, 8);
    deg_kernel<<<1024, 256>>>(adj, dinv);
    lhat_bf_kernel<<<(int)CDIV(8L * 1024 * 1024, 256), 256>>>(adj, dinv, lhatb);

    // 6) ChebConv 1: T_k into tch1 slots (trans-B Lhat GEMMs), then ONE K=2560 GEMM
    // T1 = L @ T0
    tg(lhatb, sL, tch1, sTc, 2560, 1, nullptr, nullptr, 0, 0.f, nullptr, nullptr,
       Tbf, sT, tch1 + 512, 2560, sTc, 1024, 512, 1024, 1.f, 0, 8);
    // T2 = 2 L T1 - T0
    tg(lhatb, sL, tch1 + 512, sTc, 2560, 1, nullptr, fea, sT, -1.f, nullptr, nullptr,
       Tcf, sT, tch1 + 1024, 2560, sTc, 1024, 512, 1024, 2.f, 0, 8);
    // T3 = 2 L T2 - T1
    tg(lhatb, sL, tch1 + 1024, sTc, 2560, 1, nullptr, Tbf, sT, -1.f, nullptr, nullptr,
       Taf, sT, tch1 + 1536, 2560, sTc, 1024, 512, 1024, 2.f, 0, 8);
    // T4 = 2 L T3 - T2
    tg(lhatb, sL, tch1 + 1536, sTc, 2560, 1, nullptr, Tcf, sT, -1.f, nullptr, nullptr,
       nullptr, 0, tch1 + 2048, 2560, sTc, 1024, 512, 1024, 2.f, 0, 8);
    // x1 = relu([T0..T4] @ Wg1cat + bg1) ; bf16 into tch2 slot 0
    tg(tch1, 0, wg1c, 0, 2560, 0, bg1, nullptr, 0, 0.f, nullptr, nullptr,
       x1, 0, tch2, 2560, 0, MROWS, 512, 2560, 1.f, 1, 1);

    // 7) ChebConv 2 (512 -> 384)
    tg(lhatb, sL, tch2, sTc, 2560, 1, nullptr, nullptr, 0, 0.f, nullptr, nullptr,
       Tbf, sT, tch2 + 512, 2560, sTc, 1024, 512, 1024, 1.f, 0, 8);
    tg(lhatb, sL, tch2 + 512, sTc, 2560, 1, nullptr, x1, sT, -1.f, nullptr, nullptr,
       Tcf, sT, tch2 + 1024, 2560, sTc, 1024, 512, 1024, 2.f, 0, 8);
    tg(lhatb, sL, tch2 + 1024, sTc, 2560, 1, nullptr, Tbf, sT, -1.f, nullptr, nullptr,
       Taf, sT, tch2 + 1536, 2560, sTc, 1024, 512, 1024, 2.f, 0, 8);
    tg(lhatb, sL, tch2 + 1536, sTc, 2560, 1, nullptr, Tcf, sT, -1.f, nullptr, nullptr,
       nullptr, 0, tch2 + 2048, 2560, sTc, 1024, 512, 1024, 2.f, 0, 8);
    tg(tch2, 0, wg2c, 0, 2560, 0, bg2, nullptr, 0, 0.f, nullptr, nullptr,
       x2, 0, x2b, 384, 0, MROWS, 384, 2560, 1.f, 1, 1);

    // 8) attention gate
    tg(x2b, 0, wp1b, 0, 384, 0, bp1, nullptr, 0, 0.f, nullptr, nullptr,
       g1, 0, nullptr, 0, 0, MROWS, 128, 384, 1.f, 1, 1);
    gemm_kernel<<<dim3(1, 128), 256>>>(g1, Wp2, bp2, g2, MROWS, 64, 128, 1);
    gemm_kernel<<<dim3(1, 128), 256>>>(g2, Wp3, bp3, gate, MROWS, 1, 64, 2);

    // 9) softmax pooling + output MLP
    pool_kernel<<<8, 1024>>>(gate, mask, x2, pool);
    final_kernel<<<8, 256>>>(pool, Wm1, bm1, Wm2, bm2, out);

    (void)in_sizes; (void)n_in; (void)out_size;
}